// round 1
// baseline (speedup 1.0000x reference)
#include <cuda_runtime.h>
#include <math.h>

#define Bb 8
#define Ss 1024
#define Dd 1024
#define Hh 16
#define DHh 64
#define FFf 4096
#define LAYER 3
#define MROWS (Bb*Ss)   /* 8192 */

// ---------------- scratch (device globals; allocation-free rule) ----------------
__device__ float g_h  [MROWS*Dd];
__device__ float g_x1 [MROWS*Dd];
__device__ float g_q  [MROWS*Dd];
__device__ float g_k  [MROWS*Dd];
__device__ float g_v  [MROWS*Dd];
__device__ float g_sc [(size_t)Bb*Hh*Ss*Ss];   // 512 MB scores/attn
__device__ float g_ctx[MROWS*Dd];
__device__ float g_mid[MROWS*Dd];
__device__ float g_x2 [MROWS*Dd];
__device__ float g_ffn[(size_t)MROWS*FFf];
__device__ int   g_is64;

// ---------------- dtype detection for int inputs ----------------
// If x is int64 (LE), the high 32-bit word of every token is 0 (tokens in [0,32000)).
// If x is int32, odd words are real random tokens -> essentially never all zero.
// Scan only the first 4096 pairs (safe within an int32 buffer of 8192 words).
__global__ void detect_kernel(const int* __restrict__ x) {
    __shared__ int any;
    if (threadIdx.x == 0) any = 0;
    __syncthreads();
    int local = 0;
    for (int i = threadIdx.x; i < 4096; i += blockDim.x)
        if (x[2*i + 1] != 0) local = 1;
    if (local) any = 1;   // benign race
    __syncthreads();
    if (threadIdx.x == 0) g_is64 = (any == 0) ? 1 : 0;
}

// ---------------- embed: h = emb[x]*sqrt(D) + pos ----------------
__global__ void embed_kernel(const int* __restrict__ x, const float* __restrict__ emb,
                             const float* __restrict__ pos, float* __restrict__ h) {
    int i = blockIdx.x * blockDim.x + threadIdx.x;          // over float4s
    if (i >= MROWS * (Dd/4)) return;
    int row = i >> 8;           // / 256
    int dc  = i & 255;
    int s   = row & (Ss - 1);
    long long tok = g_is64 ? ((const long long*)x)[row] : (long long)x[row];
    float4 e = ((const float4*)emb)[(size_t)tok * 256 + dc];
    float4 p = ((const float4*)pos)[(size_t)s   * 256 + dc];
    float4 r;
    r.x = fmaf(e.x, 32.0f, p.x);
    r.y = fmaf(e.y, 32.0f, p.y);
    r.z = fmaf(e.z, 32.0f, p.z);
    r.w = fmaf(e.w, 32.0f, p.w);
    ((float4*)h)[i] = r;
}

// ---------------- layernorm (one block per 1024-elem row) ----------------
__global__ __launch_bounds__(256)
void ln_kernel(const float* __restrict__ in, const float* __restrict__ gamma,
               const float* __restrict__ beta, float* __restrict__ out) {
    int row = blockIdx.x;
    int tid = threadIdx.x;
    const float4* xr = (const float4*)(in + (size_t)row * Dd);
    float4 v = xr[tid];
    float s1 = v.x + v.y + v.z + v.w;
    float s2 = v.x*v.x + v.y*v.y + v.z*v.z + v.w*v.w;
    #pragma unroll
    for (int o = 16; o; o >>= 1) {
        s1 += __shfl_xor_sync(0xffffffffu, s1, o);
        s2 += __shfl_xor_sync(0xffffffffu, s2, o);
    }
    __shared__ float a1[8], a2[8];
    int lane = tid & 31, wid = tid >> 5;
    if (lane == 0) { a1[wid] = s1; a2[wid] = s2; }
    __syncthreads();
    __shared__ float mS, invS;
    if (tid == 0) {
        float t1 = 0.f, t2 = 0.f;
        #pragma unroll
        for (int w = 0; w < 8; ++w) { t1 += a1[w]; t2 += a2[w]; }
        float mean = t1 * (1.0f / Dd);
        float var  = t2 * (1.0f / Dd) - mean * mean;
        mS = mean; invS = rsqrtf(var + 1e-5f);
    }
    __syncthreads();
    float mean = mS, inv = invS;
    float4 g4 = ((const float4*)gamma)[tid];
    float4 b4 = ((const float4*)beta)[tid];
    float4 o4;
    o4.x = (v.x - mean) * inv * g4.x + b4.x;
    o4.y = (v.y - mean) * inv * g4.y + b4.y;
    o4.z = (v.z - mean) * inv * g4.z + b4.z;
    o4.w = (v.w - mean) * inv * g4.w + b4.w;
    ((float4*)(out + (size_t)row * Dd))[tid] = o4;
}

// ---------------- generic SGEMM: C = epi(A@W + bias [+ res]) ----------------
// EPI: 0 = +bias ; 1 = +bias+res ; 2 = relu(+bias)
#define BM 128
#define BN 128
#define BK 8
template<int EPI>
__global__ __launch_bounds__(256, 2)
void sgemm_kernel(const float* __restrict__ A, const float* __restrict__ W,
                  const float* __restrict__ bias, const float* __restrict__ res,
                  float* __restrict__ C, int M, int N, int K) {
    __shared__ float As[BK][BM];
    __shared__ float Bs[BK][BN];
    int tid = threadIdx.x;
    int tx = tid & 15, ty = tid >> 4;
    int rowBase = blockIdx.y * BM, colBase = blockIdx.x * BN;

    int aRow = tid >> 1;
    int aCol = (tid & 1) * 4;
    int bRow = tid >> 5;
    int bCol = (tid & 31) * 4;

    const float* Aptr = A + (size_t)(rowBase + aRow) * K + aCol;
    const float* Wptr = W + (size_t)bRow * N + colBase + bCol;

    float acc[8][8];
    #pragma unroll
    for (int i = 0; i < 8; i++)
        #pragma unroll
        for (int j = 0; j < 8; j++) acc[i][j] = 0.f;

    for (int k0 = 0; k0 < K; k0 += BK) {
        float4 av = *(const float4*)(Aptr + k0);
        float4 wv = *(const float4*)(Wptr + (size_t)k0 * N);
        As[aCol + 0][aRow] = av.x;
        As[aCol + 1][aRow] = av.y;
        As[aCol + 2][aRow] = av.z;
        As[aCol + 3][aRow] = av.w;
        *(float4*)&Bs[bRow][bCol] = wv;
        __syncthreads();
        #pragma unroll
        for (int kk = 0; kk < BK; ++kk) {
            float a[8], b[8];
            float4 t0 = *(const float4*)&As[kk][ty * 8];
            float4 t1 = *(const float4*)&As[kk][ty * 8 + 4];
            a[0]=t0.x; a[1]=t0.y; a[2]=t0.z; a[3]=t0.w;
            a[4]=t1.x; a[5]=t1.y; a[6]=t1.z; a[7]=t1.w;
            float4 u0 = *(const float4*)&Bs[kk][tx * 8];
            float4 u1 = *(const float4*)&Bs[kk][tx * 8 + 4];
            b[0]=u0.x; b[1]=u0.y; b[2]=u0.z; b[3]=u0.w;
            b[4]=u1.x; b[5]=u1.y; b[6]=u1.z; b[7]=u1.w;
            #pragma unroll
            for (int i = 0; i < 8; i++)
                #pragma unroll
                for (int j = 0; j < 8; j++)
                    acc[i][j] = fmaf(a[i], b[j], acc[i][j]);
        }
        __syncthreads();
    }
    #pragma unroll
    for (int i = 0; i < 8; i++) {
        int row = rowBase + ty * 8 + i;
        size_t base = (size_t)row * N + colBase + tx * 8;
        #pragma unroll
        for (int j = 0; j < 8; j += 4) {
            float4 bv = *(const float4*)(bias + colBase + tx * 8 + j);
            float4 val;
            val.x = acc[i][j + 0] + bv.x;
            val.y = acc[i][j + 1] + bv.y;
            val.z = acc[i][j + 2] + bv.z;
            val.w = acc[i][j + 3] + bv.w;
            if (EPI == 1) {
                float4 rv = *(const float4*)(res + base + j);
                val.x += rv.x; val.y += rv.y; val.z += rv.z; val.w += rv.w;
            }
            if (EPI == 2) {
                val.x = fmaxf(val.x, 0.f); val.y = fmaxf(val.y, 0.f);
                val.z = fmaxf(val.z, 0.f); val.w = fmaxf(val.w, 0.f);
            }
            *(float4*)(C + base + j) = val;
        }
    }
}

// ---------------- attention scores: sc[bh,i,j] = q.k/8 ----------------
__global__ __launch_bounds__(256)
void scores_kernel(const float* __restrict__ q, const float* __restrict__ k,
                   float* __restrict__ sc) {
    int bh = blockIdx.z;
    int b = bh >> 4, h = bh & 15;
    int i0 = blockIdx.y * 64, j0 = blockIdx.x * 64;
    __shared__ float qs[64][68];   // [d][row]
    __shared__ float ks[64][68];   // [d][col]
    int tid = threadIdx.x;
    for (int t = tid; t < 1024; t += 256) {
        int r  = t >> 4;
        int c4 = (t & 15) * 4;
        float4 qv = *(const float4*)(q + ((size_t)((b * Ss + i0 + r) * Hh + h)) * DHh + c4);
        qs[c4 + 0][r] = qv.x; qs[c4 + 1][r] = qv.y;
        qs[c4 + 2][r] = qv.z; qs[c4 + 3][r] = qv.w;
        float4 kv = *(const float4*)(k + ((size_t)((b * Ss + j0 + r) * Hh + h)) * DHh + c4);
        ks[c4 + 0][r] = kv.x; ks[c4 + 1][r] = kv.y;
        ks[c4 + 2][r] = kv.z; ks[c4 + 3][r] = kv.w;
    }
    __syncthreads();
    int tx = tid & 15, ty = tid >> 4;
    float acc[4][4];
    #pragma unroll
    for (int i = 0; i < 4; i++)
        #pragma unroll
        for (int j = 0; j < 4; j++) acc[i][j] = 0.f;
    #pragma unroll 8
    for (int d = 0; d < 64; ++d) {
        float4 a = *(const float4*)&qs[d][ty * 4];
        float4 c = *(const float4*)&ks[d][tx * 4];
        float av[4] = {a.x, a.y, a.z, a.w};
        float cv[4] = {c.x, c.y, c.z, c.w};
        #pragma unroll
        for (int i = 0; i < 4; i++)
            #pragma unroll
            for (int j = 0; j < 4; j++)
                acc[i][j] = fmaf(av[i], cv[j], acc[i][j]);
    }
    #pragma unroll
    for (int i = 0; i < 4; i++) {
        int gi = i0 + ty * 4 + i;
        float4 o;
        o.x = acc[i][0] * 0.125f; o.y = acc[i][1] * 0.125f;
        o.z = acc[i][2] * 0.125f; o.w = acc[i][3] * 0.125f;
        *(float4*)(sc + ((size_t)bh * Ss + gi) * Ss + j0 + tx * 4) = o;
    }
}

// ---------------- row softmax with key-position mask ----------------
__global__ __launch_bounds__(256)
void softmax_kernel(float* __restrict__ sc, const int* __restrict__ vlen) {
    int row = blockIdx.x;              // b*H*S + h*S + i
    int b = row >> 14;                 // /(H*S)
    int vl = g_is64 ? (int)((const long long*)vlen)[b] : vlen[b];
    float* sr = sc + (size_t)row * Ss;
    int tid = threadIdx.x;
    int j0 = tid * 4;
    float4 vv = *(const float4*)(sr + j0);
    float vals[4] = {vv.x, vv.y, vv.z, vv.w};
    #pragma unroll
    for (int c = 0; c < 4; c++) if (j0 + c >= vl) vals[c] = -1e9f;
    float m = fmaxf(fmaxf(vals[0], vals[1]), fmaxf(vals[2], vals[3]));
    #pragma unroll
    for (int o = 16; o; o >>= 1) m = fmaxf(m, __shfl_xor_sync(0xffffffffu, m, o));
    __shared__ float r1[8];
    int lane = tid & 31, wid = tid >> 5;
    if (lane == 0) r1[wid] = m;
    __syncthreads();
    __shared__ float Ms;
    if (tid == 0) {
        float t = r1[0];
        #pragma unroll
        for (int w = 1; w < 8; w++) t = fmaxf(t, r1[w]);
        Ms = t;
    }
    __syncthreads();
    float M = Ms;
    float e[4];
    float s = 0.f;
    #pragma unroll
    for (int c = 0; c < 4; c++) { e[c] = expf(vals[c] - M); s += e[c]; }
    #pragma unroll
    for (int o = 16; o; o >>= 1) s += __shfl_xor_sync(0xffffffffu, s, o);
    __shared__ float r2[8];
    if (lane == 0) r2[wid] = s;
    __syncthreads();
    __shared__ float Ssum;
    if (tid == 0) {
        float t = 0.f;
        #pragma unroll
        for (int w = 0; w < 8; w++) t += r2[w];
        Ssum = t;
    }
    __syncthreads();
    float inv = 1.0f / Ssum;
    float4 o4;
    o4.x = e[0] * inv; o4.y = e[1] * inv; o4.z = e[2] * inv; o4.w = e[3] * inv;
    *(float4*)(sr + j0) = o4;
}

// ---------------- ctx = attn @ v  (per b,h; N = DH = 64) ----------------
__global__ __launch_bounds__(256)
void ctx_kernel(const float* __restrict__ sc, const float* __restrict__ v,
                float* __restrict__ ctx) {
    int bh = blockIdx.y;
    int b = bh >> 4, h = bh & 15;
    int i0 = blockIdx.x * 64;
    __shared__ float as[64][68];   // [kk][i]  (attn transposed)
    __shared__ float vs[64][68];   // [kk][d]
    int tid = threadIdx.x;
    int tx = tid & 15, ty = tid >> 4;
    float acc[4][4];
    #pragma unroll
    for (int i = 0; i < 4; i++)
        #pragma unroll
        for (int j = 0; j < 4; j++) acc[i][j] = 0.f;
    for (int kt = 0; kt < Ss; kt += 64) {
        for (int t = tid; t < 1024; t += 256) {
            int r  = t >> 4;
            int c4 = (t & 15) * 4;
            float4 av = *(const float4*)(sc + ((size_t)bh * Ss + i0 + r) * Ss + kt + c4);
            as[c4 + 0][r] = av.x; as[c4 + 1][r] = av.y;
            as[c4 + 2][r] = av.z; as[c4 + 3][r] = av.w;
            float4 vv = *(const float4*)(v + ((size_t)((b * Ss + kt + r) * Hh + h)) * DHh + c4);
            *(float4*)&vs[r][c4] = vv;
        }
        __syncthreads();
        #pragma unroll 8
        for (int kk = 0; kk < 64; ++kk) {
            float4 a = *(const float4*)&as[kk][ty * 4];
            float4 c = *(const float4*)&vs[kk][tx * 4];
            float av[4] = {a.x, a.y, a.z, a.w};
            float cv[4] = {c.x, c.y, c.z, c.w};
            #pragma unroll
            for (int i = 0; i < 4; i++)
                #pragma unroll
                for (int j = 0; j < 4; j++)
                    acc[i][j] = fmaf(av[i], cv[j], acc[i][j]);
        }
        __syncthreads();
    }
    #pragma unroll
    for (int i = 0; i < 4; i++) {
        size_t base = ((size_t)((b * Ss + i0 + ty * 4 + i) * Hh + h)) * DHh + tx * 4;
        float4 o = {acc[i][0], acc[i][1], acc[i][2], acc[i][3]};
        *(float4*)(ctx + base) = o;
    }
}

// ---------------- launch ----------------
extern "C" void kernel_launch(void* const* d_in, const int* in_sizes, int n_in,
                              void* d_out, int out_size) {
    const int*   x    = (const int*)d_in[0];
    const int*   vlen = (const int*)d_in[1];
    const float* emb  = (const float*)d_in[2];
    const float* pos  = (const float*)d_in[3];
    const float* Wq = (const float*)d_in[4]  + (size_t)LAYER * Dd * Dd;
    const float* bq = (const float*)d_in[5]  + LAYER * Dd;
    const float* Wk = (const float*)d_in[6]  + (size_t)LAYER * Dd * Dd;
    const float* bk = (const float*)d_in[7]  + LAYER * Dd;
    const float* Wv = (const float*)d_in[8]  + (size_t)LAYER * Dd * Dd;
    const float* bv = (const float*)d_in[9]  + LAYER * Dd;
    const float* Wo = (const float*)d_in[10] + (size_t)LAYER * Dd * Dd;
    const float* bo = (const float*)d_in[11] + LAYER * Dd;
    const float* W1 = (const float*)d_in[12] + (size_t)LAYER * Dd * FFf;
    const float* b1 = (const float*)d_in[13] + LAYER * FFf;
    const float* W2 = (const float*)d_in[14] + (size_t)LAYER * FFf * Dd;
    const float* b2 = (const float*)d_in[15] + LAYER * Dd;
    const float* g1    = (const float*)d_in[16] + LAYER * Dd;
    const float* beta1 = (const float*)d_in[17] + LAYER * Dd;
    const float* g2    = (const float*)d_in[18] + LAYER * Dd;
    const float* beta2 = (const float*)d_in[19] + LAYER * Dd;
    float* out = (float*)d_out;

    float *h, *x1, *q, *k, *v, *sc, *ctx, *mid, *x2, *ffn;
    cudaGetSymbolAddress((void**)&h,   g_h);
    cudaGetSymbolAddress((void**)&x1,  g_x1);
    cudaGetSymbolAddress((void**)&q,   g_q);
    cudaGetSymbolAddress((void**)&k,   g_k);
    cudaGetSymbolAddress((void**)&v,   g_v);
    cudaGetSymbolAddress((void**)&sc,  g_sc);
    cudaGetSymbolAddress((void**)&ctx, g_ctx);
    cudaGetSymbolAddress((void**)&mid, g_mid);
    cudaGetSymbolAddress((void**)&x2,  g_x2);
    cudaGetSymbolAddress((void**)&ffn, g_ffn);

    detect_kernel<<<1, 256>>>(x);
    embed_kernel<<<(MROWS * (Dd/4)) / 256, 256>>>(x, emb, pos, h);
    ln_kernel<<<MROWS, 256>>>(h, g1, beta1, x1);

    dim3 gdd(Dd / BN, MROWS / BM);             // (8, 64)
    sgemm_kernel<0><<<gdd, 256>>>(x1, Wq, bq, nullptr, q, MROWS, Dd, Dd);
    sgemm_kernel<0><<<gdd, 256>>>(x1, Wk, bk, nullptr, k, MROWS, Dd, Dd);
    sgemm_kernel<0><<<gdd, 256>>>(x1, Wv, bv, nullptr, v, MROWS, Dd, Dd);

    dim3 gs(Ss / 64, Ss / 64, Bb * Hh);
    scores_kernel<<<gs, 256>>>(q, k, sc);
    softmax_kernel<<<Bb * Hh * Ss, 256>>>(sc, vlen);
    dim3 gc(Ss / 64, Bb * Hh);
    ctx_kernel<<<gc, 256>>>(sc, v, ctx);

    sgemm_kernel<1><<<gdd, 256>>>(ctx, Wo, bo, h, mid, MROWS, Dd, Dd);
    ln_kernel<<<MROWS, 256>>>(mid, g2, beta2, x2);

    dim3 gff(FFf / BN, MROWS / BM);            // (32, 64)
    sgemm_kernel<2><<<gff, 256>>>(x2, W1, b1, nullptr, ffn, MROWS, FFf, Dd);
    sgemm_kernel<1><<<gdd, 256>>>(ffn, W2, b2, mid, out, MROWS, Dd, FFf);
}

// round 5
// speedup vs baseline: 1.6159x; 1.6159x over previous
#include <cuda_runtime.h>
#include <cuda_bf16.h>
#include <mma.h>
#include <math.h>
#include <stdint.h>

using namespace nvcuda;

#define Bb 8
#define Ss 1024
#define Dd 1024
#define Hh 16
#define DHh 64
#define FFf 4096
#define LAYER 3
#define MROWS (Bb*Ss)   /* 8192 */

// ---------------- scratch (device globals; allocation-free rule) ----------------
__device__ float g_h  [MROWS*Dd];
__device__ float g_x1 [MROWS*Dd];
__device__ float g_q  [MROWS*Dd];
__device__ float g_k  [MROWS*Dd];
__device__ float g_v  [MROWS*Dd];
__device__ float g_sc [(size_t)Bb*Hh*Ss*Ss];   // 512 MB scores/attn
__device__ float g_ctx[MROWS*Dd];
__device__ float g_mid[MROWS*Dd];
__device__ float g_x2 [MROWS*Dd];
__device__ float g_ffn[(size_t)MROWS*FFf];
__device__ __nv_bfloat16 g_Ah[(size_t)MROWS*FFf];
__device__ __nv_bfloat16 g_Al[(size_t)MROWS*FFf];
__device__ __nv_bfloat16 g_Bh[(size_t)FFf*Dd];
__device__ __nv_bfloat16 g_Bl[(size_t)FFf*Dd];
__device__ int   g_is64;

// ==================== dtype detection ====================
__global__ void detect_kernel(const int* __restrict__ x) {
    __shared__ int any;
    if (threadIdx.x == 0) any = 0;
    __syncthreads();
    int local = 0;
    for (int i = threadIdx.x; i < 4096; i += blockDim.x)
        if (x[2*i + 1] != 0) local = 1;
    if (local) any = 1;
    __syncthreads();
    if (threadIdx.x == 0) g_is64 = (any == 0) ? 1 : 0;
}

// ==================== embed ====================
__global__ void embed_kernel(const int* __restrict__ x, const float* __restrict__ emb,
                             const float* __restrict__ pos, float* __restrict__ h) {
    int i = blockIdx.x * blockDim.x + threadIdx.x;
    if (i >= MROWS * (Dd/4)) return;
    int row = i >> 8;
    int dc  = i & 255;
    int s   = row & (Ss - 1);
    long long tok = g_is64 ? ((const long long*)x)[row] : (long long)x[row];
    float4 e = ((const float4*)emb)[(size_t)tok * 256 + dc];
    float4 p = ((const float4*)pos)[(size_t)s   * 256 + dc];
    float4 r;
    r.x = fmaf(e.x, 32.0f, p.x);
    r.y = fmaf(e.y, 32.0f, p.y);
    r.z = fmaf(e.z, 32.0f, p.z);
    r.w = fmaf(e.w, 32.0f, p.w);
    ((float4*)h)[i] = r;
}

// ==================== layernorm ====================
__global__ __launch_bounds__(256)
void ln_kernel(const float* __restrict__ in, const float* __restrict__ gamma,
               const float* __restrict__ beta, float* __restrict__ out) {
    int row = blockIdx.x;
    int tid = threadIdx.x;
    const float4* xr = (const float4*)(in + (size_t)row * Dd);
    float4 v = xr[tid];
    float s1 = v.x + v.y + v.z + v.w;
    float s2 = v.x*v.x + v.y*v.y + v.z*v.z + v.w*v.w;
    #pragma unroll
    for (int o = 16; o; o >>= 1) {
        s1 += __shfl_xor_sync(0xffffffffu, s1, o);
        s2 += __shfl_xor_sync(0xffffffffu, s2, o);
    }
    __shared__ float a1[8], a2[8];
    int lane = tid & 31, wid = tid >> 5;
    if (lane == 0) { a1[wid] = s1; a2[wid] = s2; }
    __syncthreads();
    __shared__ float mS, invS;
    if (tid == 0) {
        float t1 = 0.f, t2 = 0.f;
        #pragma unroll
        for (int w = 0; w < 8; ++w) { t1 += a1[w]; t2 += a2[w]; }
        float mean = t1 * (1.0f / Dd);
        float var  = t2 * (1.0f / Dd) - mean * mean;
        mS = mean; invS = rsqrtf(var + 1e-5f);
    }
    __syncthreads();
    float mean = mS, inv = invS;
    float4 g4 = ((const float4*)gamma)[tid];
    float4 b4 = ((const float4*)beta)[tid];
    float4 o4;
    o4.x = (v.x - mean) * inv * g4.x + b4.x;
    o4.y = (v.y - mean) * inv * g4.y + b4.y;
    o4.z = (v.z - mean) * inv * g4.z + b4.z;
    o4.w = (v.w - mean) * inv * g4.w + b4.w;
    ((float4*)(out + (size_t)row * Dd))[tid] = o4;
}

// ==================== fp32 -> split bf16 (hi/lo), same layout ====================
__global__ void convsplit_kernel(const float* __restrict__ in, __nv_bfloat16* __restrict__ hi,
                                 __nv_bfloat16* __restrict__ lo, int n4) {
    int i = blockIdx.x * blockDim.x + threadIdx.x;
    if (i >= n4) return;
    float4 v = ((const float4*)in)[i];
    __nv_bfloat16 h0 = __float2bfloat16(v.x), h1 = __float2bfloat16(v.y);
    __nv_bfloat16 h2 = __float2bfloat16(v.z), h3 = __float2bfloat16(v.w);
    __nv_bfloat16 l0 = __float2bfloat16(v.x - __bfloat162float(h0));
    __nv_bfloat16 l1 = __float2bfloat16(v.y - __bfloat162float(h1));
    __nv_bfloat16 l2 = __float2bfloat16(v.z - __bfloat162float(h2));
    __nv_bfloat16 l3 = __float2bfloat16(v.w - __bfloat162float(h3));
    __nv_bfloat162* H = (__nv_bfloat162*)hi;
    __nv_bfloat162* L = (__nv_bfloat162*)lo;
    H[2*i]   = __nv_bfloat162(h0, h1);
    H[2*i+1] = __nv_bfloat162(h2, h3);
    L[2*i]   = __nv_bfloat162(l0, l1);
    L[2*i+1] = __nv_bfloat162(l2, l3);
}

// ==================== weight fp32 [K,N] -> split bf16 transposed [N,K] ====================
__global__ void convtrans_kernel(const float* __restrict__ W, __nv_bfloat16* __restrict__ TH,
                                 __nv_bfloat16* __restrict__ TL, int K, int N) {
    __shared__ float t[32][33];
    int nb = blockIdx.x * 32, kb = blockIdx.y * 32;
    int tx = threadIdx.x, ty = threadIdx.y;
    for (int r = ty; r < 32; r += 8)
        t[r][tx] = W[(size_t)(kb + r) * N + nb + tx];
    __syncthreads();
    for (int r = ty; r < 32; r += 8) {
        float v = t[tx][r];                    // W[kb+tx][nb+r]
        __nv_bfloat16 h = __float2bfloat16(v);
        __nv_bfloat16 l = __float2bfloat16(v - __bfloat162float(h));
        size_t o = (size_t)(nb + r) * K + kb + tx;
        TH[o] = h; TL[o] = l;
    }
}

// ==================== wmma split-bf16 GEMM ====================
// C[M,N] = epi(A@W + bias [+res]); A split (Ah,Al) [M,K] row-major,
// W split transposed (Bh,Bl) [N,K].  Block 128x128, BK=32, 8 warps (2x4),
// warp tile 64x32 (4x2 wmma 16x16x16 fragments). Double-buffered SMEM.
#define WTSE 40                 /* smem tile row stride, bf16 elements */
#define WTSB 80                 /* bytes */
#define TILE_B  (128*WTSB)      /* 10240 */
#define STAGE_B (4*TILE_B)      /* 40960 */
#define SMEM_B  (2*STAGE_B)     /* 81920 */

template<int EPI>   // 0:+bias  1:+bias+res  2:relu(+bias)
__global__ __launch_bounds__(256)
void bgemm_kernel(const __nv_bfloat16* __restrict__ Ah, const __nv_bfloat16* __restrict__ Al,
                  const __nv_bfloat16* __restrict__ Bh, const __nv_bfloat16* __restrict__ Bl,
                  const float* __restrict__ bias, const float* __restrict__ res,
                  float* __restrict__ C, int N, int K) {
    extern __shared__ __align__(128) char smem[];
    int tid = threadIdx.x, wid = tid >> 5;
    int rowBase = blockIdx.y * 128, colBase = blockIdx.x * 128;
    int m0 = (wid >> 2) * 64, n0 = (wid & 3) * 32;

    // per-thread load plan: 8 x 16B chunks per stage
    // chunk v in [0,2048): tile = v>>9, row = (v&511)>>2, c = v&3
    const __nv_bfloat16* gsrc[8];
    int soff[8];
    #pragma unroll
    for (int i = 0; i < 8; ++i) {
        int v = tid + (i << 8);
        int tile = v >> 9, rem = v & 511, row = rem >> 2, c = rem & 3;
        const __nv_bfloat16* base =
            (tile == 0) ? Ah : (tile == 1) ? Al : (tile == 2) ? Bh : Bl;
        int grow = (tile < 2) ? (rowBase + row) : (colBase + row);
        gsrc[i] = base + (size_t)grow * K + c * 8;
        soff[i] = tile * TILE_B + row * WTSB + c * 16;
    }

    wmma::fragment<wmma::accumulator, 16, 16, 16, float> acc[4][2];
    #pragma unroll
    for (int mf = 0; mf < 4; ++mf)
        #pragma unroll
        for (int nf = 0; nf < 2; ++nf)
            wmma::fill_fragment(acc[mf][nf], 0.0f);

    const int nch = K >> 5;
    uint4 rg[8];
    #pragma unroll
    for (int i = 0; i < 8; ++i) rg[i] = *(const uint4*)(gsrc[i]);
    #pragma unroll
    for (int i = 0; i < 8; ++i) *(uint4*)(smem + soff[i]) = rg[i];
    __syncthreads();

    for (int ch = 0; ch < nch; ++ch) {
        if (ch + 1 < nch) {
            #pragma unroll
            for (int i = 0; i < 8; ++i)
                rg[i] = *(const uint4*)(gsrc[i] + (size_t)(ch + 1) * 32);
        }
        char* stage = smem + (ch & 1) * STAGE_B;
        #pragma unroll
        for (int sp = 0; sp < 3; ++sp) {
            const __nv_bfloat16* At = (const __nv_bfloat16*)(stage + ((sp == 2) ? TILE_B : 0));
            const __nv_bfloat16* Bt = (const __nv_bfloat16*)(stage + ((sp == 1) ? 3 * TILE_B : 2 * TILE_B));
            #pragma unroll
            for (int ks = 0; ks < 2; ++ks) {
                wmma::fragment<wmma::matrix_a, 16, 16, 16, __nv_bfloat16, wmma::row_major> af[4];
                wmma::fragment<wmma::matrix_b, 16, 16, 16, __nv_bfloat16, wmma::col_major> bfr[2];
                #pragma unroll
                for (int mf = 0; mf < 4; ++mf)
                    wmma::load_matrix_sync(af[mf], At + (m0 + mf * 16) * WTSE + ks * 16, WTSE);
                #pragma unroll
                for (int nf = 0; nf < 2; ++nf)
                    wmma::load_matrix_sync(bfr[nf], Bt + (n0 + nf * 16) * WTSE + ks * 16, WTSE);
                #pragma unroll
                for (int mf = 0; mf < 4; ++mf)
                    #pragma unroll
                    for (int nf = 0; nf < 2; ++nf)
                        wmma::mma_sync(acc[mf][nf], af[mf], bfr[nf], acc[mf][nf]);
            }
        }
        __syncthreads();
        if (ch + 1 < nch) {
            #pragma unroll
            for (int i = 0; i < 8; ++i)
                *(uint4*)(smem + ((ch + 1) & 1) * STAGE_B + soff[i]) = rg[i];
            __syncthreads();
        }
    }

    // ---- epilogue: fragments -> smem (stride 132) -> global with bias/res/relu ----
    float* sf = (float*)smem;
    #pragma unroll
    for (int mf = 0; mf < 4; ++mf)
        #pragma unroll
        for (int nf = 0; nf < 2; ++nf)
            wmma::store_matrix_sync(sf + (m0 + mf * 16) * 132 + n0 + nf * 16,
                                    acc[mf][nf], 132, wmma::mem_row_major);
    __syncthreads();
    #pragma unroll
    for (int i = 0; i < 16; ++i) {
        int v = tid + (i << 8);          // 4096 float4s = 128x128
        int r = v >> 5, c4 = (v & 31) * 4;
        float4 val = *(float4*)(sf + r * 132 + c4);
        int col = colBase + c4;
        float4 bv = *(const float4*)(bias + col);
        val.x += bv.x; val.y += bv.y; val.z += bv.z; val.w += bv.w;
        size_t o = (size_t)(rowBase + r) * N + col;
        if (EPI == 1) {
            float4 rv = *(const float4*)(res + o);
            val.x += rv.x; val.y += rv.y; val.z += rv.z; val.w += rv.w;
        }
        if (EPI == 2) {
            val.x = fmaxf(val.x, 0.f); val.y = fmaxf(val.y, 0.f);
            val.z = fmaxf(val.z, 0.f); val.w = fmaxf(val.w, 0.f);
        }
        *(float4*)(C + o) = val;
    }
}

// ==================== attention scores ====================
__global__ __launch_bounds__(256)
void scores_kernel(const float* __restrict__ q, const float* __restrict__ k,
                   float* __restrict__ sc) {
    int bh = blockIdx.z;
    int b = bh >> 4, h = bh & 15;
    int i0 = blockIdx.y * 64, j0 = blockIdx.x * 64;
    __shared__ float qs[64][68];
    __shared__ float ks[64][68];
    int tid = threadIdx.x;
    for (int t = tid; t < 1024; t += 256) {
        int r  = t >> 4;
        int c4 = (t & 15) * 4;
        float4 qv = *(const float4*)(q + ((size_t)((b * Ss + i0 + r) * Hh + h)) * DHh + c4);
        qs[c4 + 0][r] = qv.x; qs[c4 + 1][r] = qv.y;
        qs[c4 + 2][r] = qv.z; qs[c4 + 3][r] = qv.w;
        float4 kv = *(const float4*)(k + ((size_t)((b * Ss + j0 + r) * Hh + h)) * DHh + c4);
        ks[c4 + 0][r] = kv.x; ks[c4 + 1][r] = kv.y;
        ks[c4 + 2][r] = kv.z; ks[c4 + 3][r] = kv.w;
    }
    __syncthreads();
    int tx = tid & 15, ty = tid >> 4;
    float acc[4][4];
    #pragma unroll
    for (int i = 0; i < 4; i++)
        #pragma unroll
        for (int j = 0; j < 4; j++) acc[i][j] = 0.f;
    #pragma unroll 8
    for (int d = 0; d < 64; ++d) {
        float4 a = *(const float4*)&qs[d][ty * 4];
        float4 c = *(const float4*)&ks[d][tx * 4];
        float av[4] = {a.x, a.y, a.z, a.w};
        float cv[4] = {c.x, c.y, c.z, c.w};
        #pragma unroll
        for (int i = 0; i < 4; i++)
            #pragma unroll
            for (int j = 0; j < 4; j++)
                acc[i][j] = fmaf(av[i], cv[j], acc[i][j]);
    }
    #pragma unroll
    for (int i = 0; i < 4; i++) {
        int gi = i0 + ty * 4 + i;
        float4 o;
        o.x = acc[i][0] * 0.125f; o.y = acc[i][1] * 0.125f;
        o.z = acc[i][2] * 0.125f; o.w = acc[i][3] * 0.125f;
        *(float4*)(sc + ((size_t)bh * Ss + gi) * Ss + j0 + tx * 4) = o;
    }
}

// ==================== softmax ====================
__global__ __launch_bounds__(256)
void softmax_kernel(float* __restrict__ sc, const int* __restrict__ vlen) {
    int row = blockIdx.x;
    int b = row >> 14;
    int vl = g_is64 ? (int)((const long long*)vlen)[b] : vlen[b];
    float* sr = sc + (size_t)row * Ss;
    int tid = threadIdx.x;
    int j0 = tid * 4;
    float4 vv = *(const float4*)(sr + j0);
    float vals[4] = {vv.x, vv.y, vv.z, vv.w};
    #pragma unroll
    for (int c = 0; c < 4; c++) if (j0 + c >= vl) vals[c] = -1e9f;
    float m = fmaxf(fmaxf(vals[0], vals[1]), fmaxf(vals[2], vals[3]));
    #pragma unroll
    for (int o = 16; o; o >>= 1) m = fmaxf(m, __shfl_xor_sync(0xffffffffu, m, o));
    __shared__ float r1[8];
    int lane = tid & 31, wid = tid >> 5;
    if (lane == 0) r1[wid] = m;
    __syncthreads();
    __shared__ float Ms;
    if (tid == 0) {
        float t = r1[0];
        #pragma unroll
        for (int w = 1; w < 8; w++) t = fmaxf(t, r1[w]);
        Ms = t;
    }
    __syncthreads();
    float M = Ms;
    float e[4];
    float s = 0.f;
    #pragma unroll
    for (int c = 0; c < 4; c++) { e[c] = expf(vals[c] - M); s += e[c]; }
    #pragma unroll
    for (int o = 16; o; o >>= 1) s += __shfl_xor_sync(0xffffffffu, s, o);
    __shared__ float r2[8];
    if (lane == 0) r2[wid] = s;
    __syncthreads();
    __shared__ float Ssum;
    if (tid == 0) {
        float t = 0.f;
        #pragma unroll
        for (int w = 0; w < 8; w++) t += r2[w];
        Ssum = t;
    }
    __syncthreads();
    float inv = 1.0f / Ssum;
    float4 o4;
    o4.x = e[0] * inv; o4.y = e[1] * inv; o4.z = e[2] * inv; o4.w = e[3] * inv;
    *(float4*)(sr + j0) = o4;
}

// ==================== ctx = attn @ v ====================
__global__ __launch_bounds__(256)
void ctx_kernel(const float* __restrict__ sc, const float* __restrict__ v,
                float* __restrict__ ctx) {
    int bh = blockIdx.y;
    int b = bh >> 4, h = bh & 15;
    int i0 = blockIdx.x * 64;
    __shared__ float as[64][68];
    __shared__ float vs[64][68];
    int tid = threadIdx.x;
    int tx = tid & 15, ty = tid >> 4;
    float acc[4][4];
    #pragma unroll
    for (int i = 0; i < 4; i++)
        #pragma unroll
        for (int j = 0; j < 4; j++) acc[i][j] = 0.f;
    for (int kt = 0; kt < Ss; kt += 64) {
        for (int t = tid; t < 1024; t += 256) {
            int r  = t >> 4;
            int c4 = (t & 15) * 4;
            float4 av = *(const float4*)(sc + ((size_t)bh * Ss + i0 + r) * Ss + kt + c4);
            as[c4 + 0][r] = av.x; as[c4 + 1][r] = av.y;
            as[c4 + 2][r] = av.z; as[c4 + 3][r] = av.w;
            float4 vv = *(const float4*)(v + ((size_t)((b * Ss + kt + r) * Hh + h)) * DHh + c4);
            *(float4*)&vs[r][c4] = vv;
        }
        __syncthreads();
        #pragma unroll 8
        for (int kk = 0; kk < 64; ++kk) {
            float4 a = *(const float4*)&as[kk][ty * 4];
            float4 c = *(const float4*)&vs[kk][tx * 4];
            float av[4] = {a.x, a.y, a.z, a.w};
            float cv[4] = {c.x, c.y, c.z, c.w};
            #pragma unroll
            for (int i = 0; i < 4; i++)
                #pragma unroll
                for (int j = 0; j < 4; j++)
                    acc[i][j] = fmaf(av[i], cv[j], acc[i][j]);
        }
        __syncthreads();
    }
    #pragma unroll
    for (int i = 0; i < 4; i++) {
        size_t base = ((size_t)((b * Ss + i0 + ty * 4 + i) * Hh + h)) * DHh + tx * 4;
        float4 o = {acc[i][0], acc[i][1], acc[i][2], acc[i][3]};
        *(float4*)(ctx + base) = o;
    }
}

// ==================== launch ====================
extern "C" void kernel_launch(void* const* d_in, const int* in_sizes, int n_in,
                              void* d_out, int out_size) {
    const int*   x    = (const int*)d_in[0];
    const int*   vlen = (const int*)d_in[1];
    const float* emb  = (const float*)d_in[2];
    const float* pos  = (const float*)d_in[3];
    const float* Wq = (const float*)d_in[4]  + (size_t)LAYER * Dd * Dd;
    const float* bq = (const float*)d_in[5]  + LAYER * Dd;
    const float* Wk = (const float*)d_in[6]  + (size_t)LAYER * Dd * Dd;
    const float* bk = (const float*)d_in[7]  + LAYER * Dd;
    const float* Wv = (const float*)d_in[8]  + (size_t)LAYER * Dd * Dd;
    const float* bv = (const float*)d_in[9]  + LAYER * Dd;
    const float* Wo = (const float*)d_in[10] + (size_t)LAYER * Dd * Dd;
    const float* bo = (const float*)d_in[11] + LAYER * Dd;
    const float* W1 = (const float*)d_in[12] + (size_t)LAYER * Dd * FFf;
    const float* b1 = (const float*)d_in[13] + LAYER * FFf;
    const float* W2 = (const float*)d_in[14] + (size_t)LAYER * FFf * Dd;
    const float* b2 = (const float*)d_in[15] + LAYER * Dd;
    const float* g1    = (const float*)d_in[16] + LAYER * Dd;
    const float* beta1 = (const float*)d_in[17] + LAYER * Dd;
    const float* g2    = (const float*)d_in[18] + LAYER * Dd;
    const float* beta2 = (const float*)d_in[19] + LAYER * Dd;
    float* out = (float*)d_out;

    float *h, *x1, *q, *k, *v, *sc, *ctx, *mid, *x2, *ffn;
    __nv_bfloat16 *Ah, *Al, *Bh, *Bl;
    cudaGetSymbolAddress((void**)&h,   g_h);
    cudaGetSymbolAddress((void**)&x1,  g_x1);
    cudaGetSymbolAddress((void**)&q,   g_q);
    cudaGetSymbolAddress((void**)&k,   g_k);
    cudaGetSymbolAddress((void**)&v,   g_v);
    cudaGetSymbolAddress((void**)&sc,  g_sc);
    cudaGetSymbolAddress((void**)&ctx, g_ctx);
    cudaGetSymbolAddress((void**)&mid, g_mid);
    cudaGetSymbolAddress((void**)&x2,  g_x2);
    cudaGetSymbolAddress((void**)&ffn, g_ffn);
    cudaGetSymbolAddress((void**)&Ah,  g_Ah);
    cudaGetSymbolAddress((void**)&Al,  g_Al);
    cudaGetSymbolAddress((void**)&Bh,  g_Bh);
    cudaGetSymbolAddress((void**)&Bl,  g_Bl);

    cudaFuncSetAttribute(bgemm_kernel<0>, cudaFuncAttributeMaxDynamicSharedMemorySize, SMEM_B);
    cudaFuncSetAttribute(bgemm_kernel<1>, cudaFuncAttributeMaxDynamicSharedMemorySize, SMEM_B);
    cudaFuncSetAttribute(bgemm_kernel<2>, cudaFuncAttributeMaxDynamicSharedMemorySize, SMEM_B);

    detect_kernel<<<1, 256>>>(x);
    embed_kernel<<<(MROWS * (Dd/4)) / 256, 256>>>(x, emb, pos, h);
    ln_kernel<<<MROWS, 256>>>(h, g1, beta1, x1);

    dim3 blkT(32, 8);
    dim3 gdd(Dd / 128, MROWS / 128);           // (8, 64)

    convsplit_kernel<<<(MROWS * Dd / 4) / 256, 256>>>(x1, Ah, Al, MROWS * Dd / 4);
    convtrans_kernel<<<dim3(Dd/32, Dd/32), blkT>>>(Wq, Bh, Bl, Dd, Dd);
    bgemm_kernel<0><<<gdd, 256, SMEM_B>>>(Ah, Al, Bh, Bl, bq, nullptr, q, Dd, Dd);
    convtrans_kernel<<<dim3(Dd/32, Dd/32), blkT>>>(Wk, Bh, Bl, Dd, Dd);
    bgemm_kernel<0><<<gdd, 256, SMEM_B>>>(Ah, Al, Bh, Bl, bk, nullptr, k, Dd, Dd);
    convtrans_kernel<<<dim3(Dd/32, Dd/32), blkT>>>(Wv, Bh, Bl, Dd, Dd);
    bgemm_kernel<0><<<gdd, 256, SMEM_B>>>(Ah, Al, Bh, Bl, bv, nullptr, v, Dd, Dd);

    dim3 gs(Ss / 64, Ss / 64, Bb * Hh);
    scores_kernel<<<gs, 256>>>(q, k, sc);
    softmax_kernel<<<Bb * Hh * Ss, 256>>>(sc, vlen);
    dim3 gc(Ss / 64, Bb * Hh);
    ctx_kernel<<<gc, 256>>>(sc, v, ctx);

    convsplit_kernel<<<(MROWS * Dd / 4) / 256, 256>>>(ctx, Ah, Al, MROWS * Dd / 4);
    convtrans_kernel<<<dim3(Dd/32, Dd/32), blkT>>>(Wo, Bh, Bl, Dd, Dd);
    bgemm_kernel<1><<<gdd, 256, SMEM_B>>>(Ah, Al, Bh, Bl, bo, h, mid, Dd, Dd);

    ln_kernel<<<MROWS, 256>>>(mid, g2, beta2, x2);

    convsplit_kernel<<<(MROWS * Dd / 4) / 256, 256>>>(x2, Ah, Al, MROWS * Dd / 4);
    convtrans_kernel<<<dim3(FFf/32, Dd/32), blkT>>>(W1, Bh, Bl, Dd, FFf);
    dim3 gff(FFf / 128, MROWS / 128);          // (32, 64)
    bgemm_kernel<2><<<gff, 256, SMEM_B>>>(Ah, Al, Bh, Bl, b1, nullptr, ffn, FFf, Dd);

    convsplit_kernel<<<(MROWS * FFf / 4) / 256, 256>>>(ffn, Ah, Al, MROWS * FFf / 4);
    convtrans_kernel<<<dim3(Dd/32, FFf/32), blkT>>>(W2, Bh, Bl, FFf, Dd);
    bgemm_kernel<1><<<gdd, 256, SMEM_B>>>(Ah, Al, Bh, Bl, b2, mid, out, Dd, FFf);
}

// round 7
// speedup vs baseline: 1.8350x; 1.1356x over previous
#include <cuda_runtime.h>
#include <cuda_bf16.h>
#include <mma.h>
#include <math.h>
#include <stdint.h>

using namespace nvcuda;

#define Bb 8
#define Ss 1024
#define Dd 1024
#define Hh 16
#define DHh 64
#define FFf 4096
#define LAYER 3
#define MROWS (Bb*Ss)   /* 8192 */

// ---------------- scratch (device globals; allocation-free rule) ----------------
__device__ float g_h  [MROWS*Dd];
__device__ float g_x1 [MROWS*Dd];
__device__ float g_q  [MROWS*Dd];
__device__ float g_k  [MROWS*Dd];
__device__ float g_v  [MROWS*Dd];
__device__ float g_sc [(size_t)Bb*Hh*Ss*Ss];   // 512 MB scores
__device__ float g_ctx[MROWS*Dd];
__device__ float g_mid[MROWS*Dd];
__device__ float g_x2 [MROWS*Dd];
__device__ float g_ffn[(size_t)MROWS*FFf];
__device__ __nv_bfloat16 g_Ah[(size_t)MROWS*FFf];
__device__ __nv_bfloat16 g_Al[(size_t)MROWS*FFf];
__device__ __nv_bfloat16 g_Bh[(size_t)FFf*Dd];
__device__ __nv_bfloat16 g_Bl[(size_t)FFf*Dd];
__device__ __nv_bfloat16 g_qh[MROWS*Dd];
__device__ __nv_bfloat16 g_ql[MROWS*Dd];
__device__ __nv_bfloat16 g_kh[MROWS*Dd];
__device__ __nv_bfloat16 g_kl[MROWS*Dd];
__device__ __nv_bfloat16 g_vh[MROWS*Dd];
__device__ __nv_bfloat16 g_vl[MROWS*Dd];
__device__ __nv_bfloat16 g_ah[(size_t)Bb*Hh*Ss*Ss];   // 256 MB attn hi
__device__ __nv_bfloat16 g_al[(size_t)Bb*Hh*Ss*Ss];   // 256 MB attn lo
__device__ int   g_is64;

// ==================== dtype detection ====================
__global__ void detect_kernel(const int* __restrict__ x) {
    __shared__ int any;
    if (threadIdx.x == 0) any = 0;
    __syncthreads();
    int local = 0;
    for (int i = threadIdx.x; i < 4096; i += blockDim.x)
        if (x[2*i + 1] != 0) local = 1;
    if (local) any = 1;
    __syncthreads();
    if (threadIdx.x == 0) g_is64 = (any == 0) ? 1 : 0;
}

// ==================== embed ====================
__global__ void embed_kernel(const int* __restrict__ x, const float* __restrict__ emb,
                             const float* __restrict__ pos, float* __restrict__ h) {
    int i = blockIdx.x * blockDim.x + threadIdx.x;
    if (i >= MROWS * (Dd/4)) return;
    int row = i >> 8;
    int dc  = i & 255;
    int s   = row & (Ss - 1);
    long long tok = g_is64 ? ((const long long*)x)[row] : (long long)x[row];
    float4 e = ((const float4*)emb)[(size_t)tok * 256 + dc];
    float4 p = ((const float4*)pos)[(size_t)s   * 256 + dc];
    float4 r;
    r.x = fmaf(e.x, 32.0f, p.x);
    r.y = fmaf(e.y, 32.0f, p.y);
    r.z = fmaf(e.z, 32.0f, p.z);
    r.w = fmaf(e.w, 32.0f, p.w);
    ((float4*)h)[i] = r;
}

// ==================== layernorm ====================
__global__ __launch_bounds__(256)
void ln_kernel(const float* __restrict__ in, const float* __restrict__ gamma,
               const float* __restrict__ beta, float* __restrict__ out) {
    int row = blockIdx.x;
    int tid = threadIdx.x;
    const float4* xr = (const float4*)(in + (size_t)row * Dd);
    float4 v = xr[tid];
    float s1 = v.x + v.y + v.z + v.w;
    float s2 = v.x*v.x + v.y*v.y + v.z*v.z + v.w*v.w;
    #pragma unroll
    for (int o = 16; o; o >>= 1) {
        s1 += __shfl_xor_sync(0xffffffffu, s1, o);
        s2 += __shfl_xor_sync(0xffffffffu, s2, o);
    }
    __shared__ float a1[8], a2[8];
    int lane = tid & 31, wid = tid >> 5;
    if (lane == 0) { a1[wid] = s1; a2[wid] = s2; }
    __syncthreads();
    __shared__ float mS, invS;
    if (tid == 0) {
        float t1 = 0.f, t2 = 0.f;
        #pragma unroll
        for (int w = 0; w < 8; ++w) { t1 += a1[w]; t2 += a2[w]; }
        float mean = t1 * (1.0f / Dd);
        float var  = t2 * (1.0f / Dd) - mean * mean;
        mS = mean; invS = rsqrtf(var + 1e-5f);
    }
    __syncthreads();
    float mean = mS, inv = invS;
    float4 g4 = ((const float4*)gamma)[tid];
    float4 b4 = ((const float4*)beta)[tid];
    float4 o4;
    o4.x = (v.x - mean) * inv * g4.x + b4.x;
    o4.y = (v.y - mean) * inv * g4.y + b4.y;
    o4.z = (v.z - mean) * inv * g4.z + b4.z;
    o4.w = (v.w - mean) * inv * g4.w + b4.w;
    ((float4*)(out + (size_t)row * Dd))[tid] = o4;
}

// ==================== fp32 -> split bf16 (hi/lo), same layout ====================
__global__ void convsplit_kernel(const float* __restrict__ in, __nv_bfloat16* __restrict__ hi,
                                 __nv_bfloat16* __restrict__ lo, int n4) {
    int i = blockIdx.x * blockDim.x + threadIdx.x;
    if (i >= n4) return;
    float4 v = ((const float4*)in)[i];
    __nv_bfloat16 h0 = __float2bfloat16(v.x), h1 = __float2bfloat16(v.y);
    __nv_bfloat16 h2 = __float2bfloat16(v.z), h3 = __float2bfloat16(v.w);
    __nv_bfloat16 l0 = __float2bfloat16(v.x - __bfloat162float(h0));
    __nv_bfloat16 l1 = __float2bfloat16(v.y - __bfloat162float(h1));
    __nv_bfloat16 l2 = __float2bfloat16(v.z - __bfloat162float(h2));
    __nv_bfloat16 l3 = __float2bfloat16(v.w - __bfloat162float(h3));
    __nv_bfloat162* H = (__nv_bfloat162*)hi;
    __nv_bfloat162* L = (__nv_bfloat162*)lo;
    H[2*i]   = __nv_bfloat162(h0, h1);
    H[2*i+1] = __nv_bfloat162(h2, h3);
    L[2*i]   = __nv_bfloat162(l0, l1);
    L[2*i+1] = __nv_bfloat162(l2, l3);
}

// ==================== weight fp32 [K,N] -> split bf16 transposed [N,K] ====================
__global__ void convtrans_kernel(const float* __restrict__ W, __nv_bfloat16* __restrict__ TH,
                                 __nv_bfloat16* __restrict__ TL, int K, int N) {
    __shared__ float t[32][33];
    int nb = blockIdx.x * 32, kb = blockIdx.y * 32;
    int tx = threadIdx.x, ty = threadIdx.y;
    for (int r = ty; r < 32; r += 8)
        t[r][tx] = W[(size_t)(kb + r) * N + nb + tx];
    __syncthreads();
    for (int r = ty; r < 32; r += 8) {
        float v = t[tx][r];                    // W[kb+tx][nb+r]
        __nv_bfloat16 h = __float2bfloat16(v);
        __nv_bfloat16 l = __float2bfloat16(v - __bfloat162float(h));
        size_t o = (size_t)(nb + r) * K + kb + tx;
        TH[o] = h; TL[o] = l;
    }
}

// ==================== wmma split-bf16 GEMM ====================
#define WTSE 40
#define WTSB 80
#define TILE_B  (128*WTSB)
#define STAGE_B (4*TILE_B)
#define SMEM_B  (2*STAGE_B)

template<int EPI>   // 0:+bias  1:+bias+res  2:relu(+bias)
__global__ __launch_bounds__(256)
void bgemm_kernel(const __nv_bfloat16* __restrict__ Ah, const __nv_bfloat16* __restrict__ Al,
                  const __nv_bfloat16* __restrict__ Bh, const __nv_bfloat16* __restrict__ Bl,
                  const float* __restrict__ bias, const float* __restrict__ res,
                  float* __restrict__ C, int N, int K) {
    extern __shared__ __align__(128) char smem[];
    int tid = threadIdx.x, wid = tid >> 5;
    int rowBase = blockIdx.y * 128, colBase = blockIdx.x * 128;
    int m0 = (wid >> 2) * 64, n0 = (wid & 3) * 32;

    const __nv_bfloat16* gsrc[8];
    int soff[8];
    #pragma unroll
    for (int i = 0; i < 8; ++i) {
        int v = tid + (i << 8);
        int tile = v >> 9, rem = v & 511, row = rem >> 2, c = rem & 3;
        const __nv_bfloat16* base =
            (tile == 0) ? Ah : (tile == 1) ? Al : (tile == 2) ? Bh : Bl;
        int grow = (tile < 2) ? (rowBase + row) : (colBase + row);
        gsrc[i] = base + (size_t)grow * K + c * 8;
        soff[i] = tile * TILE_B + row * WTSB + c * 16;
    }

    wmma::fragment<wmma::accumulator, 16, 16, 16, float> acc[4][2];
    #pragma unroll
    for (int mf = 0; mf < 4; ++mf)
        #pragma unroll
        for (int nf = 0; nf < 2; ++nf)
            wmma::fill_fragment(acc[mf][nf], 0.0f);

    const int nch = K >> 5;
    uint4 rg[8];
    #pragma unroll
    for (int i = 0; i < 8; ++i) rg[i] = *(const uint4*)(gsrc[i]);
    #pragma unroll
    for (int i = 0; i < 8; ++i) *(uint4*)(smem + soff[i]) = rg[i];
    __syncthreads();

    for (int ch = 0; ch < nch; ++ch) {
        if (ch + 1 < nch) {
            #pragma unroll
            for (int i = 0; i < 8; ++i)
                rg[i] = *(const uint4*)(gsrc[i] + (size_t)(ch + 1) * 32);
        }
        char* stage = smem + (ch & 1) * STAGE_B;
        #pragma unroll
        for (int sp = 0; sp < 3; ++sp) {
            const __nv_bfloat16* At = (const __nv_bfloat16*)(stage + ((sp == 2) ? TILE_B : 0));
            const __nv_bfloat16* Bt = (const __nv_bfloat16*)(stage + ((sp == 1) ? 3 * TILE_B : 2 * TILE_B));
            #pragma unroll
            for (int ks = 0; ks < 2; ++ks) {
                wmma::fragment<wmma::matrix_a, 16, 16, 16, __nv_bfloat16, wmma::row_major> af[4];
                wmma::fragment<wmma::matrix_b, 16, 16, 16, __nv_bfloat16, wmma::col_major> bfr[2];
                #pragma unroll
                for (int mf = 0; mf < 4; ++mf)
                    wmma::load_matrix_sync(af[mf], At + (m0 + mf * 16) * WTSE + ks * 16, WTSE);
                #pragma unroll
                for (int nf = 0; nf < 2; ++nf)
                    wmma::load_matrix_sync(bfr[nf], Bt + (n0 + nf * 16) * WTSE + ks * 16, WTSE);
                #pragma unroll
                for (int mf = 0; mf < 4; ++mf)
                    #pragma unroll
                    for (int nf = 0; nf < 2; ++nf)
                        wmma::mma_sync(acc[mf][nf], af[mf], bfr[nf], acc[mf][nf]);
            }
        }
        __syncthreads();
        if (ch + 1 < nch) {
            #pragma unroll
            for (int i = 0; i < 8; ++i)
                *(uint4*)(smem + ((ch + 1) & 1) * STAGE_B + soff[i]) = rg[i];
            __syncthreads();
        }
    }

    float* sf = (float*)smem;
    #pragma unroll
    for (int mf = 0; mf < 4; ++mf)
        #pragma unroll
        for (int nf = 0; nf < 2; ++nf)
            wmma::store_matrix_sync(sf + (m0 + mf * 16) * 132 + n0 + nf * 16,
                                    acc[mf][nf], 132, wmma::mem_row_major);
    __syncthreads();
    #pragma unroll
    for (int i = 0; i < 16; ++i) {
        int v = tid + (i << 8);
        int r = v >> 5, c4 = (v & 31) * 4;
        float4 val = *(float4*)(sf + r * 132 + c4);
        int col = colBase + c4;
        float4 bv = *(const float4*)(bias + col);
        val.x += bv.x; val.y += bv.y; val.z += bv.z; val.w += bv.w;
        size_t o = (size_t)(rowBase + r) * N + col;
        if (EPI == 1) {
            float4 rv = *(const float4*)(res + o);
            val.x += rv.x; val.y += rv.y; val.z += rv.z; val.w += rv.w;
        }
        if (EPI == 2) {
            val.x = fmaxf(val.x, 0.f); val.y = fmaxf(val.y, 0.f);
            val.z = fmaxf(val.z, 0.f); val.w = fmaxf(val.w, 0.f);
        }
        *(float4*)(C + o) = val;
    }
}

// ==================== wmma attention scores ====================
// sc[bh, i, j] = (q[i].k[j]) / 8, 3-term split. Tile 128x128, K=64.
#define ATSE 72            /* smem row stride, elements */
#define ATSB 144           /* bytes */
#define STILE (128*ATSB)   /* 18432 */
#define SSMEM (4*STILE)    /* 73728 */

__global__ __launch_bounds__(256)
void scores_wmma_kernel(const __nv_bfloat16* __restrict__ qh, const __nv_bfloat16* __restrict__ ql,
                        const __nv_bfloat16* __restrict__ kh, const __nv_bfloat16* __restrict__ kl,
                        float* __restrict__ sc) {
    extern __shared__ __align__(128) char smem[];
    int bh = blockIdx.z;
    int b = bh >> 4, hh = bh & 15;
    int i0 = blockIdx.y * 128, j0 = blockIdx.x * 128;
    int tid = threadIdx.x, wid = tid >> 5;
    int m0 = (wid >> 2) * 64, n0 = (wid & 3) * 32;

    #pragma unroll
    for (int i = 0; i < 16; ++i) {
        int v = tid + (i << 8);
        int m = v >> 10, rem = v & 1023, r = rem >> 3, c = rem & 7;
        const __nv_bfloat16* mat = (m == 0) ? qh : (m == 1) ? ql : (m == 2) ? kh : kl;
        int rowg = ((m < 2) ? i0 : j0) + r;
        uint4 d = *(const uint4*)(mat + (size_t)(b * Ss + rowg) * Dd + hh * 64 + c * 8);
        *(uint4*)(smem + m * STILE + r * ATSB + c * 16) = d;
    }
    __syncthreads();

    wmma::fragment<wmma::accumulator, 16, 16, 16, float> acc[4][2];
    #pragma unroll
    for (int mf = 0; mf < 4; ++mf)
        #pragma unroll
        for (int nf = 0; nf < 2; ++nf)
            wmma::fill_fragment(acc[mf][nf], 0.0f);

    #pragma unroll
    for (int sp = 0; sp < 3; ++sp) {
        const __nv_bfloat16* At = (const __nv_bfloat16*)(smem + ((sp == 2) ? STILE : 0));
        const __nv_bfloat16* Bt = (const __nv_bfloat16*)(smem + ((sp == 1) ? 3 * STILE : 2 * STILE));
        #pragma unroll
        for (int ks = 0; ks < 4; ++ks) {
            wmma::fragment<wmma::matrix_a, 16, 16, 16, __nv_bfloat16, wmma::row_major> af[4];
            wmma::fragment<wmma::matrix_b, 16, 16, 16, __nv_bfloat16, wmma::col_major> bfr[2];
            #pragma unroll
            for (int mf = 0; mf < 4; ++mf)
                wmma::load_matrix_sync(af[mf], At + (m0 + mf * 16) * ATSE + ks * 16, ATSE);
            #pragma unroll
            for (int nf = 0; nf < 2; ++nf)
                wmma::load_matrix_sync(bfr[nf], Bt + (n0 + nf * 16) * ATSE + ks * 16, ATSE);
            #pragma unroll
            for (int mf = 0; mf < 4; ++mf)
                #pragma unroll
                for (int nf = 0; nf < 2; ++nf)
                    wmma::mma_sync(acc[mf][nf], af[mf], bfr[nf], acc[mf][nf]);
        }
    }
    #pragma unroll
    for (int mf = 0; mf < 4; ++mf)
        #pragma unroll
        for (int nf = 0; nf < 2; ++nf) {
            #pragma unroll
            for (int t = 0; t < acc[mf][nf].num_elements; ++t)
                acc[mf][nf].x[t] *= 0.125f;
            wmma::store_matrix_sync(
                sc + ((size_t)bh * Ss + i0 + m0 + mf * 16) * Ss + j0 + n0 + nf * 16,
                acc[mf][nf], Ss, wmma::mem_row_major);
        }
}

// ==================== softmax (mask + split-bf16 output) ====================
__global__ __launch_bounds__(256)
void softmax_kernel(const float* __restrict__ sc, const int* __restrict__ vlen,
                    __nv_bfloat16* __restrict__ ah, __nv_bfloat16* __restrict__ al) {
    int row = blockIdx.x;
    int b = row >> 14;
    int vl = g_is64 ? (int)((const long long*)vlen)[b] : vlen[b];
    const float* sr = sc + (size_t)row * Ss;
    int tid = threadIdx.x;
    int j0 = tid * 4;
    float4 vv = *(const float4*)(sr + j0);
    float vals[4] = {vv.x, vv.y, vv.z, vv.w};
    #pragma unroll
    for (int c = 0; c < 4; c++) if (j0 + c >= vl) vals[c] = -1e9f;
    float m = fmaxf(fmaxf(vals[0], vals[1]), fmaxf(vals[2], vals[3]));
    #pragma unroll
    for (int o = 16; o; o >>= 1) m = fmaxf(m, __shfl_xor_sync(0xffffffffu, m, o));
    __shared__ float r1[8];
    int lane = tid & 31, wid = tid >> 5;
    if (lane == 0) r1[wid] = m;
    __syncthreads();
    __shared__ float Ms;
    if (tid == 0) {
        float t = r1[0];
        #pragma unroll
        for (int w = 1; w < 8; w++) t = fmaxf(t, r1[w]);
        Ms = t;
    }
    __syncthreads();
    float M = Ms;
    float e[4];
    float s = 0.f;
    #pragma unroll
    for (int c = 0; c < 4; c++) { e[c] = expf(vals[c] - M); s += e[c]; }
    #pragma unroll
    for (int o = 16; o; o >>= 1) s += __shfl_xor_sync(0xffffffffu, s, o);
    __shared__ float r2[8];
    if (lane == 0) r2[wid] = s;
    __syncthreads();
    __shared__ float Ssum;
    if (tid == 0) {
        float t = 0.f;
        #pragma unroll
        for (int w = 0; w < 8; w++) t += r2[w];
        Ssum = t;
    }
    __syncthreads();
    float inv = 1.0f / Ssum;
    float o0 = e[0] * inv, o1 = e[1] * inv, o2 = e[2] * inv, o3 = e[3] * inv;
    __nv_bfloat16 h0 = __float2bfloat16(o0), h1 = __float2bfloat16(o1);
    __nv_bfloat16 h2 = __float2bfloat16(o2), h3 = __float2bfloat16(o3);
    __nv_bfloat16 l0 = __float2bfloat16(o0 - __bfloat162float(h0));
    __nv_bfloat16 l1 = __float2bfloat16(o1 - __bfloat162float(h1));
    __nv_bfloat16 l2 = __float2bfloat16(o2 - __bfloat162float(h2));
    __nv_bfloat16 l3 = __float2bfloat16(o3 - __bfloat162float(h3));
    size_t base = (size_t)row * Ss + j0;
    *(__nv_bfloat162*)(ah + base)     = __nv_bfloat162(h0, h1);
    *(__nv_bfloat162*)(ah + base + 2) = __nv_bfloat162(h2, h3);
    *(__nv_bfloat162*)(al + base)     = __nv_bfloat162(l0, l1);
    *(__nv_bfloat162*)(al + base + 2) = __nv_bfloat162(l2, l3);
}

// ==================== wmma ctx = attn @ v ====================
// Tile 128 i x 64 d, K=1024 in 64-chunks, 3-term split.
#define CAH 0
#define CAL 18432
#define CVH 36864
#define CVL 46080
#define CSMEM 55296

__global__ __launch_bounds__(256)
void ctx_wmma_kernel(const __nv_bfloat16* __restrict__ ah, const __nv_bfloat16* __restrict__ al,
                     const __nv_bfloat16* __restrict__ vh, const __nv_bfloat16* __restrict__ vl,
                     float* __restrict__ ctx) {
    extern __shared__ __align__(128) char smem[];
    int bh = blockIdx.y;
    int b = bh >> 4, hh = bh & 15;
    int i0 = blockIdx.x * 128;
    int tid = threadIdx.x, wid = tid >> 5;
    int m0 = (wid >> 1) * 32, n0 = (wid & 1) * 32;

    wmma::fragment<wmma::accumulator, 16, 16, 16, float> acc[2][2];
    #pragma unroll
    for (int mf = 0; mf < 2; ++mf)
        #pragma unroll
        for (int nf = 0; nf < 2; ++nf)
            wmma::fill_fragment(acc[mf][nf], 0.0f);

    for (int ch = 0; ch < 16; ++ch) {
        int kk0 = ch * 64;
        #pragma unroll
        for (int i = 0; i < 12; ++i) {
            int v = tid + (i << 8);
            if (v < 2048) {
                int split = v >> 10, rem = v & 1023, r = rem >> 3, c = rem & 7;
                const __nv_bfloat16* src = (split ? al : ah);
                uint4 d = *(const uint4*)(src + (size_t)(bh * Ss + i0 + r) * Ss + kk0 + c * 8);
                *(uint4*)(smem + split * 18432 + r * ATSB + c * 16) = d;
            } else {
                int vv2 = v - 2048;
                int split = vv2 >> 9, rem = vv2 & 511, r = rem >> 3, c = rem & 7;
                const __nv_bfloat16* src = (split ? vl : vh);
                uint4 d = *(const uint4*)(src + (size_t)(b * Ss + kk0 + r) * Dd + hh * 64 + c * 8);
                *(uint4*)(smem + CVH + split * 9216 + r * ATSB + c * 16) = d;
            }
        }
        __syncthreads();
        #pragma unroll
        for (int sp = 0; sp < 3; ++sp) {
            const __nv_bfloat16* At = (const __nv_bfloat16*)(smem + ((sp == 1) ? CAL : CAH));
            const __nv_bfloat16* Bt = (const __nv_bfloat16*)(smem + ((sp == 2) ? CVL : CVH));
            #pragma unroll
            for (int ks = 0; ks < 4; ++ks) {
                wmma::fragment<wmma::matrix_a, 16, 16, 16, __nv_bfloat16, wmma::row_major> af[2];
                wmma::fragment<wmma::matrix_b, 16, 16, 16, __nv_bfloat16, wmma::row_major> bfr[2];
                #pragma unroll
                for (int mf = 0; mf < 2; ++mf)
                    wmma::load_matrix_sync(af[mf], At + (m0 + mf * 16) * ATSE + ks * 16, ATSE);
                #pragma unroll
                for (int nf = 0; nf < 2; ++nf)
                    wmma::load_matrix_sync(bfr[nf], Bt + (ks * 16) * ATSE + n0 + nf * 16, ATSE);
                #pragma unroll
                for (int mf = 0; mf < 2; ++mf)
                    #pragma unroll
                    for (int nf = 0; nf < 2; ++nf)
                        wmma::mma_sync(acc[mf][nf], af[mf], bfr[nf], acc[mf][nf]);
            }
        }
        __syncthreads();
    }
    // n covers 64 = DH; warp n0 in {0,32}, nf*16
    #pragma unroll
    for (int mf = 0; mf < 2; ++mf)
        #pragma unroll
        for (int nf = 0; nf < 2; ++nf)
            wmma::store_matrix_sync(
                ctx + (size_t)(b * Ss + i0 + m0 + mf * 16) * Dd + hh * 64 + n0 + nf * 16,
                acc[mf][nf], Dd, wmma::mem_row_major);
}

// ==================== launch ====================
extern "C" void kernel_launch(void* const* d_in, const int* in_sizes, int n_in,
                              void* d_out, int out_size) {
    const int*   x    = (const int*)d_in[0];
    const int*   vlen = (const int*)d_in[1];
    const float* emb  = (const float*)d_in[2];
    const float* pos  = (const float*)d_in[3];
    const float* Wq = (const float*)d_in[4]  + (size_t)LAYER * Dd * Dd;
    const float* bq = (const float*)d_in[5]  + LAYER * Dd;
    const float* Wk = (const float*)d_in[6]  + (size_t)LAYER * Dd * Dd;
    const float* bk = (const float*)d_in[7]  + LAYER * Dd;
    const float* Wv = (const float*)d_in[8]  + (size_t)LAYER * Dd * Dd;
    const float* bv = (const float*)d_in[9]  + LAYER * Dd;
    const float* Wo = (const float*)d_in[10] + (size_t)LAYER * Dd * Dd;
    const float* bo = (const float*)d_in[11] + LAYER * Dd;
    const float* W1 = (const float*)d_in[12] + (size_t)LAYER * Dd * FFf;
    const float* b1 = (const float*)d_in[13] + LAYER * FFf;
    const float* W2 = (const float*)d_in[14] + (size_t)LAYER * FFf * Dd;
    const float* b2 = (const float*)d_in[15] + LAYER * Dd;
    const float* g1    = (const float*)d_in[16] + LAYER * Dd;
    const float* beta1 = (const float*)d_in[17] + LAYER * Dd;
    const float* g2    = (const float*)d_in[18] + LAYER * Dd;
    const float* beta2 = (const float*)d_in[19] + LAYER * Dd;
    float* out = (float*)d_out;

    float *h, *x1, *q, *k, *v, *sc, *ctx, *mid, *x2, *ffn;
    __nv_bfloat16 *Ah, *Al, *Bh, *Bl, *qh, *ql, *kh, *kl, *vh, *vl, *ah, *al;
    cudaGetSymbolAddress((void**)&h,   g_h);
    cudaGetSymbolAddress((void**)&x1,  g_x1);
    cudaGetSymbolAddress((void**)&q,   g_q);
    cudaGetSymbolAddress((void**)&k,   g_k);
    cudaGetSymbolAddress((void**)&v,   g_v);
    cudaGetSymbolAddress((void**)&sc,  g_sc);
    cudaGetSymbolAddress((void**)&ctx, g_ctx);
    cudaGetSymbolAddress((void**)&mid, g_mid);
    cudaGetSymbolAddress((void**)&x2,  g_x2);
    cudaGetSymbolAddress((void**)&ffn, g_ffn);
    cudaGetSymbolAddress((void**)&Ah,  g_Ah);
    cudaGetSymbolAddress((void**)&Al,  g_Al);
    cudaGetSymbolAddress((void**)&Bh,  g_Bh);
    cudaGetSymbolAddress((void**)&Bl,  g_Bl);
    cudaGetSymbolAddress((void**)&qh,  g_qh);
    cudaGetSymbolAddress((void**)&ql,  g_ql);
    cudaGetSymbolAddress((void**)&kh,  g_kh);
    cudaGetSymbolAddress((void**)&kl,  g_kl);
    cudaGetSymbolAddress((void**)&vh,  g_vh);
    cudaGetSymbolAddress((void**)&vl,  g_vl);
    cudaGetSymbolAddress((void**)&ah,  g_ah);
    cudaGetSymbolAddress((void**)&al,  g_al);

    cudaFuncSetAttribute(bgemm_kernel<0>, cudaFuncAttributeMaxDynamicSharedMemorySize, SMEM_B);
    cudaFuncSetAttribute(bgemm_kernel<1>, cudaFuncAttributeMaxDynamicSharedMemorySize, SMEM_B);
    cudaFuncSetAttribute(bgemm_kernel<2>, cudaFuncAttributeMaxDynamicSharedMemorySize, SMEM_B);
    cudaFuncSetAttribute(scores_wmma_kernel, cudaFuncAttributeMaxDynamicSharedMemorySize, SSMEM);
    cudaFuncSetAttribute(ctx_wmma_kernel, cudaFuncAttributeMaxDynamicSharedMemorySize, CSMEM);

    detect_kernel<<<1, 256>>>(x);
    embed_kernel<<<(MROWS * (Dd/4)) / 256, 256>>>(x, emb, pos, h);
    ln_kernel<<<MROWS, 256>>>(h, g1, beta1, x1);

    dim3 blkT(32, 8);
    dim3 gdd(Dd / 128, MROWS / 128);           // (8, 64)

    convsplit_kernel<<<(MROWS * Dd / 4) / 256, 256>>>(x1, Ah, Al, MROWS * Dd / 4);
    convtrans_kernel<<<dim3(Dd/32, Dd/32), blkT>>>(Wq, Bh, Bl, Dd, Dd);
    bgemm_kernel<0><<<gdd, 256, SMEM_B>>>(Ah, Al, Bh, Bl, bq, nullptr, q, Dd, Dd);
    convtrans_kernel<<<dim3(Dd/32, Dd/32), blkT>>>(Wk, Bh, Bl, Dd, Dd);
    bgemm_kernel<0><<<gdd, 256, SMEM_B>>>(Ah, Al, Bh, Bl, bk, nullptr, k, Dd, Dd);
    convtrans_kernel<<<dim3(Dd/32, Dd/32), blkT>>>(Wv, Bh, Bl, Dd, Dd);
    bgemm_kernel<0><<<gdd, 256, SMEM_B>>>(Ah, Al, Bh, Bl, bv, nullptr, v, Dd, Dd);

    convsplit_kernel<<<(MROWS * Dd / 4) / 256, 256>>>(q, qh, ql, MROWS * Dd / 4);
    convsplit_kernel<<<(MROWS * Dd / 4) / 256, 256>>>(k, kh, kl, MROWS * Dd / 4);
    convsplit_kernel<<<(MROWS * Dd / 4) / 256, 256>>>(v, vh, vl, MROWS * Dd / 4);

    dim3 gs(Ss / 128, Ss / 128, Bb * Hh);      // (8, 8, 128)
    scores_wmma_kernel<<<gs, 256, SSMEM>>>(qh, ql, kh, kl, sc);
    softmax_kernel<<<Bb * Hh * Ss, 256>>>(sc, vlen, ah, al);
    dim3 gc(Ss / 128, Bb * Hh);                // (8, 128)
    ctx_wmma_kernel<<<gc, 256, CSMEM>>>(ah, al, vh, vl, ctx);

    convsplit_kernel<<<(MROWS * Dd / 4) / 256, 256>>>(ctx, Ah, Al, MROWS * Dd / 4);
    convtrans_kernel<<<dim3(Dd/32, Dd/32), blkT>>>(Wo, Bh, Bl, Dd, Dd);
    bgemm_kernel<1><<<gdd, 256, SMEM_B>>>(Ah, Al, Bh, Bl, bo, h, mid, Dd, Dd);

    ln_kernel<<<MROWS, 256>>>(mid, g2, beta2, x2);

    convsplit_kernel<<<(MROWS * Dd / 4) / 256, 256>>>(x2, Ah, Al, MROWS * Dd / 4);
    convtrans_kernel<<<dim3(FFf/32, Dd/32), blkT>>>(W1, Bh, Bl, Dd, FFf);
    dim3 gff(FFf / 128, MROWS / 128);          // (32, 64)
    bgemm_kernel<2><<<gff, 256, SMEM_B>>>(Ah, Al, Bh, Bl, b1, nullptr, ffn, FFf, Dd);

    convsplit_kernel<<<(MROWS * FFf / 4) / 256, 256>>>(ffn, Ah, Al, MROWS * FFf / 4);
    convtrans_kernel<<<dim3(Dd/32, FFf/32), blkT>>>(W2, Bh, Bl, FFf, Dd);
    bgemm_kernel<1><<<gdd, 256, SMEM_B>>>(Ah, Al, Bh, Bl, b2, mid, out, Dd, FFf);
}

// round 8
// speedup vs baseline: 2.1736x; 1.1845x over previous
#include <cuda_runtime.h>
#include <cuda_bf16.h>
#include <cuda_pipeline.h>
#include <mma.h>
#include <math.h>
#include <stdint.h>

using namespace nvcuda;

#define Bb 8
#define Ss 1024
#define Dd 1024
#define Hh 16
#define DHh 64
#define FFf 4096
#define LAYER 3
#define MROWS (Bb*Ss)   /* 8192 */

// ---------------- scratch (device globals; allocation-free rule) ----------------
__device__ float g_h  [MROWS*Dd];
__device__ float g_x1 [MROWS*Dd];
__device__ float g_sc [(size_t)Bb*Hh*Ss*Ss];   // 512 MB scores
__device__ float g_ctx[MROWS*Dd];
__device__ float g_mid[MROWS*Dd];
__device__ float g_x2 [MROWS*Dd];
__device__ __nv_bfloat16 g_f [(size_t)2*MROWS*FFf];  // ffn split hi|lo
__device__ __nv_bfloat16 g_Ah[(size_t)MROWS*FFf];
__device__ __nv_bfloat16 g_Al[(size_t)MROWS*FFf];
__device__ __nv_bfloat16 g_Bh[(size_t)FFf*Dd];
__device__ __nv_bfloat16 g_Bl[(size_t)FFf*Dd];
__device__ __nv_bfloat16 g_qh[MROWS*Dd];
__device__ __nv_bfloat16 g_ql[MROWS*Dd];
__device__ __nv_bfloat16 g_kh[MROWS*Dd];
__device__ __nv_bfloat16 g_kl[MROWS*Dd];
__device__ __nv_bfloat16 g_vh[MROWS*Dd];
__device__ __nv_bfloat16 g_vl[MROWS*Dd];
__device__ __nv_bfloat16 g_ah[(size_t)Bb*Hh*Ss*Ss];
__device__ __nv_bfloat16 g_al[(size_t)Bb*Hh*Ss*Ss];
__device__ int   g_is64;

// ==================== dtype detection ====================
__global__ void detect_kernel(const int* __restrict__ x) {
    __shared__ int any;
    if (threadIdx.x == 0) any = 0;
    __syncthreads();
    int local = 0;
    for (int i = threadIdx.x; i < 4096; i += blockDim.x)
        if (x[2*i + 1] != 0) local = 1;
    if (local) any = 1;
    __syncthreads();
    if (threadIdx.x == 0) g_is64 = (any == 0) ? 1 : 0;
}

// ==================== embed ====================
__global__ void embed_kernel(const int* __restrict__ x, const float* __restrict__ emb,
                             const float* __restrict__ pos, float* __restrict__ h) {
    int i = blockIdx.x * blockDim.x + threadIdx.x;
    if (i >= MROWS * (Dd/4)) return;
    int row = i >> 8;
    int dc  = i & 255;
    int s   = row & (Ss - 1);
    long long tok = g_is64 ? ((const long long*)x)[row] : (long long)x[row];
    float4 e = ((const float4*)emb)[(size_t)tok * 256 + dc];
    float4 p = ((const float4*)pos)[(size_t)s   * 256 + dc];
    float4 r;
    r.x = fmaf(e.x, 32.0f, p.x);
    r.y = fmaf(e.y, 32.0f, p.y);
    r.z = fmaf(e.z, 32.0f, p.z);
    r.w = fmaf(e.w, 32.0f, p.w);
    ((float4*)h)[i] = r;
}

// ==================== layernorm ====================
__global__ __launch_bounds__(256)
void ln_kernel(const float* __restrict__ in, const float* __restrict__ gamma,
               const float* __restrict__ beta, float* __restrict__ out) {
    int row = blockIdx.x;
    int tid = threadIdx.x;
    const float4* xr = (const float4*)(in + (size_t)row * Dd);
    float4 v = xr[tid];
    float s1 = v.x + v.y + v.z + v.w;
    float s2 = v.x*v.x + v.y*v.y + v.z*v.z + v.w*v.w;
    #pragma unroll
    for (int o = 16; o; o >>= 1) {
        s1 += __shfl_xor_sync(0xffffffffu, s1, o);
        s2 += __shfl_xor_sync(0xffffffffu, s2, o);
    }
    __shared__ float a1[8], a2[8];
    int lane = tid & 31, wid = tid >> 5;
    if (lane == 0) { a1[wid] = s1; a2[wid] = s2; }
    __syncthreads();
    __shared__ float mS, invS;
    if (tid == 0) {
        float t1 = 0.f, t2 = 0.f;
        #pragma unroll
        for (int w = 0; w < 8; ++w) { t1 += a1[w]; t2 += a2[w]; }
        float mean = t1 * (1.0f / Dd);
        float var  = t2 * (1.0f / Dd) - mean * mean;
        mS = mean; invS = rsqrtf(var + 1e-5f);
    }
    __syncthreads();
    float mean = mS, inv = invS;
    float4 g4 = ((const float4*)gamma)[tid];
    float4 b4 = ((const float4*)beta)[tid];
    float4 o4;
    o4.x = (v.x - mean) * inv * g4.x + b4.x;
    o4.y = (v.y - mean) * inv * g4.y + b4.y;
    o4.z = (v.z - mean) * inv * g4.z + b4.z;
    o4.w = (v.w - mean) * inv * g4.w + b4.w;
    ((float4*)(out + (size_t)row * Dd))[tid] = o4;
}

// ==================== fp32 -> split bf16 ====================
__global__ void convsplit_kernel(const float* __restrict__ in, __nv_bfloat16* __restrict__ hi,
                                 __nv_bfloat16* __restrict__ lo, int n4) {
    int i = blockIdx.x * blockDim.x + threadIdx.x;
    if (i >= n4) return;
    float4 v = ((const float4*)in)[i];
    __nv_bfloat16 h0 = __float2bfloat16(v.x), h1 = __float2bfloat16(v.y);
    __nv_bfloat16 h2 = __float2bfloat16(v.z), h3 = __float2bfloat16(v.w);
    __nv_bfloat16 l0 = __float2bfloat16(v.x - __bfloat162float(h0));
    __nv_bfloat16 l1 = __float2bfloat16(v.y - __bfloat162float(h1));
    __nv_bfloat16 l2 = __float2bfloat16(v.z - __bfloat162float(h2));
    __nv_bfloat16 l3 = __float2bfloat16(v.w - __bfloat162float(h3));
    __nv_bfloat162* H = (__nv_bfloat162*)hi;
    __nv_bfloat162* L = (__nv_bfloat162*)lo;
    H[2*i]   = __nv_bfloat162(h0, h1);
    H[2*i+1] = __nv_bfloat162(h2, h3);
    L[2*i]   = __nv_bfloat162(l0, l1);
    L[2*i+1] = __nv_bfloat162(l2, l3);
}

// ==================== weight fp32 [K,N] -> split bf16 transposed [N,K] ====================
__global__ void convtrans_kernel(const float* __restrict__ W, __nv_bfloat16* __restrict__ TH,
                                 __nv_bfloat16* __restrict__ TL, int K, int N) {
    __shared__ float t[32][33];
    int nb = blockIdx.x * 32, kb = blockIdx.y * 32;
    int tx = threadIdx.x, ty = threadIdx.y;
    for (int r = ty; r < 32; r += 8)
        t[r][tx] = W[(size_t)(kb + r) * N + nb + tx];
    __syncthreads();
    for (int r = ty; r < 32; r += 8) {
        float v = t[tx][r];
        __nv_bfloat16 h = __float2bfloat16(v);
        __nv_bfloat16 l = __float2bfloat16(v - __bfloat162float(h));
        size_t o = (size_t)(nb + r) * K + kb + tx;
        TH[o] = h; TL[o] = l;
    }
}

// ==================== wmma split-bf16 GEMM (cp.async pipelined) ====================
#define WTSE 40
#define WTSB 80
#define TILE_B  (128*WTSB)
#define STAGE_B (4*TILE_B)
#define SMEM_B  (2*STAGE_B)

// EPI: 0:+bias->C  1:+bias+res->C  2:relu(+bias)->C  3:+bias->split  4:relu(+bias)->split
template<int EPI>
__global__ __launch_bounds__(256)
void bgemm_kernel(const __nv_bfloat16* __restrict__ Ah, const __nv_bfloat16* __restrict__ Al,
                  const __nv_bfloat16* __restrict__ Bh, const __nv_bfloat16* __restrict__ Bl,
                  const float* __restrict__ bias, const float* __restrict__ res,
                  float* __restrict__ C, __nv_bfloat16* __restrict__ Oh,
                  __nv_bfloat16* __restrict__ Ol, int N, int K) {
    extern __shared__ __align__(128) char smem[];
    int tid = threadIdx.x, wid = tid >> 5;
    int rowBase = blockIdx.y * 128, colBase = blockIdx.x * 128;
    int m0 = (wid >> 2) * 64, n0 = (wid & 3) * 32;

    const __nv_bfloat16* gsrc[8];
    int soff[8];
    #pragma unroll
    for (int i = 0; i < 8; ++i) {
        int v = tid + (i << 8);
        int tile = v >> 9, rem = v & 511, row = rem >> 2, c = rem & 3;
        const __nv_bfloat16* base =
            (tile == 0) ? Ah : (tile == 1) ? Al : (tile == 2) ? Bh : Bl;
        int grow = (tile < 2) ? (rowBase + row) : (colBase + row);
        gsrc[i] = base + (size_t)grow * K + c * 8;
        soff[i] = tile * TILE_B + row * WTSB + c * 16;
    }

    wmma::fragment<wmma::accumulator, 16, 16, 16, float> acc[4][2];
    #pragma unroll
    for (int mf = 0; mf < 4; ++mf)
        #pragma unroll
        for (int nf = 0; nf < 2; ++nf)
            wmma::fill_fragment(acc[mf][nf], 0.0f);

    const int nch = K >> 5;
    // prologue: stages 0 and 1
    #pragma unroll
    for (int i = 0; i < 8; ++i)
        __pipeline_memcpy_async(smem + soff[i], gsrc[i], 16);
    __pipeline_commit();
    #pragma unroll
    for (int i = 0; i < 8; ++i)
        __pipeline_memcpy_async(smem + STAGE_B + soff[i], gsrc[i] + 32, 16);
    __pipeline_commit();

    for (int ch = 0; ch < nch; ++ch) {
        if (ch + 2 <= nch) __pipeline_wait_prior(1);
        else               __pipeline_wait_prior(0);
        __syncthreads();
        char* stage = smem + (ch & 1) * STAGE_B;
        const __nv_bfloat16* At_h = (const __nv_bfloat16*)(stage);
        const __nv_bfloat16* At_l = (const __nv_bfloat16*)(stage + TILE_B);
        const __nv_bfloat16* Bt_h = (const __nv_bfloat16*)(stage + 2 * TILE_B);
        const __nv_bfloat16* Bt_l = (const __nv_bfloat16*)(stage + 3 * TILE_B);
        #pragma unroll
        for (int ks = 0; ks < 2; ++ks) {
            wmma::fragment<wmma::matrix_a, 16, 16, 16, __nv_bfloat16, wmma::row_major> ah[4], al[4];
            wmma::fragment<wmma::matrix_b, 16, 16, 16, __nv_bfloat16, wmma::col_major> bh[2], bl[2];
            #pragma unroll
            for (int mf = 0; mf < 4; ++mf) {
                wmma::load_matrix_sync(ah[mf], At_h + (m0 + mf * 16) * WTSE + ks * 16, WTSE);
                wmma::load_matrix_sync(al[mf], At_l + (m0 + mf * 16) * WTSE + ks * 16, WTSE);
            }
            #pragma unroll
            for (int nf = 0; nf < 2; ++nf) {
                wmma::load_matrix_sync(bh[nf], Bt_h + (n0 + nf * 16) * WTSE + ks * 16, WTSE);
                wmma::load_matrix_sync(bl[nf], Bt_l + (n0 + nf * 16) * WTSE + ks * 16, WTSE);
            }
            #pragma unroll
            for (int mf = 0; mf < 4; ++mf)
                #pragma unroll
                for (int nf = 0; nf < 2; ++nf) {
                    wmma::mma_sync(acc[mf][nf], ah[mf], bh[nf], acc[mf][nf]);
                    wmma::mma_sync(acc[mf][nf], ah[mf], bl[nf], acc[mf][nf]);
                    wmma::mma_sync(acc[mf][nf], al[mf], bh[nf], acc[mf][nf]);
                }
        }
        __syncthreads();
        if (ch + 2 < nch) {
            #pragma unroll
            for (int i = 0; i < 8; ++i)
                __pipeline_memcpy_async(smem + (ch & 1) * STAGE_B + soff[i],
                                        gsrc[i] + (size_t)(ch + 2) * 32, 16);
            __pipeline_commit();
        }
    }

    // ---- epilogue: fragments -> smem (stride 132) -> global ----
    float* sf = (float*)smem;
    #pragma unroll
    for (int mf = 0; mf < 4; ++mf)
        #pragma unroll
        for (int nf = 0; nf < 2; ++nf)
            wmma::store_matrix_sync(sf + (m0 + mf * 16) * 132 + n0 + nf * 16,
                                    acc[mf][nf], 132, wmma::mem_row_major);
    __syncthreads();
    #pragma unroll
    for (int i = 0; i < 16; ++i) {
        int v = tid + (i << 8);
        int r = v >> 5, c4 = (v & 31) * 4;
        float4 val = *(float4*)(sf + r * 132 + c4);
        int col = colBase + c4;
        float4 bv = *(const float4*)(bias + col);
        val.x += bv.x; val.y += bv.y; val.z += bv.z; val.w += bv.w;
        size_t o = (size_t)(rowBase + r) * N + col;
        if (EPI == 1) {
            float4 rv = *(const float4*)(res + o);
            val.x += rv.x; val.y += rv.y; val.z += rv.z; val.w += rv.w;
        }
        if (EPI == 2 || EPI == 4) {
            val.x = fmaxf(val.x, 0.f); val.y = fmaxf(val.y, 0.f);
            val.z = fmaxf(val.z, 0.f); val.w = fmaxf(val.w, 0.f);
        }
        if (EPI <= 2) {
            *(float4*)(C + o) = val;
        } else {
            __nv_bfloat16 h0 = __float2bfloat16(val.x), h1 = __float2bfloat16(val.y);
            __nv_bfloat16 h2 = __float2bfloat16(val.z), h3 = __float2bfloat16(val.w);
            __nv_bfloat16 l0 = __float2bfloat16(val.x - __bfloat162float(h0));
            __nv_bfloat16 l1 = __float2bfloat16(val.y - __bfloat162float(h1));
            __nv_bfloat16 l2 = __float2bfloat16(val.z - __bfloat162float(h2));
            __nv_bfloat16 l3 = __float2bfloat16(val.w - __bfloat162float(h3));
            *(__nv_bfloat162*)(Oh + o)     = __nv_bfloat162(h0, h1);
            *(__nv_bfloat162*)(Oh + o + 2) = __nv_bfloat162(h2, h3);
            *(__nv_bfloat162*)(Ol + o)     = __nv_bfloat162(l0, l1);
            *(__nv_bfloat162*)(Ol + o + 2) = __nv_bfloat162(l2, l3);
        }
    }
}

// ==================== wmma attention scores ====================
#define ATSE 72
#define ATSB 144
#define STILE (128*ATSB)
#define SSMEM (4*STILE)

__global__ __launch_bounds__(256)
void scores_wmma_kernel(const __nv_bfloat16* __restrict__ qh, const __nv_bfloat16* __restrict__ ql,
                        const __nv_bfloat16* __restrict__ kh, const __nv_bfloat16* __restrict__ kl,
                        float* __restrict__ sc) {
    extern __shared__ __align__(128) char smem[];
    int bh = blockIdx.z;
    int b = bh >> 4, hh = bh & 15;
    int i0 = blockIdx.y * 128, j0 = blockIdx.x * 128;
    int tid = threadIdx.x, wid = tid >> 5;
    int m0 = (wid >> 2) * 64, n0 = (wid & 3) * 32;

    #pragma unroll
    for (int i = 0; i < 16; ++i) {
        int v = tid + (i << 8);
        int m = v >> 10, rem = v & 1023, r = rem >> 3, c = rem & 7;
        const __nv_bfloat16* mat = (m == 0) ? qh : (m == 1) ? ql : (m == 2) ? kh : kl;
        int rowg = ((m < 2) ? i0 : j0) + r;
        uint4 d = *(const uint4*)(mat + (size_t)(b * Ss + rowg) * Dd + hh * 64 + c * 8);
        *(uint4*)(smem + m * STILE + r * ATSB + c * 16) = d;
    }
    __syncthreads();

    wmma::fragment<wmma::accumulator, 16, 16, 16, float> acc[4][2];
    #pragma unroll
    for (int mf = 0; mf < 4; ++mf)
        #pragma unroll
        for (int nf = 0; nf < 2; ++nf)
            wmma::fill_fragment(acc[mf][nf], 0.0f);

    const __nv_bfloat16* Qh = (const __nv_bfloat16*)(smem);
    const __nv_bfloat16* Ql = (const __nv_bfloat16*)(smem + STILE);
    const __nv_bfloat16* Kh = (const __nv_bfloat16*)(smem + 2 * STILE);
    const __nv_bfloat16* Kl = (const __nv_bfloat16*)(smem + 3 * STILE);
    #pragma unroll
    for (int ks = 0; ks < 4; ++ks) {
        wmma::fragment<wmma::matrix_a, 16, 16, 16, __nv_bfloat16, wmma::row_major> ah[4], al[4];
        wmma::fragment<wmma::matrix_b, 16, 16, 16, __nv_bfloat16, wmma::col_major> bh2[2], bl2[2];
        #pragma unroll
        for (int mf = 0; mf < 4; ++mf) {
            wmma::load_matrix_sync(ah[mf], Qh + (m0 + mf * 16) * ATSE + ks * 16, ATSE);
            wmma::load_matrix_sync(al[mf], Ql + (m0 + mf * 16) * ATSE + ks * 16, ATSE);
        }
        #pragma unroll
        for (int nf = 0; nf < 2; ++nf) {
            wmma::load_matrix_sync(bh2[nf], Kh + (n0 + nf * 16) * ATSE + ks * 16, ATSE);
            wmma::load_matrix_sync(bl2[nf], Kl + (n0 + nf * 16) * ATSE + ks * 16, ATSE);
        }
        #pragma unroll
        for (int mf = 0; mf < 4; ++mf)
            #pragma unroll
            for (int nf = 0; nf < 2; ++nf) {
                wmma::mma_sync(acc[mf][nf], ah[mf], bh2[nf], acc[mf][nf]);
                wmma::mma_sync(acc[mf][nf], ah[mf], bl2[nf], acc[mf][nf]);
                wmma::mma_sync(acc[mf][nf], al[mf], bh2[nf], acc[mf][nf]);
            }
    }
    #pragma unroll
    for (int mf = 0; mf < 4; ++mf)
        #pragma unroll
        for (int nf = 0; nf < 2; ++nf) {
            #pragma unroll
            for (int t = 0; t < acc[mf][nf].num_elements; ++t)
                acc[mf][nf].x[t] *= 0.125f;
            wmma::store_matrix_sync(
                sc + ((size_t)bh * Ss + i0 + m0 + mf * 16) * Ss + j0 + n0 + nf * 16,
                acc[mf][nf], Ss, wmma::mem_row_major);
        }
}

// ==================== softmax (mask + split-bf16 output) ====================
__global__ __launch_bounds__(256)
void softmax_kernel(const float* __restrict__ sc, const int* __restrict__ vlen,
                    __nv_bfloat16* __restrict__ ah, __nv_bfloat16* __restrict__ al) {
    int row = blockIdx.x;
    int b = row >> 14;
    int vl = g_is64 ? (int)((const long long*)vlen)[b] : vlen[b];
    const float* sr = sc + (size_t)row * Ss;
    int tid = threadIdx.x;
    int j0 = tid * 4;
    float4 vv = *(const float4*)(sr + j0);
    float vals[4] = {vv.x, vv.y, vv.z, vv.w};
    #pragma unroll
    for (int c = 0; c < 4; c++) if (j0 + c >= vl) vals[c] = -1e9f;
    float m = fmaxf(fmaxf(vals[0], vals[1]), fmaxf(vals[2], vals[3]));
    #pragma unroll
    for (int o = 16; o; o >>= 1) m = fmaxf(m, __shfl_xor_sync(0xffffffffu, m, o));
    __shared__ float r1[8];
    int lane = tid & 31, wid = tid >> 5;
    if (lane == 0) r1[wid] = m;
    __syncthreads();
    __shared__ float Ms;
    if (tid == 0) {
        float t = r1[0];
        #pragma unroll
        for (int w = 1; w < 8; w++) t = fmaxf(t, r1[w]);
        Ms = t;
    }
    __syncthreads();
    float M = Ms;
    float e[4];
    float s = 0.f;
    #pragma unroll
    for (int c = 0; c < 4; c++) { e[c] = expf(vals[c] - M); s += e[c]; }
    #pragma unroll
    for (int o = 16; o; o >>= 1) s += __shfl_xor_sync(0xffffffffu, s, o);
    __shared__ float r2[8];
    if (lane == 0) r2[wid] = s;
    __syncthreads();
    __shared__ float Ssum;
    if (tid == 0) {
        float t = 0.f;
        #pragma unroll
        for (int w = 0; w < 8; w++) t += r2[w];
        Ssum = t;
    }
    __syncthreads();
    float inv = 1.0f / Ssum;
    float o0 = e[0] * inv, o1 = e[1] * inv, o2 = e[2] * inv, o3 = e[3] * inv;
    __nv_bfloat16 h0 = __float2bfloat16(o0), h1 = __float2bfloat16(o1);
    __nv_bfloat16 h2 = __float2bfloat16(o2), h3 = __float2bfloat16(o3);
    __nv_bfloat16 l0 = __float2bfloat16(o0 - __bfloat162float(h0));
    __nv_bfloat16 l1 = __float2bfloat16(o1 - __bfloat162float(h1));
    __nv_bfloat16 l2 = __float2bfloat16(o2 - __bfloat162float(h2));
    __nv_bfloat16 l3 = __float2bfloat16(o3 - __bfloat162float(h3));
    size_t base = (size_t)row * Ss + j0;
    *(__nv_bfloat162*)(ah + base)     = __nv_bfloat162(h0, h1);
    *(__nv_bfloat162*)(ah + base + 2) = __nv_bfloat162(h2, h3);
    *(__nv_bfloat162*)(al + base)     = __nv_bfloat162(l0, l1);
    *(__nv_bfloat162*)(al + base + 2) = __nv_bfloat162(l2, l3);
}

// ==================== wmma ctx = attn @ v ====================
#define CAH 0
#define CAL 18432
#define CVH 36864
#define CVL 46080
#define CSMEM 55296

__global__ __launch_bounds__(256)
void ctx_wmma_kernel(const __nv_bfloat16* __restrict__ ah, const __nv_bfloat16* __restrict__ al,
                     const __nv_bfloat16* __restrict__ vh, const __nv_bfloat16* __restrict__ vl,
                     float* __restrict__ ctx) {
    extern __shared__ __align__(128) char smem[];
    int bh = blockIdx.y;
    int b = bh >> 4, hh = bh & 15;
    int i0 = blockIdx.x * 128;
    int tid = threadIdx.x, wid = tid >> 5;
    int m0 = (wid >> 1) * 32, n0 = (wid & 1) * 32;

    wmma::fragment<wmma::accumulator, 16, 16, 16, float> acc[2][2];
    #pragma unroll
    for (int mf = 0; mf < 2; ++mf)
        #pragma unroll
        for (int nf = 0; nf < 2; ++nf)
            wmma::fill_fragment(acc[mf][nf], 0.0f);

    for (int ch = 0; ch < 16; ++ch) {
        int kk0 = ch * 64;
        #pragma unroll
        for (int i = 0; i < 12; ++i) {
            int v = tid + (i << 8);
            if (v < 2048) {
                int split = v >> 10, rem = v & 1023, r = rem >> 3, c = rem & 7;
                const __nv_bfloat16* src = (split ? al : ah);
                uint4 d = *(const uint4*)(src + (size_t)(bh * Ss + i0 + r) * Ss + kk0 + c * 8);
                *(uint4*)(smem + split * 18432 + r * ATSB + c * 16) = d;
            } else {
                int vv2 = v - 2048;
                int split = vv2 >> 9, rem = vv2 & 511, r = rem >> 3, c = rem & 7;
                const __nv_bfloat16* src = (split ? vl : vh);
                uint4 d = *(const uint4*)(src + (size_t)(b * Ss + kk0 + r) * Dd + hh * 64 + c * 8);
                *(uint4*)(smem + CVH + split * 9216 + r * ATSB + c * 16) = d;
            }
        }
        __syncthreads();
        const __nv_bfloat16* Ath = (const __nv_bfloat16*)(smem + CAH);
        const __nv_bfloat16* Atl = (const __nv_bfloat16*)(smem + CAL);
        const __nv_bfloat16* Vth = (const __nv_bfloat16*)(smem + CVH);
        const __nv_bfloat16* Vtl = (const __nv_bfloat16*)(smem + CVL);
        #pragma unroll
        for (int ks = 0; ks < 4; ++ks) {
            wmma::fragment<wmma::matrix_a, 16, 16, 16, __nv_bfloat16, wmma::row_major> fah[2], fal[2];
            wmma::fragment<wmma::matrix_b, 16, 16, 16, __nv_bfloat16, wmma::row_major> fvh[2], fvl[2];
            #pragma unroll
            for (int mf = 0; mf < 2; ++mf) {
                wmma::load_matrix_sync(fah[mf], Ath + (m0 + mf * 16) * ATSE + ks * 16, ATSE);
                wmma::load_matrix_sync(fal[mf], Atl + (m0 + mf * 16) * ATSE + ks * 16, ATSE);
            }
            #pragma unroll
            for (int nf = 0; nf < 2; ++nf) {
                wmma::load_matrix_sync(fvh[nf], Vth + (ks * 16) * ATSE + n0 + nf * 16, ATSE);
                wmma::load_matrix_sync(fvl[nf], Vtl + (ks * 16) * ATSE + n0 + nf * 16, ATSE);
            }
            #pragma unroll
            for (int mf = 0; mf < 2; ++mf)
                #pragma unroll
                for (int nf = 0; nf < 2; ++nf) {
                    wmma::mma_sync(acc[mf][nf], fah[mf], fvh[nf], acc[mf][nf]);
                    wmma::mma_sync(acc[mf][nf], fah[mf], fvl[nf], acc[mf][nf]);
                    wmma::mma_sync(acc[mf][nf], fal[mf], fvh[nf], acc[mf][nf]);
                }
        }
        __syncthreads();
    }
    #pragma unroll
    for (int mf = 0; mf < 2; ++mf)
        #pragma unroll
        for (int nf = 0; nf < 2; ++nf)
            wmma::store_matrix_sync(
                ctx + (size_t)(b * Ss + i0 + m0 + mf * 16) * Dd + hh * 64 + n0 + nf * 16,
                acc[mf][nf], Dd, wmma::mem_row_major);
}

// ==================== launch ====================
extern "C" void kernel_launch(void* const* d_in, const int* in_sizes, int n_in,
                              void* d_out, int out_size) {
    const int*   x    = (const int*)d_in[0];
    const int*   vlen = (const int*)d_in[1];
    const float* emb  = (const float*)d_in[2];
    const float* pos  = (const float*)d_in[3];
    const float* Wq = (const float*)d_in[4]  + (size_t)LAYER * Dd * Dd;
    const float* bq = (const float*)d_in[5]  + LAYER * Dd;
    const float* Wk = (const float*)d_in[6]  + (size_t)LAYER * Dd * Dd;
    const float* bk = (const float*)d_in[7]  + LAYER * Dd;
    const float* Wv = (const float*)d_in[8]  + (size_t)LAYER * Dd * Dd;
    const float* bv = (const float*)d_in[9]  + LAYER * Dd;
    const float* Wo = (const float*)d_in[10] + (size_t)LAYER * Dd * Dd;
    const float* bo = (const float*)d_in[11] + LAYER * Dd;
    const float* W1 = (const float*)d_in[12] + (size_t)LAYER * Dd * FFf;
    const float* b1 = (const float*)d_in[13] + LAYER * FFf;
    const float* W2 = (const float*)d_in[14] + (size_t)LAYER * FFf * Dd;
    const float* b2 = (const float*)d_in[15] + LAYER * Dd;
    const float* g1    = (const float*)d_in[16] + LAYER * Dd;
    const float* beta1 = (const float*)d_in[17] + LAYER * Dd;
    const float* g2    = (const float*)d_in[18] + LAYER * Dd;
    const float* beta2 = (const float*)d_in[19] + LAYER * Dd;
    float* out = (float*)d_out;

    float *h, *x1, *sc, *ctx, *mid, *x2;
    __nv_bfloat16 *f, *Ah, *Al, *Bh, *Bl, *qh, *ql, *kh, *kl, *vh, *vl, *ah, *al;
    cudaGetSymbolAddress((void**)&h,   g_h);
    cudaGetSymbolAddress((void**)&x1,  g_x1);
    cudaGetSymbolAddress((void**)&sc,  g_sc);
    cudaGetSymbolAddress((void**)&ctx, g_ctx);
    cudaGetSymbolAddress((void**)&mid, g_mid);
    cudaGetSymbolAddress((void**)&x2,  g_x2);
    cudaGetSymbolAddress((void**)&f,   g_f);
    cudaGetSymbolAddress((void**)&Ah,  g_Ah);
    cudaGetSymbolAddress((void**)&Al,  g_Al);
    cudaGetSymbolAddress((void**)&Bh,  g_Bh);
    cudaGetSymbolAddress((void**)&Bl,  g_Bl);
    cudaGetSymbolAddress((void**)&qh,  g_qh);
    cudaGetSymbolAddress((void**)&ql,  g_ql);
    cudaGetSymbolAddress((void**)&kh,  g_kh);
    cudaGetSymbolAddress((void**)&kl,  g_kl);
    cudaGetSymbolAddress((void**)&vh,  g_vh);
    cudaGetSymbolAddress((void**)&vl,  g_vl);
    cudaGetSymbolAddress((void**)&ah,  g_ah);
    cudaGetSymbolAddress((void**)&al,  g_al);
    __nv_bfloat16* fh = f;
    __nv_bfloat16* fl = f + (size_t)MROWS * FFf;

    cudaFuncSetAttribute(bgemm_kernel<1>, cudaFuncAttributeMaxDynamicSharedMemorySize, SMEM_B);
    cudaFuncSetAttribute(bgemm_kernel<3>, cudaFuncAttributeMaxDynamicSharedMemorySize, SMEM_B);
    cudaFuncSetAttribute(bgemm_kernel<4>, cudaFuncAttributeMaxDynamicSharedMemorySize, SMEM_B);
    cudaFuncSetAttribute(scores_wmma_kernel, cudaFuncAttributeMaxDynamicSharedMemorySize, SSMEM);
    cudaFuncSetAttribute(ctx_wmma_kernel, cudaFuncAttributeMaxDynamicSharedMemorySize, CSMEM);

    detect_kernel<<<1, 256>>>(x);
    embed_kernel<<<(MROWS * (Dd/4)) / 256, 256>>>(x, emb, pos, h);
    ln_kernel<<<MROWS, 256>>>(h, g1, beta1, x1);

    dim3 blkT(32, 8);
    dim3 gdd(Dd / 128, MROWS / 128);           // (8, 64)

    convsplit_kernel<<<(MROWS * Dd / 4) / 256, 256>>>(x1, Ah, Al, MROWS * Dd / 4);
    convtrans_kernel<<<dim3(Dd/32, Dd/32), blkT>>>(Wq, Bh, Bl, Dd, Dd);
    bgemm_kernel<3><<<gdd, 256, SMEM_B>>>(Ah, Al, Bh, Bl, bq, nullptr, nullptr, qh, ql, Dd, Dd);
    convtrans_kernel<<<dim3(Dd/32, Dd/32), blkT>>>(Wk, Bh, Bl, Dd, Dd);
    bgemm_kernel<3><<<gdd, 256, SMEM_B>>>(Ah, Al, Bh, Bl, bk, nullptr, nullptr, kh, kl, Dd, Dd);
    convtrans_kernel<<<dim3(Dd/32, Dd/32), blkT>>>(Wv, Bh, Bl, Dd, Dd);
    bgemm_kernel<3><<<gdd, 256, SMEM_B>>>(Ah, Al, Bh, Bl, bv, nullptr, nullptr, vh, vl, Dd, Dd);

    dim3 gs(Ss / 128, Ss / 128, Bb * Hh);      // (8, 8, 128)
    scores_wmma_kernel<<<gs, 256, SSMEM>>>(qh, ql, kh, kl, sc);
    softmax_kernel<<<Bb * Hh * Ss, 256>>>(sc, vlen, ah, al);
    dim3 gc(Ss / 128, Bb * Hh);                // (8, 128)
    ctx_wmma_kernel<<<gc, 256, CSMEM>>>(ah, al, vh, vl, ctx);

    convsplit_kernel<<<(MROWS * Dd / 4) / 256, 256>>>(ctx, Ah, Al, MROWS * Dd / 4);
    convtrans_kernel<<<dim3(Dd/32, Dd/32), blkT>>>(Wo, Bh, Bl, Dd, Dd);
    bgemm_kernel<1><<<gdd, 256, SMEM_B>>>(Ah, Al, Bh, Bl, bo, h, mid, nullptr, nullptr, Dd, Dd);

    ln_kernel<<<MROWS, 256>>>(mid, g2, beta2, x2);

    convsplit_kernel<<<(MROWS * Dd / 4) / 256, 256>>>(x2, Ah, Al, MROWS * Dd / 4);
    convtrans_kernel<<<dim3(FFf/32, Dd/32), blkT>>>(W1, Bh, Bl, Dd, FFf);
    dim3 gff(FFf / 128, MROWS / 128);          // (32, 64)
    bgemm_kernel<4><<<gff, 256, SMEM_B>>>(Ah, Al, Bh, Bl, b1, nullptr, nullptr, fh, fl, FFf, Dd);

    convtrans_kernel<<<dim3(Dd/32, FFf/32), blkT>>>(W2, Bh, Bl, FFf, Dd);
    bgemm_kernel<1><<<gdd, 256, SMEM_B>>>(fh, fl, Bh, Bl, b2, mid, out, nullptr, nullptr, Dd, FFf);
}

// round 9
// speedup vs baseline: 2.4123x; 1.1098x over previous
#include <cuda_runtime.h>
#include <cuda_bf16.h>
#include <cuda_pipeline.h>
#include <mma.h>
#include <math.h>
#include <stdint.h>

using namespace nvcuda;

#define Bb 8
#define Ss 1024
#define Dd 1024
#define Hh 16
#define DHh 64
#define FFf 4096
#define LAYER 3
#define MROWS (Bb*Ss)   /* 8192 */

// ---------------- scratch (device globals; allocation-free rule) ----------------
__device__ float g_h  [MROWS*Dd];
__device__ float g_x1 [MROWS*Dd];
__device__ float g_sc [(size_t)Bb*Hh*Ss*Ss];   // 512 MB scores
__device__ float g_ctx[MROWS*Dd];
__device__ float g_mid[MROWS*Dd];
__device__ float g_x2 [MROWS*Dd];
__device__ __nv_bfloat16 g_f [(size_t)2*MROWS*FFf];  // ffn split hi|lo
__device__ __nv_bfloat16 g_Ah[(size_t)MROWS*FFf];
__device__ __nv_bfloat16 g_Al[(size_t)MROWS*FFf];
__device__ __nv_bfloat16 g_Bh[(size_t)FFf*Dd];
__device__ __nv_bfloat16 g_Bl[(size_t)FFf*Dd];
__device__ __nv_bfloat16 g_qh[MROWS*Dd];
__device__ __nv_bfloat16 g_ql[MROWS*Dd];
__device__ __nv_bfloat16 g_kh[MROWS*Dd];
__device__ __nv_bfloat16 g_kl[MROWS*Dd];
__device__ __nv_bfloat16 g_vh[MROWS*Dd];
__device__ __nv_bfloat16 g_vl[MROWS*Dd];
__device__ __nv_bfloat16 g_ah[(size_t)Bb*Hh*Ss*Ss];
__device__ __nv_bfloat16 g_al[(size_t)Bb*Hh*Ss*Ss];
__device__ int   g_is64;

// ==================== dtype detection ====================
__global__ void detect_kernel(const int* __restrict__ x) {
    __shared__ int any;
    if (threadIdx.x == 0) any = 0;
    __syncthreads();
    int local = 0;
    for (int i = threadIdx.x; i < 4096; i += blockDim.x)
        if (x[2*i + 1] != 0) local = 1;
    if (local) any = 1;
    __syncthreads();
    if (threadIdx.x == 0) g_is64 = (any == 0) ? 1 : 0;
}

// ==================== embed ====================
__global__ void embed_kernel(const int* __restrict__ x, const float* __restrict__ emb,
                             const float* __restrict__ pos, float* __restrict__ h) {
    int i = blockIdx.x * blockDim.x + threadIdx.x;
    if (i >= MROWS * (Dd/4)) return;
    int row = i >> 8;
    int dc  = i & 255;
    int s   = row & (Ss - 1);
    long long tok = g_is64 ? ((const long long*)x)[row] : (long long)x[row];
    float4 e = ((const float4*)emb)[(size_t)tok * 256 + dc];
    float4 p = ((const float4*)pos)[(size_t)s   * 256 + dc];
    float4 r;
    r.x = fmaf(e.x, 32.0f, p.x);
    r.y = fmaf(e.y, 32.0f, p.y);
    r.z = fmaf(e.z, 32.0f, p.z);
    r.w = fmaf(e.w, 32.0f, p.w);
    ((float4*)h)[i] = r;
}

// ==================== layernorm ====================
__global__ __launch_bounds__(256)
void ln_kernel(const float* __restrict__ in, const float* __restrict__ gamma,
               const float* __restrict__ beta, float* __restrict__ out) {
    int row = blockIdx.x;
    int tid = threadIdx.x;
    const float4* xr = (const float4*)(in + (size_t)row * Dd);
    float4 v = xr[tid];
    float s1 = v.x + v.y + v.z + v.w;
    float s2 = v.x*v.x + v.y*v.y + v.z*v.z + v.w*v.w;
    #pragma unroll
    for (int o = 16; o; o >>= 1) {
        s1 += __shfl_xor_sync(0xffffffffu, s1, o);
        s2 += __shfl_xor_sync(0xffffffffu, s2, o);
    }
    __shared__ float a1[8], a2[8];
    int lane = tid & 31, wid = tid >> 5;
    if (lane == 0) { a1[wid] = s1; a2[wid] = s2; }
    __syncthreads();
    __shared__ float mS, invS;
    if (tid == 0) {
        float t1 = 0.f, t2 = 0.f;
        #pragma unroll
        for (int w = 0; w < 8; ++w) { t1 += a1[w]; t2 += a2[w]; }
        float mean = t1 * (1.0f / Dd);
        float var  = t2 * (1.0f / Dd) - mean * mean;
        mS = mean; invS = rsqrtf(var + 1e-5f);
    }
    __syncthreads();
    float mean = mS, inv = invS;
    float4 g4 = ((const float4*)gamma)[tid];
    float4 b4 = ((const float4*)beta)[tid];
    float4 o4;
    o4.x = (v.x - mean) * inv * g4.x + b4.x;
    o4.y = (v.y - mean) * inv * g4.y + b4.y;
    o4.z = (v.z - mean) * inv * g4.z + b4.z;
    o4.w = (v.w - mean) * inv * g4.w + b4.w;
    ((float4*)(out + (size_t)row * Dd))[tid] = o4;
}

// ==================== fp32 -> split bf16 ====================
__global__ void convsplit_kernel(const float* __restrict__ in, __nv_bfloat16* __restrict__ hi,
                                 __nv_bfloat16* __restrict__ lo, int n4) {
    int i = blockIdx.x * blockDim.x + threadIdx.x;
    if (i >= n4) return;
    float4 v = ((const float4*)in)[i];
    __nv_bfloat16 h0 = __float2bfloat16(v.x), h1 = __float2bfloat16(v.y);
    __nv_bfloat16 h2 = __float2bfloat16(v.z), h3 = __float2bfloat16(v.w);
    __nv_bfloat16 l0 = __float2bfloat16(v.x - __bfloat162float(h0));
    __nv_bfloat16 l1 = __float2bfloat16(v.y - __bfloat162float(h1));
    __nv_bfloat16 l2 = __float2bfloat16(v.z - __bfloat162float(h2));
    __nv_bfloat16 l3 = __float2bfloat16(v.w - __bfloat162float(h3));
    __nv_bfloat162* H = (__nv_bfloat162*)hi;
    __nv_bfloat162* L = (__nv_bfloat162*)lo;
    H[2*i]   = __nv_bfloat162(h0, h1);
    H[2*i+1] = __nv_bfloat162(h2, h3);
    L[2*i]   = __nv_bfloat162(l0, l1);
    L[2*i+1] = __nv_bfloat162(l2, l3);
}

// ==================== weight fp32 [K,N] -> split bf16 transposed [N,K] ====================
__global__ void convtrans_kernel(const float* __restrict__ W, __nv_bfloat16* __restrict__ TH,
                                 __nv_bfloat16* __restrict__ TL, int K, int N) {
    __shared__ float t[32][33];
    int nb = blockIdx.x * 32, kb = blockIdx.y * 32;
    int tx = threadIdx.x, ty = threadIdx.y;
    for (int r = ty; r < 32; r += 8)
        t[r][tx] = W[(size_t)(kb + r) * N + nb + tx];
    __syncthreads();
    for (int r = ty; r < 32; r += 8) {
        float v = t[tx][r];
        __nv_bfloat16 h = __float2bfloat16(v);
        __nv_bfloat16 l = __float2bfloat16(v - __bfloat162float(h));
        size_t o = (size_t)(nb + r) * K + kb + tx;
        TH[o] = h; TL[o] = l;
    }
}

// ==================== wmma split-bf16 GEMM (128x256 tile, 64x64 warp tile) ====================
#define WTSE 40
#define WTSB 80
#define A_TILE_B (128*WTSB)                 /* 10240 */
#define B_TILE_B (256*WTSB)                 /* 20480 */
#define STAGE_B  (2*A_TILE_B + 2*B_TILE_B)  /* 61440 */
#define SMEM_B   133632                     /* >= max(2*STAGE_B, 128*260*4) */

// EPI: 0:+bias->C  1:+bias+res->C  2:relu(+bias)->C  3:+bias->split  4:relu(+bias)->split
template<int EPI>
__global__ __launch_bounds__(256)
void bgemm_kernel(const __nv_bfloat16* __restrict__ Ah, const __nv_bfloat16* __restrict__ Al,
                  const __nv_bfloat16* __restrict__ Bh, const __nv_bfloat16* __restrict__ Bl,
                  const float* __restrict__ bias, const float* __restrict__ res,
                  float* __restrict__ C, __nv_bfloat16* __restrict__ Oh,
                  __nv_bfloat16* __restrict__ Ol, int N, int K) {
    extern __shared__ __align__(128) char smem[];
    int tid = threadIdx.x, wid = tid >> 5;
    int rowBase = blockIdx.y * 128, colBase = blockIdx.x * 256;
    int m0 = (wid >> 2) * 64, n0 = (wid & 3) * 64;

    // load plan: 12 x 16B chunks per stage per thread (3072 total)
    const __nv_bfloat16* gsrc[12];
    int soff[12];
    #pragma unroll
    for (int i = 0; i < 12; ++i) {
        int v = tid + (i << 8);
        const __nv_bfloat16* base;
        int grow, s;
        if (v < 1024) {            // A tiles: hi [0,512), lo [512,1024)
            int t2 = v >> 9, idx = v & 511, row = idx >> 2, c = idx & 3;
            base = t2 ? Al : Ah;
            grow = rowBase + row;
            s = t2 * A_TILE_B + row * WTSB + c * 16;
            gsrc[i] = base + (size_t)grow * K + c * 8;
        } else {                   // B tiles: hi [0,1024), lo [1024,2048)
            int w = v - 1024;
            int t2 = w >> 10, idx = w & 1023, row = idx >> 2, c = idx & 3;
            base = t2 ? Bl : Bh;
            grow = colBase + row;
            s = 2 * A_TILE_B + t2 * B_TILE_B + row * WTSB + c * 16;
            gsrc[i] = base + (size_t)grow * K + c * 8;
        }
        soff[i] = s;
    }

    wmma::fragment<wmma::accumulator, 16, 16, 16, float> acc[4][4];
    #pragma unroll
    for (int mf = 0; mf < 4; ++mf)
        #pragma unroll
        for (int nf = 0; nf < 4; ++nf)
            wmma::fill_fragment(acc[mf][nf], 0.0f);

    const int nch = K >> 5;
    #pragma unroll
    for (int i = 0; i < 12; ++i)
        __pipeline_memcpy_async(smem + soff[i], gsrc[i], 16);
    __pipeline_commit();
    #pragma unroll
    for (int i = 0; i < 12; ++i)
        __pipeline_memcpy_async(smem + STAGE_B + soff[i], gsrc[i] + 32, 16);
    __pipeline_commit();

    for (int ch = 0; ch < nch; ++ch) {
        if (ch + 2 <= nch) __pipeline_wait_prior(1);
        else               __pipeline_wait_prior(0);
        __syncthreads();
        char* stage = smem + (ch & 1) * STAGE_B;
        const __nv_bfloat16* At_h = (const __nv_bfloat16*)(stage);
        const __nv_bfloat16* At_l = (const __nv_bfloat16*)(stage + A_TILE_B);
        const __nv_bfloat16* Bt_h = (const __nv_bfloat16*)(stage + 2 * A_TILE_B);
        const __nv_bfloat16* Bt_l = (const __nv_bfloat16*)(stage + 2 * A_TILE_B + B_TILE_B);
        #pragma unroll
        for (int ks = 0; ks < 2; ++ks) {
            wmma::fragment<wmma::matrix_b, 16, 16, 16, __nv_bfloat16, wmma::col_major> bh[4], bl[4];
            #pragma unroll
            for (int nf = 0; nf < 4; ++nf) {
                wmma::load_matrix_sync(bh[nf], Bt_h + (n0 + nf * 16) * WTSE + ks * 16, WTSE);
                wmma::load_matrix_sync(bl[nf], Bt_l + (n0 + nf * 16) * WTSE + ks * 16, WTSE);
            }
            #pragma unroll
            for (int mf = 0; mf < 4; ++mf) {
                wmma::fragment<wmma::matrix_a, 16, 16, 16, __nv_bfloat16, wmma::row_major> fa, fl2;
                wmma::load_matrix_sync(fa,  At_h + (m0 + mf * 16) * WTSE + ks * 16, WTSE);
                wmma::load_matrix_sync(fl2, At_l + (m0 + mf * 16) * WTSE + ks * 16, WTSE);
                #pragma unroll
                for (int nf = 0; nf < 4; ++nf)
                    wmma::mma_sync(acc[mf][nf], fa, bh[nf], acc[mf][nf]);
                #pragma unroll
                for (int nf = 0; nf < 4; ++nf)
                    wmma::mma_sync(acc[mf][nf], fa, bl[nf], acc[mf][nf]);
                #pragma unroll
                for (int nf = 0; nf < 4; ++nf)
                    wmma::mma_sync(acc[mf][nf], fl2, bh[nf], acc[mf][nf]);
            }
        }
        __syncthreads();
        if (ch + 2 < nch) {
            #pragma unroll
            for (int i = 0; i < 12; ++i)
                __pipeline_memcpy_async(smem + (ch & 1) * STAGE_B + soff[i],
                                        gsrc[i] + (size_t)(ch + 2) * 32, 16);
            __pipeline_commit();
        }
    }

    // ---- epilogue: fragments -> smem (stride 260) -> global ----
    float* sf = (float*)smem;
    #pragma unroll
    for (int mf = 0; mf < 4; ++mf)
        #pragma unroll
        for (int nf = 0; nf < 4; ++nf)
            wmma::store_matrix_sync(sf + (m0 + mf * 16) * 260 + n0 + nf * 16,
                                    acc[mf][nf], 260, wmma::mem_row_major);
    __syncthreads();
    #pragma unroll
    for (int i = 0; i < 32; ++i) {
        int v = tid + (i << 8);          // 8192 float4s = 128x256
        int r = v >> 6, c4 = (v & 63) * 4;
        float4 val = *(float4*)(sf + r * 260 + c4);
        int col = colBase + c4;
        float4 bv = *(const float4*)(bias + col);
        val.x += bv.x; val.y += bv.y; val.z += bv.z; val.w += bv.w;
        size_t o = (size_t)(rowBase + r) * N + col;
        if (EPI == 1) {
            float4 rv = *(const float4*)(res + o);
            val.x += rv.x; val.y += rv.y; val.z += rv.z; val.w += rv.w;
        }
        if (EPI == 2 || EPI == 4) {
            val.x = fmaxf(val.x, 0.f); val.y = fmaxf(val.y, 0.f);
            val.z = fmaxf(val.z, 0.f); val.w = fmaxf(val.w, 0.f);
        }
        if (EPI <= 2) {
            *(float4*)(C + o) = val;
        } else {
            __nv_bfloat16 h0 = __float2bfloat16(val.x), h1 = __float2bfloat16(val.y);
            __nv_bfloat16 h2 = __float2bfloat16(val.z), h3 = __float2bfloat16(val.w);
            __nv_bfloat16 l0 = __float2bfloat16(val.x - __bfloat162float(h0));
            __nv_bfloat16 l1 = __float2bfloat16(val.y - __bfloat162float(h1));
            __nv_bfloat16 l2 = __float2bfloat16(val.z - __bfloat162float(h2));
            __nv_bfloat16 l3 = __float2bfloat16(val.w - __bfloat162float(h3));
            *(__nv_bfloat162*)(Oh + o)     = __nv_bfloat162(h0, h1);
            *(__nv_bfloat162*)(Oh + o + 2) = __nv_bfloat162(h2, h3);
            *(__nv_bfloat162*)(Ol + o)     = __nv_bfloat162(l0, l1);
            *(__nv_bfloat162*)(Ol + o + 2) = __nv_bfloat162(l2, l3);
        }
    }
}

// ==================== wmma attention scores ====================
#define ATSE 72
#define ATSB 144
#define STILE (128*ATSB)
#define SSMEM (4*STILE)

__global__ __launch_bounds__(256)
void scores_wmma_kernel(const __nv_bfloat16* __restrict__ qh, const __nv_bfloat16* __restrict__ ql,
                        const __nv_bfloat16* __restrict__ kh, const __nv_bfloat16* __restrict__ kl,
                        float* __restrict__ sc) {
    extern __shared__ __align__(128) char smem[];
    int bh = blockIdx.z;
    int b = bh >> 4, hh = bh & 15;
    int i0 = blockIdx.y * 128, j0 = blockIdx.x * 128;
    int tid = threadIdx.x, wid = tid >> 5;
    int m0 = (wid >> 2) * 64, n0 = (wid & 3) * 32;

    #pragma unroll
    for (int i = 0; i < 16; ++i) {
        int v = tid + (i << 8);
        int m = v >> 10, rem = v & 1023, r = rem >> 3, c = rem & 7;
        const __nv_bfloat16* mat = (m == 0) ? qh : (m == 1) ? ql : (m == 2) ? kh : kl;
        int rowg = ((m < 2) ? i0 : j0) + r;
        uint4 d = *(const uint4*)(mat + (size_t)(b * Ss + rowg) * Dd + hh * 64 + c * 8);
        *(uint4*)(smem + m * STILE + r * ATSB + c * 16) = d;
    }
    __syncthreads();

    wmma::fragment<wmma::accumulator, 16, 16, 16, float> acc[4][2];
    #pragma unroll
    for (int mf = 0; mf < 4; ++mf)
        #pragma unroll
        for (int nf = 0; nf < 2; ++nf)
            wmma::fill_fragment(acc[mf][nf], 0.0f);

    const __nv_bfloat16* Qh = (const __nv_bfloat16*)(smem);
    const __nv_bfloat16* Ql = (const __nv_bfloat16*)(smem + STILE);
    const __nv_bfloat16* Kh = (const __nv_bfloat16*)(smem + 2 * STILE);
    const __nv_bfloat16* Kl = (const __nv_bfloat16*)(smem + 3 * STILE);
    #pragma unroll
    for (int ks = 0; ks < 4; ++ks) {
        wmma::fragment<wmma::matrix_a, 16, 16, 16, __nv_bfloat16, wmma::row_major> ah[4], al[4];
        wmma::fragment<wmma::matrix_b, 16, 16, 16, __nv_bfloat16, wmma::col_major> bh2[2], bl2[2];
        #pragma unroll
        for (int mf = 0; mf < 4; ++mf) {
            wmma::load_matrix_sync(ah[mf], Qh + (m0 + mf * 16) * ATSE + ks * 16, ATSE);
            wmma::load_matrix_sync(al[mf], Ql + (m0 + mf * 16) * ATSE + ks * 16, ATSE);
        }
        #pragma unroll
        for (int nf = 0; nf < 2; ++nf) {
            wmma::load_matrix_sync(bh2[nf], Kh + (n0 + nf * 16) * ATSE + ks * 16, ATSE);
            wmma::load_matrix_sync(bl2[nf], Kl + (n0 + nf * 16) * ATSE + ks * 16, ATSE);
        }
        #pragma unroll
        for (int mf = 0; mf < 4; ++mf)
            #pragma unroll
            for (int nf = 0; nf < 2; ++nf) {
                wmma::mma_sync(acc[mf][nf], ah[mf], bh2[nf], acc[mf][nf]);
                wmma::mma_sync(acc[mf][nf], ah[mf], bl2[nf], acc[mf][nf]);
                wmma::mma_sync(acc[mf][nf], al[mf], bh2[nf], acc[mf][nf]);
            }
    }
    #pragma unroll
    for (int mf = 0; mf < 4; ++mf)
        #pragma unroll
        for (int nf = 0; nf < 2; ++nf) {
            #pragma unroll
            for (int t = 0; t < acc[mf][nf].num_elements; ++t)
                acc[mf][nf].x[t] *= 0.125f;
            wmma::store_matrix_sync(
                sc + ((size_t)bh * Ss + i0 + m0 + mf * 16) * Ss + j0 + n0 + nf * 16,
                acc[mf][nf], Ss, wmma::mem_row_major);
        }
}

// ==================== softmax (mask + split-bf16 output) ====================
__global__ __launch_bounds__(256)
void softmax_kernel(const float* __restrict__ sc, const int* __restrict__ vlen,
                    __nv_bfloat16* __restrict__ ah, __nv_bfloat16* __restrict__ al) {
    int row = blockIdx.x;
    int b = row >> 14;
    int vl = g_is64 ? (int)((const long long*)vlen)[b] : vlen[b];
    const float* sr = sc + (size_t)row * Ss;
    int tid = threadIdx.x;
    int j0 = tid * 4;
    float4 vv = *(const float4*)(sr + j0);
    float vals[4] = {vv.x, vv.y, vv.z, vv.w};
    #pragma unroll
    for (int c = 0; c < 4; c++) if (j0 + c >= vl) vals[c] = -1e9f;
    float m = fmaxf(fmaxf(vals[0], vals[1]), fmaxf(vals[2], vals[3]));
    #pragma unroll
    for (int o = 16; o; o >>= 1) m = fmaxf(m, __shfl_xor_sync(0xffffffffu, m, o));
    __shared__ float r1[8];
    int lane = tid & 31, wid = tid >> 5;
    if (lane == 0) r1[wid] = m;
    __syncthreads();
    __shared__ float Ms;
    if (tid == 0) {
        float t = r1[0];
        #pragma unroll
        for (int w = 1; w < 8; w++) t = fmaxf(t, r1[w]);
        Ms = t;
    }
    __syncthreads();
    float M = Ms;
    float e[4];
    float s = 0.f;
    #pragma unroll
    for (int c = 0; c < 4; c++) { e[c] = expf(vals[c] - M); s += e[c]; }
    #pragma unroll
    for (int o = 16; o; o >>= 1) s += __shfl_xor_sync(0xffffffffu, s, o);
    __shared__ float r2[8];
    if (lane == 0) r2[wid] = s;
    __syncthreads();
    __shared__ float Ssum;
    if (tid == 0) {
        float t = 0.f;
        #pragma unroll
        for (int w = 0; w < 8; w++) t += r2[w];
        Ssum = t;
    }
    __syncthreads();
    float inv = 1.0f / Ssum;
    float o0 = e[0] * inv, o1 = e[1] * inv, o2 = e[2] * inv, o3 = e[3] * inv;
    __nv_bfloat16 h0 = __float2bfloat16(o0), h1 = __float2bfloat16(o1);
    __nv_bfloat16 h2 = __float2bfloat16(o2), h3 = __float2bfloat16(o3);
    __nv_bfloat16 l0 = __float2bfloat16(o0 - __bfloat162float(h0));
    __nv_bfloat16 l1 = __float2bfloat16(o1 - __bfloat162float(h1));
    __nv_bfloat16 l2 = __float2bfloat16(o2 - __bfloat162float(h2));
    __nv_bfloat16 l3 = __float2bfloat16(o3 - __bfloat162float(h3));
    size_t base = (size_t)row * Ss + j0;
    *(__nv_bfloat162*)(ah + base)     = __nv_bfloat162(h0, h1);
    *(__nv_bfloat162*)(ah + base + 2) = __nv_bfloat162(h2, h3);
    *(__nv_bfloat162*)(al + base)     = __nv_bfloat162(l0, l1);
    *(__nv_bfloat162*)(al + base + 2) = __nv_bfloat162(l2, l3);
}

// ==================== wmma ctx = attn @ v ====================
#define CAH 0
#define CAL 18432
#define CVH 36864
#define CVL 46080
#define CSMEM 55296

__global__ __launch_bounds__(256)
void ctx_wmma_kernel(const __nv_bfloat16* __restrict__ ah, const __nv_bfloat16* __restrict__ al,
                     const __nv_bfloat16* __restrict__ vh, const __nv_bfloat16* __restrict__ vl,
                     float* __restrict__ ctx) {
    extern __shared__ __align__(128) char smem[];
    int bh = blockIdx.y;
    int b = bh >> 4, hh = bh & 15;
    int i0 = blockIdx.x * 128;
    int tid = threadIdx.x, wid = tid >> 5;
    int m0 = (wid >> 1) * 32, n0 = (wid & 1) * 32;

    wmma::fragment<wmma::accumulator, 16, 16, 16, float> acc[2][2];
    #pragma unroll
    for (int mf = 0; mf < 2; ++mf)
        #pragma unroll
        for (int nf = 0; nf < 2; ++nf)
            wmma::fill_fragment(acc[mf][nf], 0.0f);

    for (int ch = 0; ch < 16; ++ch) {
        int kk0 = ch * 64;
        #pragma unroll
        for (int i = 0; i < 12; ++i) {
            int v = tid + (i << 8);
            if (v < 2048) {
                int split = v >> 10, rem = v & 1023, r = rem >> 3, c = rem & 7;
                const __nv_bfloat16* src = (split ? al : ah);
                uint4 d = *(const uint4*)(src + (size_t)(bh * Ss + i0 + r) * Ss + kk0 + c * 8);
                *(uint4*)(smem + split * 18432 + r * ATSB + c * 16) = d;
            } else {
                int vv2 = v - 2048;
                int split = vv2 >> 9, rem = vv2 & 511, r = rem >> 3, c = rem & 7;
                const __nv_bfloat16* src = (split ? vl : vh);
                uint4 d = *(const uint4*)(src + (size_t)(b * Ss + kk0 + r) * Dd + hh * 64 + c * 8);
                *(uint4*)(smem + CVH + split * 9216 + r * ATSB + c * 16) = d;
            }
        }
        __syncthreads();
        const __nv_bfloat16* Ath = (const __nv_bfloat16*)(smem + CAH);
        const __nv_bfloat16* Atl = (const __nv_bfloat16*)(smem + CAL);
        const __nv_bfloat16* Vth = (const __nv_bfloat16*)(smem + CVH);
        const __nv_bfloat16* Vtl = (const __nv_bfloat16*)(smem + CVL);
        #pragma unroll
        for (int ks = 0; ks < 4; ++ks) {
            wmma::fragment<wmma::matrix_a, 16, 16, 16, __nv_bfloat16, wmma::row_major> fah[2], fal[2];
            wmma::fragment<wmma::matrix_b, 16, 16, 16, __nv_bfloat16, wmma::row_major> fvh[2], fvl[2];
            #pragma unroll
            for (int mf = 0; mf < 2; ++mf) {
                wmma::load_matrix_sync(fah[mf], Ath + (m0 + mf * 16) * ATSE + ks * 16, ATSE);
                wmma::load_matrix_sync(fal[mf], Atl + (m0 + mf * 16) * ATSE + ks * 16, ATSE);
            }
            #pragma unroll
            for (int nf = 0; nf < 2; ++nf) {
                wmma::load_matrix_sync(fvh[nf], Vth + (ks * 16) * ATSE + n0 + nf * 16, ATSE);
                wmma::load_matrix_sync(fvl[nf], Vtl + (ks * 16) * ATSE + n0 + nf * 16, ATSE);
            }
            #pragma unroll
            for (int mf = 0; mf < 2; ++mf)
                #pragma unroll
                for (int nf = 0; nf < 2; ++nf) {
                    wmma::mma_sync(acc[mf][nf], fah[mf], fvh[nf], acc[mf][nf]);
                    wmma::mma_sync(acc[mf][nf], fah[mf], fvl[nf], acc[mf][nf]);
                    wmma::mma_sync(acc[mf][nf], fal[mf], fvh[nf], acc[mf][nf]);
                }
        }
        __syncthreads();
    }
    #pragma unroll
    for (int mf = 0; mf < 2; ++mf)
        #pragma unroll
        for (int nf = 0; nf < 2; ++nf)
            wmma::store_matrix_sync(
                ctx + (size_t)(b * Ss + i0 + m0 + mf * 16) * Dd + hh * 64 + n0 + nf * 16,
                acc[mf][nf], Dd, wmma::mem_row_major);
}

// ==================== launch ====================
extern "C" void kernel_launch(void* const* d_in, const int* in_sizes, int n_in,
                              void* d_out, int out_size) {
    const int*   x    = (const int*)d_in[0];
    const int*   vlen = (const int*)d_in[1];
    const float* emb  = (const float*)d_in[2];
    const float* pos  = (const float*)d_in[3];
    const float* Wq = (const float*)d_in[4]  + (size_t)LAYER * Dd * Dd;
    const float* bq = (const float*)d_in[5]  + LAYER * Dd;
    const float* Wk = (const float*)d_in[6]  + (size_t)LAYER * Dd * Dd;
    const float* bk = (const float*)d_in[7]  + LAYER * Dd;
    const float* Wv = (const float*)d_in[8]  + (size_t)LAYER * Dd * Dd;
    const float* bv = (const float*)d_in[9]  + LAYER * Dd;
    const float* Wo = (const float*)d_in[10] + (size_t)LAYER * Dd * Dd;
    const float* bo = (const float*)d_in[11] + LAYER * Dd;
    const float* W1 = (const float*)d_in[12] + (size_t)LAYER * Dd * FFf;
    const float* b1 = (const float*)d_in[13] + LAYER * FFf;
    const float* W2 = (const float*)d_in[14] + (size_t)LAYER * FFf * Dd;
    const float* b2 = (const float*)d_in[15] + LAYER * Dd;
    const float* g1    = (const float*)d_in[16] + LAYER * Dd;
    const float* beta1 = (const float*)d_in[17] + LAYER * Dd;
    const float* g2    = (const float*)d_in[18] + LAYER * Dd;
    const float* beta2 = (const float*)d_in[19] + LAYER * Dd;
    float* out = (float*)d_out;

    float *h, *x1, *sc, *ctx, *mid, *x2;
    __nv_bfloat16 *f, *Ah, *Al, *Bh, *Bl, *qh, *ql, *kh, *kl, *vh, *vl, *ah, *al;
    cudaGetSymbolAddress((void**)&h,   g_h);
    cudaGetSymbolAddress((void**)&x1,  g_x1);
    cudaGetSymbolAddress((void**)&sc,  g_sc);
    cudaGetSymbolAddress((void**)&ctx, g_ctx);
    cudaGetSymbolAddress((void**)&mid, g_mid);
    cudaGetSymbolAddress((void**)&x2,  g_x2);
    cudaGetSymbolAddress((void**)&f,   g_f);
    cudaGetSymbolAddress((void**)&Ah,  g_Ah);
    cudaGetSymbolAddress((void**)&Al,  g_Al);
    cudaGetSymbolAddress((void**)&Bh,  g_Bh);
    cudaGetSymbolAddress((void**)&Bl,  g_Bl);
    cudaGetSymbolAddress((void**)&qh,  g_qh);
    cudaGetSymbolAddress((void**)&ql,  g_ql);
    cudaGetSymbolAddress((void**)&kh,  g_kh);
    cudaGetSymbolAddress((void**)&kl,  g_kl);
    cudaGetSymbolAddress((void**)&vh,  g_vh);
    cudaGetSymbolAddress((void**)&vl,  g_vl);
    cudaGetSymbolAddress((void**)&ah,  g_ah);
    cudaGetSymbolAddress((void**)&al,  g_al);
    __nv_bfloat16* fh = f;
    __nv_bfloat16* fl = f + (size_t)MROWS * FFf;

    cudaFuncSetAttribute(bgemm_kernel<1>, cudaFuncAttributeMaxDynamicSharedMemorySize, SMEM_B);
    cudaFuncSetAttribute(bgemm_kernel<3>, cudaFuncAttributeMaxDynamicSharedMemorySize, SMEM_B);
    cudaFuncSetAttribute(bgemm_kernel<4>, cudaFuncAttributeMaxDynamicSharedMemorySize, SMEM_B);
    cudaFuncSetAttribute(scores_wmma_kernel, cudaFuncAttributeMaxDynamicSharedMemorySize, SSMEM);
    cudaFuncSetAttribute(ctx_wmma_kernel, cudaFuncAttributeMaxDynamicSharedMemorySize, CSMEM);

    detect_kernel<<<1, 256>>>(x);
    embed_kernel<<<(MROWS * (Dd/4)) / 256, 256>>>(x, emb, pos, h);
    ln_kernel<<<MROWS, 256>>>(h, g1, beta1, x1);

    dim3 blkT(32, 8);
    dim3 gdd(Dd / 256, MROWS / 128);           // (4, 64)

    convsplit_kernel<<<(MROWS * Dd / 4) / 256, 256>>>(x1, Ah, Al, MROWS * Dd / 4);
    convtrans_kernel<<<dim3(Dd/32, Dd/32), blkT>>>(Wq, Bh, Bl, Dd, Dd);
    bgemm_kernel<3><<<gdd, 256, SMEM_B>>>(Ah, Al, Bh, Bl, bq, nullptr, nullptr, qh, ql, Dd, Dd);
    convtrans_kernel<<<dim3(Dd/32, Dd/32), blkT>>>(Wk, Bh, Bl, Dd, Dd);
    bgemm_kernel<3><<<gdd, 256, SMEM_B>>>(Ah, Al, Bh, Bl, bk, nullptr, nullptr, kh, kl, Dd, Dd);
    convtrans_kernel<<<dim3(Dd/32, Dd/32), blkT>>>(Wv, Bh, Bl, Dd, Dd);
    bgemm_kernel<3><<<gdd, 256, SMEM_B>>>(Ah, Al, Bh, Bl, bv, nullptr, nullptr, vh, vl, Dd, Dd);

    dim3 gs(Ss / 128, Ss / 128, Bb * Hh);      // (8, 8, 128)
    scores_wmma_kernel<<<gs, 256, SSMEM>>>(qh, ql, kh, kl, sc);
    softmax_kernel<<<Bb * Hh * Ss, 256>>>(sc, vlen, ah, al);
    dim3 gc(Ss / 128, Bb * Hh);                // (8, 128)
    ctx_wmma_kernel<<<gc, 256, CSMEM>>>(ah, al, vh, vl, ctx);

    convsplit_kernel<<<(MROWS * Dd / 4) / 256, 256>>>(ctx, Ah, Al, MROWS * Dd / 4);
    convtrans_kernel<<<dim3(Dd/32, Dd/32), blkT>>>(Wo, Bh, Bl, Dd, Dd);
    bgemm_kernel<1><<<gdd, 256, SMEM_B>>>(Ah, Al, Bh, Bl, bo, h, mid, nullptr, nullptr, Dd, Dd);

    ln_kernel<<<MROWS, 256>>>(mid, g2, beta2, x2);

    convsplit_kernel<<<(MROWS * Dd / 4) / 256, 256>>>(x2, Ah, Al, MROWS * Dd / 4);
    convtrans_kernel<<<dim3(FFf/32, Dd/32), blkT>>>(W1, Bh, Bl, Dd, FFf);
    dim3 gff(FFf / 256, MROWS / 128);          // (16, 64)
    bgemm_kernel<4><<<gff, 256, SMEM_B>>>(Ah, Al, Bh, Bl, b1, nullptr, nullptr, fh, fl, FFf, Dd);

    convtrans_kernel<<<dim3(Dd/32, FFf/32), blkT>>>(W2, Bh, Bl, FFf, Dd);
    bgemm_kernel<1><<<gdd, 256, SMEM_B>>>(fh, fl, Bh, Bl, b2, mid, out, nullptr, nullptr, Dd, FFf);
}

// round 10
// speedup vs baseline: 2.4243x; 1.0050x over previous
#include <cuda_runtime.h>
#include <cuda_bf16.h>
#include <cuda_pipeline.h>
#include <mma.h>
#include <math.h>
#include <stdint.h>

using namespace nvcuda;

#define Bb 8
#define Ss 1024
#define Dd 1024
#define Hh 16
#define DHh 64
#define FFf 4096
#define LAYER 3
#define MROWS (Bb*Ss)   /* 8192 */

// ---------------- scratch (device globals; allocation-free rule) ----------------
__device__ float g_h  [MROWS*Dd];
__device__ float g_x1 [MROWS*Dd];
__device__ float g_sc [(size_t)Bb*Hh*Ss*Ss];   // 512 MB scores
__device__ float g_ctx[MROWS*Dd];
__device__ float g_mid[MROWS*Dd];
__device__ float g_x2 [MROWS*Dd];
__device__ __nv_bfloat16 g_f [(size_t)2*MROWS*FFf];  // ffn split hi|lo
__device__ __nv_bfloat16 g_Ah[(size_t)MROWS*FFf];
__device__ __nv_bfloat16 g_Al[(size_t)MROWS*FFf];
__device__ __nv_bfloat16 g_Bh[(size_t)FFf*Dd];
__device__ __nv_bfloat16 g_Bl[(size_t)FFf*Dd];
__device__ __nv_bfloat16 g_qh[MROWS*Dd];
__device__ __nv_bfloat16 g_ql[MROWS*Dd];
__device__ __nv_bfloat16 g_kh[MROWS*Dd];
__device__ __nv_bfloat16 g_kl[MROWS*Dd];
__device__ __nv_bfloat16 g_vh[MROWS*Dd];
__device__ __nv_bfloat16 g_vl[MROWS*Dd];
__device__ __nv_bfloat16 g_ah[(size_t)Bb*Hh*Ss*Ss];
__device__ __nv_bfloat16 g_al[(size_t)Bb*Hh*Ss*Ss];
__device__ int   g_is64;

// ==================== dtype detection ====================
__global__ void detect_kernel(const int* __restrict__ x) {
    __shared__ int any;
    if (threadIdx.x == 0) any = 0;
    __syncthreads();
    int local = 0;
    for (int i = threadIdx.x; i < 4096; i += blockDim.x)
        if (x[2*i + 1] != 0) local = 1;
    if (local) any = 1;
    __syncthreads();
    if (threadIdx.x == 0) g_is64 = (any == 0) ? 1 : 0;
}

// ==================== embed ====================
__global__ void embed_kernel(const int* __restrict__ x, const float* __restrict__ emb,
                             const float* __restrict__ pos, float* __restrict__ h) {
    int i = blockIdx.x * blockDim.x + threadIdx.x;
    if (i >= MROWS * (Dd/4)) return;
    int row = i >> 8;
    int dc  = i & 255;
    int s   = row & (Ss - 1);
    long long tok = g_is64 ? ((const long long*)x)[row] : (long long)x[row];
    float4 e = ((const float4*)emb)[(size_t)tok * 256 + dc];
    float4 p = ((const float4*)pos)[(size_t)s   * 256 + dc];
    float4 r;
    r.x = fmaf(e.x, 32.0f, p.x);
    r.y = fmaf(e.y, 32.0f, p.y);
    r.z = fmaf(e.z, 32.0f, p.z);
    r.w = fmaf(e.w, 32.0f, p.w);
    ((float4*)h)[i] = r;
}

// ==================== layernorm ====================
__global__ __launch_bounds__(256)
void ln_kernel(const float* __restrict__ in, const float* __restrict__ gamma,
               const float* __restrict__ beta, float* __restrict__ out) {
    int row = blockIdx.x;
    int tid = threadIdx.x;
    const float4* xr = (const float4*)(in + (size_t)row * Dd);
    float4 v = xr[tid];
    float s1 = v.x + v.y + v.z + v.w;
    float s2 = v.x*v.x + v.y*v.y + v.z*v.z + v.w*v.w;
    #pragma unroll
    for (int o = 16; o; o >>= 1) {
        s1 += __shfl_xor_sync(0xffffffffu, s1, o);
        s2 += __shfl_xor_sync(0xffffffffu, s2, o);
    }
    __shared__ float a1[8], a2[8];
    int lane = tid & 31, wid = tid >> 5;
    if (lane == 0) { a1[wid] = s1; a2[wid] = s2; }
    __syncthreads();
    __shared__ float mS, invS;
    if (tid == 0) {
        float t1 = 0.f, t2 = 0.f;
        #pragma unroll
        for (int w = 0; w < 8; ++w) { t1 += a1[w]; t2 += a2[w]; }
        float mean = t1 * (1.0f / Dd);
        float var  = t2 * (1.0f / Dd) - mean * mean;
        mS = mean; invS = rsqrtf(var + 1e-5f);
    }
    __syncthreads();
    float mean = mS, inv = invS;
    float4 g4 = ((const float4*)gamma)[tid];
    float4 b4 = ((const float4*)beta)[tid];
    float4 o4;
    o4.x = (v.x - mean) * inv * g4.x + b4.x;
    o4.y = (v.y - mean) * inv * g4.y + b4.y;
    o4.z = (v.z - mean) * inv * g4.z + b4.z;
    o4.w = (v.w - mean) * inv * g4.w + b4.w;
    ((float4*)(out + (size_t)row * Dd))[tid] = o4;
}

// ==================== fp32 -> split bf16 ====================
__global__ void convsplit_kernel(const float* __restrict__ in, __nv_bfloat16* __restrict__ hi,
                                 __nv_bfloat16* __restrict__ lo, int n4) {
    int i = blockIdx.x * blockDim.x + threadIdx.x;
    if (i >= n4) return;
    float4 v = ((const float4*)in)[i];
    __nv_bfloat16 h0 = __float2bfloat16(v.x), h1 = __float2bfloat16(v.y);
    __nv_bfloat16 h2 = __float2bfloat16(v.z), h3 = __float2bfloat16(v.w);
    __nv_bfloat16 l0 = __float2bfloat16(v.x - __bfloat162float(h0));
    __nv_bfloat16 l1 = __float2bfloat16(v.y - __bfloat162float(h1));
    __nv_bfloat16 l2 = __float2bfloat16(v.z - __bfloat162float(h2));
    __nv_bfloat16 l3 = __float2bfloat16(v.w - __bfloat162float(h3));
    __nv_bfloat162* H = (__nv_bfloat162*)hi;
    __nv_bfloat162* L = (__nv_bfloat162*)lo;
    H[2*i]   = __nv_bfloat162(h0, h1);
    H[2*i+1] = __nv_bfloat162(h2, h3);
    L[2*i]   = __nv_bfloat162(l0, l1);
    L[2*i+1] = __nv_bfloat162(l2, l3);
}

// ==================== weight fp32 [K,N] -> split bf16 transposed [N,K] ====================
__global__ void convtrans_kernel(const float* __restrict__ W, __nv_bfloat16* __restrict__ TH,
                                 __nv_bfloat16* __restrict__ TL, int K, int N) {
    __shared__ float t[32][33];
    int nb = blockIdx.x * 32, kb = blockIdx.y * 32;
    int tx = threadIdx.x, ty = threadIdx.y;
    for (int r = ty; r < 32; r += 8)
        t[r][tx] = W[(size_t)(kb + r) * N + nb + tx];
    __syncthreads();
    for (int r = ty; r < 32; r += 8) {
        float v = t[tx][r];
        __nv_bfloat16 h = __float2bfloat16(v);
        __nv_bfloat16 l = __float2bfloat16(v - __bfloat162float(h));
        size_t o = (size_t)(nb + r) * K + kb + tx;
        TH[o] = h; TL[o] = l;
    }
}

// ==================== wmma split-bf16 GEMM (128x256 tile, 3-stage cp.async) ====================
#define WTSE 40
#define WTSB 80
#define A_TILE_B (128*WTSB)
#define B_TILE_B (256*WTSB)
#define STAGE_B  (2*A_TILE_B + 2*B_TILE_B)  /* 61440 */
#define SMEM_B   (3*STAGE_B)                /* 184320 */

template<int EPI>
__global__ __launch_bounds__(256)
void bgemm_kernel(const __nv_bfloat16* __restrict__ Ah, const __nv_bfloat16* __restrict__ Al,
                  const __nv_bfloat16* __restrict__ Bh, const __nv_bfloat16* __restrict__ Bl,
                  const float* __restrict__ bias, const float* __restrict__ res,
                  float* __restrict__ C, __nv_bfloat16* __restrict__ Oh,
                  __nv_bfloat16* __restrict__ Ol, int N, int K) {
    extern __shared__ __align__(128) char smem[];
    int tid = threadIdx.x, wid = tid >> 5;
    int rowBase = blockIdx.y * 128, colBase = blockIdx.x * 256;
    int m0 = (wid >> 2) * 64, n0 = (wid & 3) * 64;

    const __nv_bfloat16* gsrc[12];
    int soff[12];
    #pragma unroll
    for (int i = 0; i < 12; ++i) {
        int v = tid + (i << 8);
        const __nv_bfloat16* base;
        int grow, s;
        if (v < 1024) {
            int t2 = v >> 9, idx = v & 511, row = idx >> 2, c = idx & 3;
            base = t2 ? Al : Ah;
            grow = rowBase + row;
            s = t2 * A_TILE_B + row * WTSB + c * 16;
            gsrc[i] = base + (size_t)grow * K + c * 8;
        } else {
            int w = v - 1024;
            int t2 = w >> 10, idx = w & 1023, row = idx >> 2, c = idx & 3;
            base = t2 ? Bl : Bh;
            grow = colBase + row;
            s = 2 * A_TILE_B + t2 * B_TILE_B + row * WTSB + c * 16;
            gsrc[i] = base + (size_t)grow * K + c * 8;
        }
        soff[i] = s;
    }

    wmma::fragment<wmma::accumulator, 16, 16, 16, float> acc[4][4];
    #pragma unroll
    for (int mf = 0; mf < 4; ++mf)
        #pragma unroll
        for (int nf = 0; nf < 4; ++nf)
            wmma::fill_fragment(acc[mf][nf], 0.0f);

    const int nch = K >> 5;
    #pragma unroll
    for (int i = 0; i < 12; ++i)
        __pipeline_memcpy_async(smem + soff[i], gsrc[i], 16);
    __pipeline_commit();
    #pragma unroll
    for (int i = 0; i < 12; ++i)
        __pipeline_memcpy_async(smem + STAGE_B + soff[i], gsrc[i] + 32, 16);
    __pipeline_commit();

    int stage_id = 0, fill_id = 2;
    for (int ch = 0; ch < nch; ++ch) {
        if (ch + 1 < nch) __pipeline_wait_prior(1);
        else              __pipeline_wait_prior(0);
        __syncthreads();
        if (ch + 2 < nch) {
            #pragma unroll
            for (int i = 0; i < 12; ++i)
                __pipeline_memcpy_async(smem + fill_id * STAGE_B + soff[i],
                                        gsrc[i] + (size_t)(ch + 2) * 32, 16);
            __pipeline_commit();
        }
        char* stage = smem + stage_id * STAGE_B;
        const __nv_bfloat16* At_h = (const __nv_bfloat16*)(stage);
        const __nv_bfloat16* At_l = (const __nv_bfloat16*)(stage + A_TILE_B);
        const __nv_bfloat16* Bt_h = (const __nv_bfloat16*)(stage + 2 * A_TILE_B);
        const __nv_bfloat16* Bt_l = (const __nv_bfloat16*)(stage + 2 * A_TILE_B + B_TILE_B);
        #pragma unroll
        for (int ks = 0; ks < 2; ++ks) {
            wmma::fragment<wmma::matrix_b, 16, 16, 16, __nv_bfloat16, wmma::col_major> bh[4], bl[4];
            #pragma unroll
            for (int nf = 0; nf < 4; ++nf) {
                wmma::load_matrix_sync(bh[nf], Bt_h + (n0 + nf * 16) * WTSE + ks * 16, WTSE);
                wmma::load_matrix_sync(bl[nf], Bt_l + (n0 + nf * 16) * WTSE + ks * 16, WTSE);
            }
            #pragma unroll
            for (int mf = 0; mf < 4; ++mf) {
                wmma::fragment<wmma::matrix_a, 16, 16, 16, __nv_bfloat16, wmma::row_major> fa, fl2;
                wmma::load_matrix_sync(fa,  At_h + (m0 + mf * 16) * WTSE + ks * 16, WTSE);
                wmma::load_matrix_sync(fl2, At_l + (m0 + mf * 16) * WTSE + ks * 16, WTSE);
                #pragma unroll
                for (int nf = 0; nf < 4; ++nf)
                    wmma::mma_sync(acc[mf][nf], fa, bh[nf], acc[mf][nf]);
                #pragma unroll
                for (int nf = 0; nf < 4; ++nf)
                    wmma::mma_sync(acc[mf][nf], fa, bl[nf], acc[mf][nf]);
                #pragma unroll
                for (int nf = 0; nf < 4; ++nf)
                    wmma::mma_sync(acc[mf][nf], fl2, bh[nf], acc[mf][nf]);
            }
        }
        stage_id = (stage_id == 2) ? 0 : stage_id + 1;
        fill_id  = (fill_id == 2)  ? 0 : fill_id + 1;
    }
    __syncthreads();

    float* sf = (float*)smem;
    #pragma unroll
    for (int mf = 0; mf < 4; ++mf)
        #pragma unroll
        for (int nf = 0; nf < 4; ++nf)
            wmma::store_matrix_sync(sf + (m0 + mf * 16) * 260 + n0 + nf * 16,
                                    acc[mf][nf], 260, wmma::mem_row_major);
    __syncthreads();
    #pragma unroll
    for (int i = 0; i < 32; ++i) {
        int v = tid + (i << 8);
        int r = v >> 6, c4 = (v & 63) * 4;
        float4 val = *(float4*)(sf + r * 260 + c4);
        int col = colBase + c4;
        float4 bv = *(const float4*)(bias + col);
        val.x += bv.x; val.y += bv.y; val.z += bv.z; val.w += bv.w;
        size_t o = (size_t)(rowBase + r) * N + col;
        if (EPI == 1) {
            float4 rv = *(const float4*)(res + o);
            val.x += rv.x; val.y += rv.y; val.z += rv.z; val.w += rv.w;
        }
        if (EPI == 2 || EPI == 4) {
            val.x = fmaxf(val.x, 0.f); val.y = fmaxf(val.y, 0.f);
            val.z = fmaxf(val.z, 0.f); val.w = fmaxf(val.w, 0.f);
        }
        if (EPI <= 2) {
            *(float4*)(C + o) = val;
        } else {
            __nv_bfloat16 h0 = __float2bfloat16(val.x), h1 = __float2bfloat16(val.y);
            __nv_bfloat16 h2 = __float2bfloat16(val.z), h3 = __float2bfloat16(val.w);
            __nv_bfloat16 l0 = __float2bfloat16(val.x - __bfloat162float(h0));
            __nv_bfloat16 l1 = __float2bfloat16(val.y - __bfloat162float(h1));
            __nv_bfloat16 l2 = __float2bfloat16(val.z - __bfloat162float(h2));
            __nv_bfloat16 l3 = __float2bfloat16(val.w - __bfloat162float(h3));
            *(__nv_bfloat162*)(Oh + o)     = __nv_bfloat162(h0, h1);
            *(__nv_bfloat162*)(Oh + o + 2) = __nv_bfloat162(h2, h3);
            *(__nv_bfloat162*)(Ol + o)     = __nv_bfloat162(l0, l1);
            *(__nv_bfloat162*)(Ol + o + 2) = __nv_bfloat162(l2, l3);
        }
    }
}

// ==================== wmma attention scores (mask-aware tile skip) ====================
#define ATSE 72
#define ATSB 144
#define STILE (128*ATSB)
#define SSMEM (4*STILE)

__global__ __launch_bounds__(256)
void scores_wmma_kernel(const __nv_bfloat16* __restrict__ qh, const __nv_bfloat16* __restrict__ ql,
                        const __nv_bfloat16* __restrict__ kh, const __nv_bfloat16* __restrict__ kl,
                        const int* __restrict__ vlen, float* __restrict__ sc) {
    extern __shared__ __align__(128) char smem[];
    int bh = blockIdx.z;
    int b = bh >> 4, hh = bh & 15;
    int i0 = blockIdx.y * 128, j0 = blockIdx.x * 128;
    int vl = g_is64 ? (int)((const long long*)vlen)[b] : vlen[b];
    if (j0 >= vl) return;
    int tid = threadIdx.x, wid = tid >> 5;
    int m0 = (wid >> 2) * 64, n0 = (wid & 3) * 32;

    #pragma unroll
    for (int i = 0; i < 16; ++i) {
        int v = tid + (i << 8);
        int m = v >> 10, rem = v & 1023, r = rem >> 3, c = rem & 7;
        const __nv_bfloat16* mat = (m == 0) ? qh : (m == 1) ? ql : (m == 2) ? kh : kl;
        int rowg = ((m < 2) ? i0 : j0) + r;
        uint4 d = *(const uint4*)(mat + (size_t)(b * Ss + rowg) * Dd + hh * 64 + c * 8);
        *(uint4*)(smem + m * STILE + r * ATSB + c * 16) = d;
    }
    __syncthreads();

    wmma::fragment<wmma::accumulator, 16, 16, 16, float> acc[4][2];
    #pragma unroll
    for (int mf = 0; mf < 4; ++mf)
        #pragma unroll
        for (int nf = 0; nf < 2; ++nf)
            wmma::fill_fragment(acc[mf][nf], 0.0f);

    const __nv_bfloat16* Qh = (const __nv_bfloat16*)(smem);
    const __nv_bfloat16* Ql = (const __nv_bfloat16*)(smem + STILE);
    const __nv_bfloat16* Kh = (const __nv_bfloat16*)(smem + 2 * STILE);
    const __nv_bfloat16* Kl = (const __nv_bfloat16*)(smem + 3 * STILE);
    #pragma unroll
    for (int ks = 0; ks < 4; ++ks) {
        wmma::fragment<wmma::matrix_a, 16, 16, 16, __nv_bfloat16, wmma::row_major> ah[4], al[4];
        wmma::fragment<wmma::matrix_b, 16, 16, 16, __nv_bfloat16, wmma::col_major> bh2[2], bl2[2];
        #pragma unroll
        for (int mf = 0; mf < 4; ++mf) {
            wmma::load_matrix_sync(ah[mf], Qh + (m0 + mf * 16) * ATSE + ks * 16, ATSE);
            wmma::load_matrix_sync(al[mf], Ql + (m0 + mf * 16) * ATSE + ks * 16, ATSE);
        }
        #pragma unroll
        for (int nf = 0; nf < 2; ++nf) {
            wmma::load_matrix_sync(bh2[nf], Kh + (n0 + nf * 16) * ATSE + ks * 16, ATSE);
            wmma::load_matrix_sync(bl2[nf], Kl + (n0 + nf * 16) * ATSE + ks * 16, ATSE);
        }
        #pragma unroll
        for (int mf = 0; mf < 4; ++mf)
            #pragma unroll
            for (int nf = 0; nf < 2; ++nf) {
                wmma::mma_sync(acc[mf][nf], ah[mf], bh2[nf], acc[mf][nf]);
                wmma::mma_sync(acc[mf][nf], ah[mf], bl2[nf], acc[mf][nf]);
                wmma::mma_sync(acc[mf][nf], al[mf], bh2[nf], acc[mf][nf]);
            }
    }
    #pragma unroll
    for (int mf = 0; mf < 4; ++mf)
        #pragma unroll
        for (int nf = 0; nf < 2; ++nf) {
            #pragma unroll
            for (int t = 0; t < acc[mf][nf].num_elements; ++t)
                acc[mf][nf].x[t] *= 0.125f;
            wmma::store_matrix_sync(
                sc + ((size_t)bh * Ss + i0 + m0 + mf * 16) * Ss + j0 + n0 + nf * 16,
                acc[mf][nf], Ss, wmma::mem_row_major);
        }
}

// ==================== softmax (mask-aware loads/stores + split-bf16 output) ====================
__global__ __launch_bounds__(256)
void softmax_kernel(const float* __restrict__ sc, const int* __restrict__ vlen,
                    __nv_bfloat16* __restrict__ ah, __nv_bfloat16* __restrict__ al) {
    int row = blockIdx.x;
    int b = row >> 14;
    int vl = g_is64 ? (int)((const long long*)vlen)[b] : vlen[b];
    int vlc = (vl + 63) & ~63;
    const float* sr = sc + (size_t)row * Ss;
    int tid = threadIdx.x;
    int j0 = tid * 4;
    float vals[4] = {-1e9f, -1e9f, -1e9f, -1e9f};
    if (j0 < vl) {
        float4 vv = *(const float4*)(sr + j0);
        vals[0] = vv.x; vals[1] = vv.y; vals[2] = vv.z; vals[3] = vv.w;
        #pragma unroll
        for (int c = 0; c < 4; c++) if (j0 + c >= vl) vals[c] = -1e9f;
    }
    float m = fmaxf(fmaxf(vals[0], vals[1]), fmaxf(vals[2], vals[3]));
    #pragma unroll
    for (int o = 16; o; o >>= 1) m = fmaxf(m, __shfl_xor_sync(0xffffffffu, m, o));
    __shared__ float r1[8];
    int lane = tid & 31, wid = tid >> 5;
    if (lane == 0) r1[wid] = m;
    __syncthreads();
    __shared__ float Ms;
    if (tid == 0) {
        float t = r1[0];
        #pragma unroll
        for (int w = 1; w < 8; w++) t = fmaxf(t, r1[w]);
        Ms = t;
    }
    __syncthreads();
    float M = Ms;
    float e[4];
    float s = 0.f;
    #pragma unroll
    for (int c = 0; c < 4; c++) { e[c] = expf(vals[c] - M); s += e[c]; }
    #pragma unroll
    for (int o = 16; o; o >>= 1) s += __shfl_xor_sync(0xffffffffu, s, o);
    __shared__ float r2[8];
    if (lane == 0) r2[wid] = s;
    __syncthreads();
    __shared__ float Ssum;
    if (tid == 0) {
        float t = 0.f;
        #pragma unroll
        for (int w = 0; w < 8; w++) t += r2[w];
        Ssum = t;
    }
    __syncthreads();
    if (j0 >= vlc) return;
    float inv = 1.0f / Ssum;
    float o0 = e[0] * inv, o1 = e[1] * inv, o2 = e[2] * inv, o3 = e[3] * inv;
    __nv_bfloat16 h0 = __float2bfloat16(o0), h1 = __float2bfloat16(o1);
    __nv_bfloat16 h2 = __float2bfloat16(o2), h3 = __float2bfloat16(o3);
    __nv_bfloat16 l0 = __float2bfloat16(o0 - __bfloat162float(h0));
    __nv_bfloat16 l1 = __float2bfloat16(o1 - __bfloat162float(h1));
    __nv_bfloat16 l2 = __float2bfloat16(o2 - __bfloat162float(h2));
    __nv_bfloat16 l3 = __float2bfloat16(o3 - __bfloat162float(h3));
    size_t base = (size_t)row * Ss + j0;
    *(__nv_bfloat162*)(ah + base)     = __nv_bfloat162(h0, h1);
    *(__nv_bfloat162*)(ah + base + 2) = __nv_bfloat162(h2, h3);
    *(__nv_bfloat162*)(al + base)     = __nv_bfloat162(l0, l1);
    *(__nv_bfloat162*)(al + base + 2) = __nv_bfloat162(l2, l3);
}

// ==================== wmma ctx = attn @ v (mask-bounded K loop) ====================
#define CAH 0
#define CAL 18432
#define CVH 36864
#define CVL 46080
#define CSMEM 55296

__global__ __launch_bounds__(256)
void ctx_wmma_kernel(const __nv_bfloat16* __restrict__ ah, const __nv_bfloat16* __restrict__ al,
                     const __nv_bfloat16* __restrict__ vh, const __nv_bfloat16* __restrict__ vl_,
                     const int* __restrict__ vlen, float* __restrict__ ctx) {
    extern __shared__ __align__(128) char smem[];
    int bh = blockIdx.y;
    int b = bh >> 4, hh = bh & 15;
    int i0 = blockIdx.x * 128;
    int vl = g_is64 ? (int)((const long long*)vlen)[b] : vlen[b];
    int nch_eff = (vl + 63) >> 6;
    int tid = threadIdx.x, wid = tid >> 5;
    int m0 = (wid >> 1) * 32, n0 = (wid & 1) * 32;

    wmma::fragment<wmma::accumulator, 16, 16, 16, float> acc[2][2];
    #pragma unroll
    for (int mf = 0; mf < 2; ++mf)
        #pragma unroll
        for (int nf = 0; nf < 2; ++nf)
            wmma::fill_fragment(acc[mf][nf], 0.0f);

    for (int ch = 0; ch < nch_eff; ++ch) {
        int kk0 = ch * 64;
        #pragma unroll
        for (int i = 0; i < 12; ++i) {
            int v = tid + (i << 8);
            if (v < 2048) {
                int split = v >> 10, rem = v & 1023, r = rem >> 3, c = rem & 7;
                const __nv_bfloat16* src = (split ? al : ah);
                uint4 d = *(const uint4*)(src + (size_t)(bh * Ss + i0 + r) * Ss + kk0 + c * 8);
                *(uint4*)(smem + split * 18432 + r * ATSB + c * 16) = d;
            } else {
                int vv2 = v - 2048;
                int split = vv2 >> 9, rem = vv2 & 511, r = rem >> 3, c = rem & 7;
                const __nv_bfloat16* src = (split ? vl_ : vh);
                uint4 d = *(const uint4*)(src + (size_t)(b * Ss + kk0 + r) * Dd + hh * 64 + c * 8);
                *(uint4*)(smem + CVH + split * 9216 + r * ATSB + c * 16) = d;
            }
        }
        __syncthreads();
        const __nv_bfloat16* Ath = (const __nv_bfloat16*)(smem + CAH);
        const __nv_bfloat16* Atl = (const __nv_bfloat16*)(smem + CAL);
        const __nv_bfloat16* Vth = (const __nv_bfloat16*)(smem + CVH);
        const __nv_bfloat16* Vtl = (const __nv_bfloat16*)(smem + CVL);
        #pragma unroll
        for (int ks = 0; ks < 4; ++ks) {
            wmma::fragment<wmma::matrix_a, 16, 16, 16, __nv_bfloat16, wmma::row_major> fah[2], fal[2];
            wmma::fragment<wmma::matrix_b, 16, 16, 16, __nv_bfloat16, wmma::row_major> fvh[2], fvl[2];
            #pragma unroll
            for (int mf = 0; mf < 2; ++mf) {
                wmma::load_matrix_sync(fah[mf], Ath + (m0 + mf * 16) * ATSE + ks * 16, ATSE);
                wmma::load_matrix_sync(fal[mf], Atl + (m0 + mf * 16) * ATSE + ks * 16, ATSE);
            }
            #pragma unroll
            for (int nf = 0; nf < 2; ++nf) {
                wmma::load_matrix_sync(fvh[nf], Vth + (ks * 16) * ATSE + n0 + nf * 16, ATSE);
                wmma::load_matrix_sync(fvl[nf], Vtl + (ks * 16) * ATSE + n0 + nf * 16, ATSE);
            }
            #pragma unroll
            for (int mf = 0; mf < 2; ++mf)
                #pragma unroll
                for (int nf = 0; nf < 2; ++nf) {
                    wmma::mma_sync(acc[mf][nf], fah[mf], fvh[nf], acc[mf][nf]);
                    wmma::mma_sync(acc[mf][nf], fah[mf], fvl[nf], acc[mf][nf]);
                    wmma::mma_sync(acc[mf][nf], fal[mf], fvh[nf], acc[mf][nf]);
                }
        }
        __syncthreads();
    }
    #pragma unroll
    for (int mf = 0; mf < 2; ++mf)
        #pragma unroll
        for (int nf = 0; nf < 2; ++nf)
            wmma::store_matrix_sync(
                ctx + (size_t)(b * Ss + i0 + m0 + mf * 16) * Dd + hh * 64 + n0 + nf * 16,
                acc[mf][nf], Dd, wmma::mem_row_major);
}

// ==================== launch ====================
extern "C" void kernel_launch(void* const* d_in, const int* in_sizes, int n_in,
                              void* d_out, int out_size) {
    const int*   x    = (const int*)d_in[0];
    const int*   vlen = (const int*)d_in[1];
    const float* emb  = (const float*)d_in[2];
    const float* pos  = (const float*)d_in[3];
    const float* Wq = (const float*)d_in[4]  + (size_t)LAYER * Dd * Dd;
    const float* bq = (const float*)d_in[5]  + LAYER * Dd;
    const float* Wk = (const float*)d_in[6]  + (size_t)LAYER * Dd * Dd;
    const float* bk = (const float*)d_in[7]  + LAYER * Dd;
    const float* Wv = (const float*)d_in[8]  + (size_t)LAYER * Dd * Dd;
    const float* bv = (const float*)d_in[9]  + LAYER * Dd;
    const float* Wo = (const float*)d_in[10] + (size_t)LAYER * Dd * Dd;
    const float* bo = (const float*)d_in[11] + LAYER * Dd;
    const float* W1 = (const float*)d_in[12] + (size_t)LAYER * Dd * FFf;
    const float* b1 = (const float*)d_in[13] + LAYER * FFf;
    const float* W2 = (const float*)d_in[14] + (size_t)LAYER * FFf * Dd;
    const float* b2 = (const float*)d_in[15] + LAYER * Dd;
    const float* g1    = (const float*)d_in[16] + LAYER * Dd;
    const float* beta1 = (const float*)d_in[17] + LAYER * Dd;
    const float* g2    = (const float*)d_in[18] + LAYER * Dd;
    const float* beta2 = (const float*)d_in[19] + LAYER * Dd;
    float* out = (float*)d_out;

    float *h, *x1, *sc, *ctx, *mid, *x2;
    __nv_bfloat16 *f, *Ah, *Al, *Bh, *Bl, *qh, *ql, *kh, *kl, *vh, *vl, *ah, *al;
    cudaGetSymbolAddress((void**)&h,   g_h);
    cudaGetSymbolAddress((void**)&x1,  g_x1);
    cudaGetSymbolAddress((void**)&sc,  g_sc);
    cudaGetSymbolAddress((void**)&ctx, g_ctx);
    cudaGetSymbolAddress((void**)&mid, g_mid);
    cudaGetSymbolAddress((void**)&x2,  g_x2);
    cudaGetSymbolAddress((void**)&f,   g_f);
    cudaGetSymbolAddress((void**)&Ah,  g_Ah);
    cudaGetSymbolAddress((void**)&Al,  g_Al);
    cudaGetSymbolAddress((void**)&Bh,  g_Bh);
    cudaGetSymbolAddress((void**)&Bl,  g_Bl);
    cudaGetSymbolAddress((void**)&qh,  g_qh);
    cudaGetSymbolAddress((void**)&ql,  g_ql);
    cudaGetSymbolAddress((void**)&kh,  g_kh);
    cudaGetSymbolAddress((void**)&kl,  g_kl);
    cudaGetSymbolAddress((void**)&vh,  g_vh);
    cudaGetSymbolAddress((void**)&vl,  g_vl);
    cudaGetSymbolAddress((void**)&ah,  g_ah);
    cudaGetSymbolAddress((void**)&al,  g_al);
    __nv_bfloat16* fh = f;
    __nv_bfloat16* fl = f + (size_t)MROWS * FFf;

    cudaFuncSetAttribute(bgemm_kernel<1>, cudaFuncAttributeMaxDynamicSharedMemorySize, SMEM_B);
    cudaFuncSetAttribute(bgemm_kernel<3>, cudaFuncAttributeMaxDynamicSharedMemorySize, SMEM_B);
    cudaFuncSetAttribute(bgemm_kernel<4>, cudaFuncAttributeMaxDynamicSharedMemorySize, SMEM_B);
    cudaFuncSetAttribute(scores_wmma_kernel, cudaFuncAttributeMaxDynamicSharedMemorySize, SSMEM);
    cudaFuncSetAttribute(ctx_wmma_kernel, cudaFuncAttributeMaxDynamicSharedMemorySize, CSMEM);

    detect_kernel<<<1, 256>>>(x);
    embed_kernel<<<(MROWS * (Dd/4)) / 256, 256>>>(x, emb, pos, h);
    ln_kernel<<<MROWS, 256>>>(h, g1, beta1, x1);

    dim3 blkT(32, 8);
    dim3 gdd(Dd / 256, MROWS / 128);           // (4, 64)

    convsplit_kernel<<<(MROWS * Dd / 4) / 256, 256>>>(x1, Ah, Al, MROWS * Dd / 4);
    convtrans_kernel<<<dim3(Dd/32, Dd/32), blkT>>>(Wq, Bh, Bl, Dd, Dd);
    bgemm_kernel<3><<<gdd, 256, SMEM_B>>>(Ah, Al, Bh, Bl, bq, nullptr, nullptr, qh, ql, Dd, Dd);
    convtrans_kernel<<<dim3(Dd/32, Dd/32), blkT>>>(Wk, Bh, Bl, Dd, Dd);
    bgemm_kernel<3><<<gdd, 256, SMEM_B>>>(Ah, Al, Bh, Bl, bk, nullptr, nullptr, kh, kl, Dd, Dd);
    convtrans_kernel<<<dim3(Dd/32, Dd/32), blkT>>>(Wv, Bh, Bl, Dd, Dd);
    bgemm_kernel<3><<<gdd, 256, SMEM_B>>>(Ah, Al, Bh, Bl, bv, nullptr, nullptr, vh, vl, Dd, Dd);

    dim3 gs(Ss / 128, Ss / 128, Bb * Hh);
    scores_wmma_kernel<<<gs, 256, SSMEM>>>(qh, ql, kh, kl, vlen, sc);
    softmax_kernel<<<Bb * Hh * Ss, 256>>>(sc, vlen, ah, al);
    dim3 gc(Ss / 128, Bb * Hh);
    ctx_wmma_kernel<<<gc, 256, CSMEM>>>(ah, al, vh, vl, vlen, ctx);

    convsplit_kernel<<<(MROWS * Dd / 4) / 256, 256>>>(ctx, Ah, Al, MROWS * Dd / 4);
    convtrans_kernel<<<dim3(Dd/32, Dd/32), blkT>>>(Wo, Bh, Bl, Dd, Dd);
    bgemm_kernel<1><<<gdd, 256, SMEM_B>>>(Ah, Al, Bh, Bl, bo, h, mid, nullptr, nullptr, Dd, Dd);

    ln_kernel<<<MROWS, 256>>>(mid, g2, beta2, x2);

    convsplit_kernel<<<(MROWS * Dd / 4) / 256, 256>>>(x2, Ah, Al, MROWS * Dd / 4);
    convtrans_kernel<<<dim3(FFf/32, Dd/32), blkT>>>(W1, Bh, Bl, Dd, FFf);
    dim3 gff(FFf / 256, MROWS / 128);
    bgemm_kernel<4><<<gff, 256, SMEM_B>>>(Ah, Al, Bh, Bl, b1, nullptr, nullptr, fh, fl, FFf, Dd);

    convtrans_kernel<<<dim3(Dd/32, FFf/32), blkT>>>(W2, Bh, Bl, FFf, Dd);
    bgemm_kernel<1><<<gdd, 256, SMEM_B>>>(fh, fl, Bh, Bl, b2, mid, out, nullptr, nullptr, Dd, FFf);
}

// round 11
// speedup vs baseline: 2.7019x; 1.1145x over previous
#include <cuda_runtime.h>
#include <cuda_bf16.h>
#include <cuda_pipeline.h>
#include <mma.h>
#include <math.h>
#include <stdint.h>

using namespace nvcuda;

#define Bb 8
#define Ss 1024
#define Dd 1024
#define Hh 16
#define DHh 64
#define FFf 4096
#define LAYER 3
#define MROWS (Bb*Ss)   /* 8192 */

// ---------------- scratch (device globals; allocation-free rule) ----------------
__device__ float g_h  [MROWS*Dd];
__device__ float g_sc [(size_t)Bb*Hh*Ss*Ss];   // 512 MB scores
__device__ float g_mid[MROWS*Dd];
__device__ __nv_bfloat16 g_f [(size_t)2*MROWS*FFf];  // ffn split hi|lo
__device__ __nv_bfloat16 g_Ah[(size_t)MROWS*FFf];
__device__ __nv_bfloat16 g_Al[(size_t)MROWS*FFf];
__device__ __nv_bfloat16 g_Bh[(size_t)FFf*Dd];
__device__ __nv_bfloat16 g_Bl[(size_t)FFf*Dd];
__device__ __nv_bfloat16 g_qh[MROWS*Dd];
__device__ __nv_bfloat16 g_ql[MROWS*Dd];
__device__ __nv_bfloat16 g_kh[MROWS*Dd];
__device__ __nv_bfloat16 g_kl[MROWS*Dd];
__device__ __nv_bfloat16 g_vh[MROWS*Dd];
__device__ __nv_bfloat16 g_vl[MROWS*Dd];
__device__ __nv_bfloat16 g_ah[(size_t)Bb*Hh*Ss*Ss];
__device__ __nv_bfloat16 g_al[(size_t)Bb*Hh*Ss*Ss];
__device__ int   g_is64;

// ==================== dtype detection ====================
__global__ void detect_kernel(const int* __restrict__ x) {
    __shared__ int any;
    if (threadIdx.x == 0) any = 0;
    __syncthreads();
    int local = 0;
    for (int i = threadIdx.x; i < 4096; i += blockDim.x)
        if (x[2*i + 1] != 0) local = 1;
    if (local) any = 1;
    __syncthreads();
    if (threadIdx.x == 0) g_is64 = (any == 0) ? 1 : 0;
}

// ==================== embed ====================
__global__ void embed_kernel(const int* __restrict__ x, const float* __restrict__ emb,
                             const float* __restrict__ pos, float* __restrict__ h) {
    int i = blockIdx.x * blockDim.x + threadIdx.x;
    if (i >= MROWS * (Dd/4)) return;
    int row = i >> 8;
    int dc  = i & 255;
    int s   = row & (Ss - 1);
    long long tok = g_is64 ? ((const long long*)x)[row] : (long long)x[row];
    float4 e = ((const float4*)emb)[(size_t)tok * 256 + dc];
    float4 p = ((const float4*)pos)[(size_t)s   * 256 + dc];
    float4 r;
    r.x = fmaf(e.x, 32.0f, p.x);
    r.y = fmaf(e.y, 32.0f, p.y);
    r.z = fmaf(e.z, 32.0f, p.z);
    r.w = fmaf(e.w, 32.0f, p.w);
    ((float4*)h)[i] = r;
}

// ==================== layernorm with fused split-bf16 output ====================
__global__ __launch_bounds__(256)
void ln_split_kernel(const float* __restrict__ in, const float* __restrict__ gamma,
                     const float* __restrict__ beta, __nv_bfloat16* __restrict__ oh,
                     __nv_bfloat16* __restrict__ ol) {
    int row = blockIdx.x;
    int tid = threadIdx.x;
    const float4* xr = (const float4*)(in + (size_t)row * Dd);
    float4 v = xr[tid];
    float s1 = v.x + v.y + v.z + v.w;
    float s2 = v.x*v.x + v.y*v.y + v.z*v.z + v.w*v.w;
    #pragma unroll
    for (int o = 16; o; o >>= 1) {
        s1 += __shfl_xor_sync(0xffffffffu, s1, o);
        s2 += __shfl_xor_sync(0xffffffffu, s2, o);
    }
    __shared__ float a1[8], a2[8];
    int lane = tid & 31, wid = tid >> 5;
    if (lane == 0) { a1[wid] = s1; a2[wid] = s2; }
    __syncthreads();
    __shared__ float mS, invS;
    if (tid == 0) {
        float t1 = 0.f, t2 = 0.f;
        #pragma unroll
        for (int w = 0; w < 8; ++w) { t1 += a1[w]; t2 += a2[w]; }
        float mean = t1 * (1.0f / Dd);
        float var  = t2 * (1.0f / Dd) - mean * mean;
        mS = mean; invS = rsqrtf(var + 1e-5f);
    }
    __syncthreads();
    float mean = mS, inv = invS;
    float4 g4 = ((const float4*)gamma)[tid];
    float4 b4 = ((const float4*)beta)[tid];
    float o0 = (v.x - mean) * inv * g4.x + b4.x;
    float o1 = (v.y - mean) * inv * g4.y + b4.y;
    float o2 = (v.z - mean) * inv * g4.z + b4.z;
    float o3 = (v.w - mean) * inv * g4.w + b4.w;
    __nv_bfloat16 h0 = __float2bfloat16(o0), h1 = __float2bfloat16(o1);
    __nv_bfloat16 h2 = __float2bfloat16(o2), h3 = __float2bfloat16(o3);
    __nv_bfloat16 l0 = __float2bfloat16(o0 - __bfloat162float(h0));
    __nv_bfloat16 l1 = __float2bfloat16(o1 - __bfloat162float(h1));
    __nv_bfloat16 l2 = __float2bfloat16(o2 - __bfloat162float(h2));
    __nv_bfloat16 l3 = __float2bfloat16(o3 - __bfloat162float(h3));
    size_t base = (size_t)row * Dd + tid * 4;
    *(__nv_bfloat162*)(oh + base)     = __nv_bfloat162(h0, h1);
    *(__nv_bfloat162*)(oh + base + 2) = __nv_bfloat162(h2, h3);
    *(__nv_bfloat162*)(ol + base)     = __nv_bfloat162(l0, l1);
    *(__nv_bfloat162*)(ol + base + 2) = __nv_bfloat162(l2, l3);
}

// ==================== weight fp32 [K,N] -> split bf16 transposed [N,K] ====================
__global__ void convtrans_kernel(const float* __restrict__ W, __nv_bfloat16* __restrict__ TH,
                                 __nv_bfloat16* __restrict__ TL, int K, int N) {
    __shared__ float t[32][33];
    int nb = blockIdx.x * 32, kb = blockIdx.y * 32;
    int tx = threadIdx.x, ty = threadIdx.y;
    for (int r = ty; r < 32; r += 8)
        t[r][tx] = W[(size_t)(kb + r) * N + nb + tx];
    __syncthreads();
    for (int r = ty; r < 32; r += 8) {
        float v = t[tx][r];
        __nv_bfloat16 h = __float2bfloat16(v);
        __nv_bfloat16 l = __float2bfloat16(v - __bfloat162float(h));
        size_t o = (size_t)(nb + r) * K + kb + tx;
        TH[o] = h; TL[o] = l;
    }
}

// ==================== wmma split-bf16 GEMM (128x256 tile, BK=64, 2-stage) ====================
#define WTSE 72
#define WTSB 144
#define A_TILE_B (128*WTSB)                 /* 18432 */
#define B_TILE_B (256*WTSB)                 /* 36864 */
#define STAGE_B  (2*A_TILE_B + 2*B_TILE_B)  /* 110592 */
#define SMEM_B   (2*STAGE_B)                /* 221184 */

// EPI: 0:+bias->C  1:+bias+res->C  2:relu(+bias)->C  3:+bias->split  4:relu(+bias)->split
template<int EPI>
__global__ __launch_bounds__(256)
void bgemm_kernel(const __nv_bfloat16* __restrict__ Ah, const __nv_bfloat16* __restrict__ Al,
                  const __nv_bfloat16* __restrict__ Bh, const __nv_bfloat16* __restrict__ Bl,
                  const float* __restrict__ bias, const float* __restrict__ res,
                  float* __restrict__ C, __nv_bfloat16* __restrict__ Oh,
                  __nv_bfloat16* __restrict__ Ol, int N, int K) {
    extern __shared__ __align__(128) char smem[];
    int tid = threadIdx.x, wid = tid >> 5;
    int rowBase = blockIdx.y * 128, colBase = blockIdx.x * 256;
    int m0 = (wid >> 2) * 64, n0 = (wid & 3) * 64;

    // 24 x 16B chunks per stage per thread (6144 total)
    const __nv_bfloat16* gsrc[24];
    int soff[24];
    #pragma unroll
    for (int i = 0; i < 24; ++i) {
        int v = tid + (i << 8);
        if (v < 2048) {                    // A: hi [0,1024), lo [1024,2048)
            int t2 = v >> 10, idx = v & 1023, row = idx >> 3, c = idx & 7;
            gsrc[i] = (t2 ? Al : Ah) + (size_t)(rowBase + row) * K + c * 8;
            soff[i] = t2 * A_TILE_B + row * WTSB + c * 16;
        } else {                           // B: hi [0,2048), lo [2048,4096)
            int w = v - 2048;
            int t2 = w >> 11, idx = w & 2047, row = idx >> 3, c = idx & 7;
            gsrc[i] = (t2 ? Bl : Bh) + (size_t)(colBase + row) * K + c * 8;
            soff[i] = 2 * A_TILE_B + t2 * B_TILE_B + row * WTSB + c * 16;
        }
    }

    wmma::fragment<wmma::accumulator, 16, 16, 16, float> acc[4][4];
    #pragma unroll
    for (int mf = 0; mf < 4; ++mf)
        #pragma unroll
        for (int nf = 0; nf < 4; ++nf)
            wmma::fill_fragment(acc[mf][nf], 0.0f);

    const int nch = K >> 6;
    #pragma unroll
    for (int i = 0; i < 24; ++i)
        __pipeline_memcpy_async(smem + soff[i], gsrc[i], 16);
    __pipeline_commit();
    #pragma unroll
    for (int i = 0; i < 24; ++i)
        __pipeline_memcpy_async(smem + STAGE_B + soff[i], gsrc[i] + 64, 16);
    __pipeline_commit();

    for (int ch = 0; ch < nch; ++ch) {
        if (ch + 2 <= nch) __pipeline_wait_prior(1);
        else               __pipeline_wait_prior(0);
        __syncthreads();
        char* stage = smem + (ch & 1) * STAGE_B;
        const __nv_bfloat16* At_h = (const __nv_bfloat16*)(stage);
        const __nv_bfloat16* At_l = (const __nv_bfloat16*)(stage + A_TILE_B);
        const __nv_bfloat16* Bt_h = (const __nv_bfloat16*)(stage + 2 * A_TILE_B);
        const __nv_bfloat16* Bt_l = (const __nv_bfloat16*)(stage + 2 * A_TILE_B + B_TILE_B);
        #pragma unroll
        for (int ks = 0; ks < 4; ++ks) {
            wmma::fragment<wmma::matrix_b, 16, 16, 16, __nv_bfloat16, wmma::col_major> bh[4], bl[4];
            #pragma unroll
            for (int nf = 0; nf < 4; ++nf) {
                wmma::load_matrix_sync(bh[nf], Bt_h + (n0 + nf * 16) * WTSE + ks * 16, WTSE);
                wmma::load_matrix_sync(bl[nf], Bt_l + (n0 + nf * 16) * WTSE + ks * 16, WTSE);
            }
            #pragma unroll
            for (int mf = 0; mf < 4; ++mf) {
                wmma::fragment<wmma::matrix_a, 16, 16, 16, __nv_bfloat16, wmma::row_major> fa, fl2;
                wmma::load_matrix_sync(fa,  At_h + (m0 + mf * 16) * WTSE + ks * 16, WTSE);
                wmma::load_matrix_sync(fl2, At_l + (m0 + mf * 16) * WTSE + ks * 16, WTSE);
                #pragma unroll
                for (int nf = 0; nf < 4; ++nf)
                    wmma::mma_sync(acc[mf][nf], fa, bh[nf], acc[mf][nf]);
                #pragma unroll
                for (int nf = 0; nf < 4; ++nf)
                    wmma::mma_sync(acc[mf][nf], fa, bl[nf], acc[mf][nf]);
                #pragma unroll
                for (int nf = 0; nf < 4; ++nf)
                    wmma::mma_sync(acc[mf][nf], fl2, bh[nf], acc[mf][nf]);
            }
        }
        __syncthreads();
        if (ch + 2 < nch) {
            #pragma unroll
            for (int i = 0; i < 24; ++i)
                __pipeline_memcpy_async(smem + (ch & 1) * STAGE_B + soff[i],
                                        gsrc[i] + (size_t)(ch + 2) * 64, 16);
            __pipeline_commit();
        }
    }

    // ---- epilogue: fragments -> smem (stride 260) -> global ----
    float* sf = (float*)smem;
    #pragma unroll
    for (int mf = 0; mf < 4; ++mf)
        #pragma unroll
        for (int nf = 0; nf < 4; ++nf)
            wmma::store_matrix_sync(sf + (m0 + mf * 16) * 260 + n0 + nf * 16,
                                    acc[mf][nf], 260, wmma::mem_row_major);
    __syncthreads();
    #pragma unroll
    for (int i = 0; i < 32; ++i) {
        int v = tid + (i << 8);
        int r = v >> 6, c4 = (v & 63) * 4;
        float4 val = *(float4*)(sf + r * 260 + c4);
        int col = colBase + c4;
        float4 bv = *(const float4*)(bias + col);
        val.x += bv.x; val.y += bv.y; val.z += bv.z; val.w += bv.w;
        size_t o = (size_t)(rowBase + r) * N + col;
        if (EPI == 1) {
            float4 rv = *(const float4*)(res + o);
            val.x += rv.x; val.y += rv.y; val.z += rv.z; val.w += rv.w;
        }
        if (EPI == 2 || EPI == 4) {
            val.x = fmaxf(val.x, 0.f); val.y = fmaxf(val.y, 0.f);
            val.z = fmaxf(val.z, 0.f); val.w = fmaxf(val.w, 0.f);
        }
        if (EPI <= 2) {
            *(float4*)(C + o) = val;
        } else {
            __nv_bfloat16 h0 = __float2bfloat16(val.x), h1 = __float2bfloat16(val.y);
            __nv_bfloat16 h2 = __float2bfloat16(val.z), h3 = __float2bfloat16(val.w);
            __nv_bfloat16 l0 = __float2bfloat16(val.x - __bfloat162float(h0));
            __nv_bfloat16 l1 = __float2bfloat16(val.y - __bfloat162float(h1));
            __nv_bfloat16 l2 = __float2bfloat16(val.z - __bfloat162float(h2));
            __nv_bfloat16 l3 = __float2bfloat16(val.w - __bfloat162float(h3));
            *(__nv_bfloat162*)(Oh + o)     = __nv_bfloat162(h0, h1);
            *(__nv_bfloat162*)(Oh + o + 2) = __nv_bfloat162(h2, h3);
            *(__nv_bfloat162*)(Ol + o)     = __nv_bfloat162(l0, l1);
            *(__nv_bfloat162*)(Ol + o + 2) = __nv_bfloat162(l2, l3);
        }
    }
}

// ==================== wmma attention scores (mask-aware tile skip) ====================
#define ATSE 72
#define ATSB 144
#define STILE (128*ATSB)
#define SSMEM (4*STILE)

__global__ __launch_bounds__(256)
void scores_wmma_kernel(const __nv_bfloat16* __restrict__ qh, const __nv_bfloat16* __restrict__ ql,
                        const __nv_bfloat16* __restrict__ kh, const __nv_bfloat16* __restrict__ kl,
                        const int* __restrict__ vlen, float* __restrict__ sc) {
    extern __shared__ __align__(128) char smem[];
    int bh = blockIdx.z;
    int b = bh >> 4, hh = bh & 15;
    int i0 = blockIdx.y * 128, j0 = blockIdx.x * 128;
    int vl = g_is64 ? (int)((const long long*)vlen)[b] : vlen[b];
    if (j0 >= vl) return;
    int tid = threadIdx.x, wid = tid >> 5;
    int m0 = (wid >> 2) * 64, n0 = (wid & 3) * 32;

    #pragma unroll
    for (int i = 0; i < 16; ++i) {
        int v = tid + (i << 8);
        int m = v >> 10, rem = v & 1023, r = rem >> 3, c = rem & 7;
        const __nv_bfloat16* mat = (m == 0) ? qh : (m == 1) ? ql : (m == 2) ? kh : kl;
        int rowg = ((m < 2) ? i0 : j0) + r;
        uint4 d = *(const uint4*)(mat + (size_t)(b * Ss + rowg) * Dd + hh * 64 + c * 8);
        *(uint4*)(smem + m * STILE + r * ATSB + c * 16) = d;
    }
    __syncthreads();

    wmma::fragment<wmma::accumulator, 16, 16, 16, float> acc[4][2];
    #pragma unroll
    for (int mf = 0; mf < 4; ++mf)
        #pragma unroll
        for (int nf = 0; nf < 2; ++nf)
            wmma::fill_fragment(acc[mf][nf], 0.0f);

    const __nv_bfloat16* Qh = (const __nv_bfloat16*)(smem);
    const __nv_bfloat16* Ql = (const __nv_bfloat16*)(smem + STILE);
    const __nv_bfloat16* Kh = (const __nv_bfloat16*)(smem + 2 * STILE);
    const __nv_bfloat16* Kl = (const __nv_bfloat16*)(smem + 3 * STILE);
    #pragma unroll
    for (int ks = 0; ks < 4; ++ks) {
        wmma::fragment<wmma::matrix_a, 16, 16, 16, __nv_bfloat16, wmma::row_major> ah[4], al[4];
        wmma::fragment<wmma::matrix_b, 16, 16, 16, __nv_bfloat16, wmma::col_major> bh2[2], bl2[2];
        #pragma unroll
        for (int mf = 0; mf < 4; ++mf) {
            wmma::load_matrix_sync(ah[mf], Qh + (m0 + mf * 16) * ATSE + ks * 16, ATSE);
            wmma::load_matrix_sync(al[mf], Ql + (m0 + mf * 16) * ATSE + ks * 16, ATSE);
        }
        #pragma unroll
        for (int nf = 0; nf < 2; ++nf) {
            wmma::load_matrix_sync(bh2[nf], Kh + (n0 + nf * 16) * ATSE + ks * 16, ATSE);
            wmma::load_matrix_sync(bl2[nf], Kl + (n0 + nf * 16) * ATSE + ks * 16, ATSE);
        }
        #pragma unroll
        for (int mf = 0; mf < 4; ++mf)
            #pragma unroll
            for (int nf = 0; nf < 2; ++nf) {
                wmma::mma_sync(acc[mf][nf], ah[mf], bh2[nf], acc[mf][nf]);
                wmma::mma_sync(acc[mf][nf], ah[mf], bl2[nf], acc[mf][nf]);
                wmma::mma_sync(acc[mf][nf], al[mf], bh2[nf], acc[mf][nf]);
            }
    }
    #pragma unroll
    for (int mf = 0; mf < 4; ++mf)
        #pragma unroll
        for (int nf = 0; nf < 2; ++nf) {
            #pragma unroll
            for (int t = 0; t < acc[mf][nf].num_elements; ++t)
                acc[mf][nf].x[t] *= 0.125f;
            wmma::store_matrix_sync(
                sc + ((size_t)bh * Ss + i0 + m0 + mf * 16) * Ss + j0 + n0 + nf * 16,
                acc[mf][nf], Ss, wmma::mem_row_major);
        }
}

// ==================== softmax (mask-aware + split-bf16 output) ====================
__global__ __launch_bounds__(256)
void softmax_kernel(const float* __restrict__ sc, const int* __restrict__ vlen,
                    __nv_bfloat16* __restrict__ ah, __nv_bfloat16* __restrict__ al) {
    int row = blockIdx.x;
    int b = row >> 14;
    int vl = g_is64 ? (int)((const long long*)vlen)[b] : vlen[b];
    int vlc = (vl + 63) & ~63;
    const float* sr = sc + (size_t)row * Ss;
    int tid = threadIdx.x;
    int j0 = tid * 4;
    float vals[4] = {-1e9f, -1e9f, -1e9f, -1e9f};
    if (j0 < vl) {
        float4 vv = *(const float4*)(sr + j0);
        vals[0] = vv.x; vals[1] = vv.y; vals[2] = vv.z; vals[3] = vv.w;
        #pragma unroll
        for (int c = 0; c < 4; c++) if (j0 + c >= vl) vals[c] = -1e9f;
    }
    float m = fmaxf(fmaxf(vals[0], vals[1]), fmaxf(vals[2], vals[3]));
    #pragma unroll
    for (int o = 16; o; o >>= 1) m = fmaxf(m, __shfl_xor_sync(0xffffffffu, m, o));
    __shared__ float r1[8];
    int lane = tid & 31, wid = tid >> 5;
    if (lane == 0) r1[wid] = m;
    __syncthreads();
    __shared__ float Ms;
    if (tid == 0) {
        float t = r1[0];
        #pragma unroll
        for (int w = 1; w < 8; w++) t = fmaxf(t, r1[w]);
        Ms = t;
    }
    __syncthreads();
    float M = Ms;
    float e[4];
    float s = 0.f;
    #pragma unroll
    for (int c = 0; c < 4; c++) { e[c] = expf(vals[c] - M); s += e[c]; }
    #pragma unroll
    for (int o = 16; o; o >>= 1) s += __shfl_xor_sync(0xffffffffu, s, o);
    __shared__ float r2[8];
    if (lane == 0) r2[wid] = s;
    __syncthreads();
    __shared__ float Ssum;
    if (tid == 0) {
        float t = 0.f;
        #pragma unroll
        for (int w = 0; w < 8; w++) t += r2[w];
        Ssum = t;
    }
    __syncthreads();
    if (j0 >= vlc) return;
    float inv = 1.0f / Ssum;
    float o0 = e[0] * inv, o1 = e[1] * inv, o2 = e[2] * inv, o3 = e[3] * inv;
    __nv_bfloat16 h0 = __float2bfloat16(o0), h1 = __float2bfloat16(o1);
    __nv_bfloat16 h2 = __float2bfloat16(o2), h3 = __float2bfloat16(o3);
    __nv_bfloat16 l0 = __float2bfloat16(o0 - __bfloat162float(h0));
    __nv_bfloat16 l1 = __float2bfloat16(o1 - __bfloat162float(h1));
    __nv_bfloat16 l2 = __float2bfloat16(o2 - __bfloat162float(h2));
    __nv_bfloat16 l3 = __float2bfloat16(o3 - __bfloat162float(h3));
    size_t base = (size_t)row * Ss + j0;
    *(__nv_bfloat162*)(ah + base)     = __nv_bfloat162(h0, h1);
    *(__nv_bfloat162*)(ah + base + 2) = __nv_bfloat162(h2, h3);
    *(__nv_bfloat162*)(al + base)     = __nv_bfloat162(l0, l1);
    *(__nv_bfloat162*)(al + base + 2) = __nv_bfloat162(l2, l3);
}

// ==================== wmma ctx = attn @ v (mask-bounded, split-bf16 output) ====================
#define CAH 0
#define CAL 18432
#define CVH 36864
#define CVL 46080
#define CSMEM 55296

__global__ __launch_bounds__(256)
void ctx_wmma_kernel(const __nv_bfloat16* __restrict__ ah, const __nv_bfloat16* __restrict__ al,
                     const __nv_bfloat16* __restrict__ vh, const __nv_bfloat16* __restrict__ vl_,
                     const int* __restrict__ vlen,
                     __nv_bfloat16* __restrict__ Oh, __nv_bfloat16* __restrict__ Ol) {
    extern __shared__ __align__(128) char smem[];
    int bh = blockIdx.y;
    int b = bh >> 4, hh = bh & 15;
    int i0 = blockIdx.x * 128;
    int vl = g_is64 ? (int)((const long long*)vlen)[b] : vlen[b];
    int nch_eff = (vl + 63) >> 6;
    int tid = threadIdx.x, wid = tid >> 5;
    int m0 = (wid >> 1) * 32, n0 = (wid & 1) * 32;

    wmma::fragment<wmma::accumulator, 16, 16, 16, float> acc[2][2];
    #pragma unroll
    for (int mf = 0; mf < 2; ++mf)
        #pragma unroll
        for (int nf = 0; nf < 2; ++nf)
            wmma::fill_fragment(acc[mf][nf], 0.0f);

    for (int ch = 0; ch < nch_eff; ++ch) {
        int kk0 = ch * 64;
        #pragma unroll
        for (int i = 0; i < 12; ++i) {
            int v = tid + (i << 8);
            if (v < 2048) {
                int split = v >> 10, rem = v & 1023, r = rem >> 3, c = rem & 7;
                const __nv_bfloat16* src = (split ? al : ah);
                uint4 d = *(const uint4*)(src + (size_t)(bh * Ss + i0 + r) * Ss + kk0 + c * 8);
                *(uint4*)(smem + split * 18432 + r * ATSB + c * 16) = d;
            } else {
                int vv2 = v - 2048;
                int split = vv2 >> 9, rem = vv2 & 511, r = rem >> 3, c = rem & 7;
                const __nv_bfloat16* src = (split ? vl_ : vh);
                uint4 d = *(const uint4*)(src + (size_t)(b * Ss + kk0 + r) * Dd + hh * 64 + c * 8);
                *(uint4*)(smem + CVH + split * 9216 + r * ATSB + c * 16) = d;
            }
        }
        __syncthreads();
        const __nv_bfloat16* Ath = (const __nv_bfloat16*)(smem + CAH);
        const __nv_bfloat16* Atl = (const __nv_bfloat16*)(smem + CAL);
        const __nv_bfloat16* Vth = (const __nv_bfloat16*)(smem + CVH);
        const __nv_bfloat16* Vtl = (const __nv_bfloat16*)(smem + CVL);
        #pragma unroll
        for (int ks = 0; ks < 4; ++ks) {
            wmma::fragment<wmma::matrix_a, 16, 16, 16, __nv_bfloat16, wmma::row_major> fah[2], fal[2];
            wmma::fragment<wmma::matrix_b, 16, 16, 16, __nv_bfloat16, wmma::row_major> fvh[2], fvl[2];
            #pragma unroll
            for (int mf = 0; mf < 2; ++mf) {
                wmma::load_matrix_sync(fah[mf], Ath + (m0 + mf * 16) * ATSE + ks * 16, ATSE);
                wmma::load_matrix_sync(fal[mf], Atl + (m0 + mf * 16) * ATSE + ks * 16, ATSE);
            }
            #pragma unroll
            for (int nf = 0; nf < 2; ++nf) {
                wmma::load_matrix_sync(fvh[nf], Vth + (ks * 16) * ATSE + n0 + nf * 16, ATSE);
                wmma::load_matrix_sync(fvl[nf], Vtl + (ks * 16) * ATSE + n0 + nf * 16, ATSE);
            }
            #pragma unroll
            for (int mf = 0; mf < 2; ++mf)
                #pragma unroll
                for (int nf = 0; nf < 2; ++nf) {
                    wmma::mma_sync(acc[mf][nf], fah[mf], fvh[nf], acc[mf][nf]);
                    wmma::mma_sync(acc[mf][nf], fah[mf], fvl[nf], acc[mf][nf]);
                    wmma::mma_sync(acc[mf][nf], fal[mf], fvh[nf], acc[mf][nf]);
                }
        }
        __syncthreads();
    }
    // ---- split-bf16 epilogue via smem (stride 68) ----
    float* sf = (float*)smem;
    #pragma unroll
    for (int mf = 0; mf < 2; ++mf)
        #pragma unroll
        for (int nf = 0; nf < 2; ++nf)
            wmma::store_matrix_sync(sf + (m0 + mf * 16) * 68 + n0 + nf * 16,
                                    acc[mf][nf], 68, wmma::mem_row_major);
    __syncthreads();
    #pragma unroll
    for (int i = 0; i < 8; ++i) {
        int v = tid + (i << 8);          // 2048 float4s = 128x64
        int r = v >> 4, c4 = (v & 15) * 4;
        float4 val = *(float4*)(sf + r * 68 + c4);
        size_t o = (size_t)(b * Ss + i0 + r) * Dd + hh * 64 + c4;
        __nv_bfloat16 h0 = __float2bfloat16(val.x), h1 = __float2bfloat16(val.y);
        __nv_bfloat16 h2 = __float2bfloat16(val.z), h3 = __float2bfloat16(val.w);
        __nv_bfloat16 l0 = __float2bfloat16(val.x - __bfloat162float(h0));
        __nv_bfloat16 l1 = __float2bfloat16(val.y - __bfloat162float(h1));
        __nv_bfloat16 l2 = __float2bfloat16(val.z - __bfloat162float(h2));
        __nv_bfloat16 l3 = __float2bfloat16(val.w - __bfloat162float(h3));
        *(__nv_bfloat162*)(Oh + o)     = __nv_bfloat162(h0, h1);
        *(__nv_bfloat162*)(Oh + o + 2) = __nv_bfloat162(h2, h3);
        *(__nv_bfloat162*)(Ol + o)     = __nv_bfloat162(l0, l1);
        *(__nv_bfloat162*)(Ol + o + 2) = __nv_bfloat162(l2, l3);
    }
}

// ==================== launch ====================
extern "C" void kernel_launch(void* const* d_in, const int* in_sizes, int n_in,
                              void* d_out, int out_size) {
    const int*   x    = (const int*)d_in[0];
    const int*   vlen = (const int*)d_in[1];
    const float* emb  = (const float*)d_in[2];
    const float* pos  = (const float*)d_in[3];
    const float* Wq = (const float*)d_in[4]  + (size_t)LAYER * Dd * Dd;
    const float* bq = (const float*)d_in[5]  + LAYER * Dd;
    const float* Wk = (const float*)d_in[6]  + (size_t)LAYER * Dd * Dd;
    const float* bk = (const float*)d_in[7]  + LAYER * Dd;
    const float* Wv = (const float*)d_in[8]  + (size_t)LAYER * Dd * Dd;
    const float* bv = (const float*)d_in[9]  + LAYER * Dd;
    const float* Wo = (const float*)d_in[10] + (size_t)LAYER * Dd * Dd;
    const float* bo = (const float*)d_in[11] + LAYER * Dd;
    const float* W1 = (const float*)d_in[12] + (size_t)LAYER * Dd * FFf;
    const float* b1 = (const float*)d_in[13] + LAYER * FFf;
    const float* W2 = (const float*)d_in[14] + (size_t)LAYER * FFf * Dd;
    const float* b2 = (const float*)d_in[15] + LAYER * Dd;
    const float* g1    = (const float*)d_in[16] + LAYER * Dd;
    const float* beta1 = (const float*)d_in[17] + LAYER * Dd;
    const float* g2    = (const float*)d_in[18] + LAYER * Dd;
    const float* beta2 = (const float*)d_in[19] + LAYER * Dd;
    float* out = (float*)d_out;

    float *h, *sc, *mid;
    __nv_bfloat16 *f, *Ah, *Al, *Bh, *Bl, *qh, *ql, *kh, *kl, *vh, *vl, *ah, *al;
    cudaGetSymbolAddress((void**)&h,   g_h);
    cudaGetSymbolAddress((void**)&sc,  g_sc);
    cudaGetSymbolAddress((void**)&mid, g_mid);
    cudaGetSymbolAddress((void**)&f,   g_f);
    cudaGetSymbolAddress((void**)&Ah,  g_Ah);
    cudaGetSymbolAddress((void**)&Al,  g_Al);
    cudaGetSymbolAddress((void**)&Bh,  g_Bh);
    cudaGetSymbolAddress((void**)&Bl,  g_Bl);
    cudaGetSymbolAddress((void**)&qh,  g_qh);
    cudaGetSymbolAddress((void**)&ql,  g_ql);
    cudaGetSymbolAddress((void**)&kh,  g_kh);
    cudaGetSymbolAddress((void**)&kl,  g_kl);
    cudaGetSymbolAddress((void**)&vh,  g_vh);
    cudaGetSymbolAddress((void**)&vl,  g_vl);
    cudaGetSymbolAddress((void**)&ah,  g_ah);
    cudaGetSymbolAddress((void**)&al,  g_al);
    __nv_bfloat16* fh = f;
    __nv_bfloat16* fl = f + (size_t)MROWS * FFf;

    cudaFuncSetAttribute(bgemm_kernel<1>, cudaFuncAttributeMaxDynamicSharedMemorySize, SMEM_B);
    cudaFuncSetAttribute(bgemm_kernel<3>, cudaFuncAttributeMaxDynamicSharedMemorySize, SMEM_B);
    cudaFuncSetAttribute(bgemm_kernel<4>, cudaFuncAttributeMaxDynamicSharedMemorySize, SMEM_B);
    cudaFuncSetAttribute(scores_wmma_kernel, cudaFuncAttributeMaxDynamicSharedMemorySize, SSMEM);
    cudaFuncSetAttribute(ctx_wmma_kernel, cudaFuncAttributeMaxDynamicSharedMemorySize, CSMEM);

    detect_kernel<<<1, 256>>>(x);
    embed_kernel<<<(MROWS * (Dd/4)) / 256, 256>>>(x, emb, pos, h);
    ln_split_kernel<<<MROWS, 256>>>(h, g1, beta1, Ah, Al);

    dim3 blkT(32, 8);
    dim3 gdd(Dd / 256, MROWS / 128);           // (4, 64)

    convtrans_kernel<<<dim3(Dd/32, Dd/32), blkT>>>(Wq, Bh, Bl, Dd, Dd);
    bgemm_kernel<3><<<gdd, 256, SMEM_B>>>(Ah, Al, Bh, Bl, bq, nullptr, nullptr, qh, ql, Dd, Dd);
    convtrans_kernel<<<dim3(Dd/32, Dd/32), blkT>>>(Wk, Bh, Bl, Dd, Dd);
    bgemm_kernel<3><<<gdd, 256, SMEM_B>>>(Ah, Al, Bh, Bl, bk, nullptr, nullptr, kh, kl, Dd, Dd);
    convtrans_kernel<<<dim3(Dd/32, Dd/32), blkT>>>(Wv, Bh, Bl, Dd, Dd);
    bgemm_kernel<3><<<gdd, 256, SMEM_B>>>(Ah, Al, Bh, Bl, bv, nullptr, nullptr, vh, vl, Dd, Dd);

    dim3 gs(Ss / 128, Ss / 128, Bb * Hh);
    scores_wmma_kernel<<<gs, 256, SSMEM>>>(qh, ql, kh, kl, vlen, sc);
    softmax_kernel<<<Bb * Hh * Ss, 256>>>(sc, vlen, ah, al);
    dim3 gc(Ss / 128, Bb * Hh);
    ctx_wmma_kernel<<<gc, 256, CSMEM>>>(ah, al, vh, vl, vlen, Ah, Al);

    convtrans_kernel<<<dim3(Dd/32, Dd/32), blkT>>>(Wo, Bh, Bl, Dd, Dd);
    bgemm_kernel<1><<<gdd, 256, SMEM_B>>>(Ah, Al, Bh, Bl, bo, h, mid, nullptr, nullptr, Dd, Dd);

    ln_split_kernel<<<MROWS, 256>>>(mid, g2, beta2, Ah, Al);

    convtrans_kernel<<<dim3(FFf/32, Dd/32), blkT>>>(W1, Bh, Bl, Dd, FFf);
    dim3 gff(FFf / 256, MROWS / 128);          // (16, 64)
    bgemm_kernel<4><<<gff, 256, SMEM_B>>>(Ah, Al, Bh, Bl, b1, nullptr, nullptr, fh, fl, FFf, Dd);

    convtrans_kernel<<<dim3(Dd/32, FFf/32), blkT>>>(W2, Bh, Bl, FFf, Dd);
    bgemm_kernel<1><<<gdd, 256, SMEM_B>>>(fh, fl, Bh, Bl, b2, mid, out, nullptr, nullptr, Dd, FFf);
}